// round 6
// baseline (speedup 1.0000x reference)
#include <cuda_runtime.h>
#include <cuda_bf16.h>

// ---------------- problem constants ----------------
#define B_   32
#define T_   128
#define D_   512
#define H_   8
#define HD_  64
#define FF_  2048
#define E_   8
#define NL_  3
#define NF_  16
#define FEAT_ 200
#define NTOK  4096          // B*T
#define NSLOT 8192          // NTOK*2 (top-2 slots)
#define SCALE_ 10.0f
#define EPS_   1e-5f

// ---------------- scratch (device globals; no allocation allowed) ----------------
__device__ float g_x  [NTOK * D_];
__device__ float g_pb [B_ * T_ * T_];
__device__ float g_K  [NTOK * D_];
__device__ float g_V  [NTOK * D_];
__device__ float g_kv [B_ * D_];
__device__ float g_wv [NTOK * D_];
__device__ float g_o  [NTOK * D_];
__device__ float g_h  [(NSLOT + 128) * FF_];
__device__ float g_eo [(NSLOT + 128) * D_];
__device__ int   g_te [NSLOT];
__device__ float g_tw [NSLOT];
__device__ int   g_cnt[E_];
__device__ int   g_off[E_ + 1];
__device__ int   g_cur[E_];
__device__ int   g_tok[NSLOT + 128];
__device__ int   g_pos[NSLOT];

// ---------------- bf16x3 tensor-core GEMM core: 128x64x16, 2 CTAs/SM ----------------
#define BM 128
#define BN 64
#define BK 16
#define AW 12      // A smem row stride in words (8 + 4 pad -> conflict-free frags)
#define BW 72      // B smem row stride in words (64 + 8 pad; 72 % 32 == 8, conflict-free)

__device__ __forceinline__ float4 ld4(const float* p) {
    return *reinterpret_cast<const float4*>(p);
}
__device__ __forceinline__ float2 ld2(const float* p) {
    return *reinterpret_cast<const float2*>(p);
}

// pack two floats as bf16x2 word: low half = lo, high half = hi
__device__ __forceinline__ unsigned pack2(float lo, float hi) {
    unsigned r;
    asm("cvt.rn.bf16x2.f32 %0, %1, %2;" : "=r"(r) : "f"(hi), "f"(lo));
    return r;
}

__device__ __forceinline__ void split_bf(float x, float& h, float& l) {
    h = __bfloat162float(__float2bfloat16_rn(x));
    l = x - h;
}

__device__ __forceinline__ void mma_bf16(float* c, const unsigned* a, const unsigned* b) {
    asm("mma.sync.aligned.m16n8k16.row.col.f32.bf16.bf16.f32 "
        "{%0,%1,%2,%3}, {%4,%5,%6,%7}, {%8,%9}, {%0,%1,%2,%3};"
        : "+f"(c[0]), "+f"(c[1]), "+f"(c[2]), "+f"(c[3])
        : "r"(a[0]), "r"(a[1]), "r"(a[2]), "r"(a[3]), "r"(b[0]), "r"(b[1]));
}

// C[M,N] = op( gather(A)[M,K] @ B[K,N] + bias + addvec )
// 256 threads = 8 warps (4m x 2n), each warp 32x32 of m16n8k16 tiles, hi/lo split.
template <bool GATHER, bool RELU, bool ADDVEC>
__device__ __forceinline__ void gemm_tc(
    const float* __restrict__ A, int lda, const int* __restrict__ rowmap,
    const float* __restrict__ B, int ldb,
    const float* __restrict__ bias, const float* __restrict__ addvec,
    float* __restrict__ C, int ldc,
    int M, int N, int K, int mtile, int ntile)
{
    __shared__ unsigned Ash[2][BM][AW];   // bf16x2 words: word j = k pair (2j, 2j+1)
    __shared__ unsigned Asl[2][BM][AW];
    __shared__ unsigned Bsh[2][8][BW];    // [kp][n]: word = k pair (2kp, 2kp+1) at col n
    __shared__ unsigned Bsl[2][8][BW];

    const int tid  = threadIdx.x;
    const int lane = tid & 31;
    const int warp = tid >> 5;
    const int wm = (warp >> 1) * 32;      // 0,32,64,96
    const int wn = (warp & 1) * 32;       // 0,32
    const int gq  = lane >> 2;            // 0..7
    const int tig = lane & 3;             // 0..3

    // A tile loader: thread handles rows ar0, ar0+64; floats k = ac..ac+3 -> words wc, wc+1
    const int ar0 = tid >> 2;             // 0..63
    const int ac  = (tid & 3) * 4;
    const int wc  = (tid & 3) * 2;
    int gm0 = mtile * BM + ar0;       if (gm0 > M - 1) gm0 = M - 1;
    int gm1 = mtile * BM + ar0 + 64;  if (gm1 > M - 1) gm1 = M - 1;
    const int ra0 = GATHER ? rowmap[gm0] : gm0;
    const int ra1 = GATHER ? rowmap[gm1] : gm1;
    const float* Ap0 = A + (size_t)ra0 * lda + ac;
    const float* Ap1 = A + (size_t)ra1 * lda + ac;

    // B tile loader: thread handles k-rows 2*kp, 2*kp+1; cols bc, bc+1
    const int kp = tid >> 5;              // 0..7
    const int bc = (tid & 31) * 2;        // 0..62
    const float* Bp = B + (size_t)(2 * kp) * ldb + ntile * BN + bc;

    float acc[2][4][4];
#pragma unroll
    for (int i = 0; i < 2; i++)
#pragma unroll
        for (int j = 0; j < 4; j++)
#pragma unroll
            for (int r = 0; r < 4; r++) acc[i][j][r] = 0.f;

    const int nk = (K + BK - 1) / BK;
    const float4 z4 = make_float4(0.f, 0.f, 0.f, 0.f);
    const float2 z2 = make_float2(0.f, 0.f);

    float4 a0v, a1v;
    float2 b0v, b1v;

    // prefetch tile 0 into regs (K is a multiple of 4; guards exact)
    a0v = (ac < K) ? ld4(Ap0) : z4;
    a1v = (ac < K) ? ld4(Ap1) : z4;
    b0v = (2 * kp < K) ? ld2(Bp) : z2;
    b1v = (2 * kp < K) ? ld2(Bp + ldb) : z2;

    // store stage 0
    auto store_stage = [&](int s, const float4& av0, const float4& av1,
                           const float2& bv0, const float2& bv1) {
        float h0, l0, h1, l1, h2, l2, h3, l3;
        split_bf(av0.x, h0, l0); split_bf(av0.y, h1, l1);
        split_bf(av0.z, h2, l2); split_bf(av0.w, h3, l3);
        *reinterpret_cast<uint2*>(&Ash[s][ar0][wc]) = make_uint2(pack2(h0, h1), pack2(h2, h3));
        *reinterpret_cast<uint2*>(&Asl[s][ar0][wc]) = make_uint2(pack2(l0, l1), pack2(l2, l3));
        split_bf(av1.x, h0, l0); split_bf(av1.y, h1, l1);
        split_bf(av1.z, h2, l2); split_bf(av1.w, h3, l3);
        *reinterpret_cast<uint2*>(&Ash[s][ar0 + 64][wc]) = make_uint2(pack2(h0, h1), pack2(h2, h3));
        *reinterpret_cast<uint2*>(&Asl[s][ar0 + 64][wc]) = make_uint2(pack2(l0, l1), pack2(l2, l3));
        float e0h, e0l, e1h, e1l;   // even-k (row 2kp)
        float o0h, o0l, o1h, o1l;   // odd-k  (row 2kp+1)
        split_bf(bv0.x, e0h, e0l); split_bf(bv0.y, e1h, e1l);
        split_bf(bv1.x, o0h, o0l); split_bf(bv1.y, o1h, o1l);
        *reinterpret_cast<uint2*>(&Bsh[s][kp][bc]) = make_uint2(pack2(e0h, o0h), pack2(e1h, o1h));
        *reinterpret_cast<uint2*>(&Bsl[s][kp][bc]) = make_uint2(pack2(e0l, o0l), pack2(e1l, o1l));
    };

    store_stage(0, a0v, a1v, b0v, b1v);
    __syncthreads();

    for (int kt = 0; kt < nk; kt++) {
        const int s = kt & 1;
        const bool more = (kt + 1 < nk);
        if (more) {
            const int kb = (kt + 1) * BK;
            a0v = (kb + ac < K) ? ld4(Ap0 + kb) : z4;
            a1v = (kb + ac < K) ? ld4(Ap1 + kb) : z4;
            b0v = (kb + 2 * kp < K) ? ld2(Bp + (size_t)kb * ldb) : z2;
            b1v = (kb + 2 * kp < K) ? ld2(Bp + (size_t)(kb + 1) * ldb) : z2;
        }

        unsigned ahi[2][4], alo[2][4], bhi[4][2], blo[4][2];
#pragma unroll
        for (int mt = 0; mt < 2; mt++) {
            const int r0 = wm + mt * 16 + gq;
            ahi[mt][0] = Ash[s][r0]    [tig];
            ahi[mt][1] = Ash[s][r0 + 8][tig];
            ahi[mt][2] = Ash[s][r0]    [tig + 4];
            ahi[mt][3] = Ash[s][r0 + 8][tig + 4];
            alo[mt][0] = Asl[s][r0]    [tig];
            alo[mt][1] = Asl[s][r0 + 8][tig];
            alo[mt][2] = Asl[s][r0]    [tig + 4];
            alo[mt][3] = Asl[s][r0 + 8][tig + 4];
        }
#pragma unroll
        for (int nt = 0; nt < 4; nt++) {
            const int nn = wn + nt * 8 + gq;
            bhi[nt][0] = Bsh[s][tig]    [nn];
            bhi[nt][1] = Bsh[s][tig + 4][nn];
            blo[nt][0] = Bsl[s][tig]    [nn];
            blo[nt][1] = Bsl[s][tig + 4][nn];
        }
#pragma unroll
        for (int mt = 0; mt < 2; mt++)
#pragma unroll
            for (int nt = 0; nt < 4; nt++) {
                mma_bf16(acc[mt][nt], alo[mt], bhi[nt]);
                mma_bf16(acc[mt][nt], ahi[mt], blo[nt]);
                mma_bf16(acc[mt][nt], ahi[mt], bhi[nt]);
            }

        if (more) {
            store_stage(s ^ 1, a0v, a1v, b0v, b1v);
            __syncthreads();
        }
    }

    // epilogue: c0:(g, 2t) c1:(g, 2t+1) c2:(g+8, 2t) c3:(g+8, 2t+1)
#pragma unroll
    for (int nt = 0; nt < 4; nt++) {
        const int gn = ntile * BN + wn + nt * 8 + 2 * tig;
        float bx = 0.f, by = 0.f;
        if (bias) { bx = bias[gn]; by = bias[gn + 1]; }
        if (ADDVEC) { bx += addvec[gn]; by += addvec[gn + 1]; }
#pragma unroll
        for (int mt = 0; mt < 2; mt++) {
            const int gm0w = mtile * BM + wm + mt * 16 + gq;
            float v0 = acc[mt][nt][0] + bx;
            float v1 = acc[mt][nt][1] + by;
            float v2 = acc[mt][nt][2] + bx;
            float v3 = acc[mt][nt][3] + by;
            if (RELU) {
                v0 = fmaxf(v0, 0.f); v1 = fmaxf(v1, 0.f);
                v2 = fmaxf(v2, 0.f); v3 = fmaxf(v3, 0.f);
            }
            if (gm0w < M)
                *reinterpret_cast<float2*>(C + (size_t)gm0w * ldc + gn) = make_float2(v0, v1);
            if (gm0w + 8 < M)
                *reinterpret_cast<float2*>(C + (size_t)(gm0w + 8) * ldc + gn) = make_float2(v2, v3);
        }
    }
}

// ---------------- GEMM kernel wrappers ----------------
__global__ __launch_bounds__(256, 2) void k_embed(
    const int* __restrict__ src, const float* __restrict__ tab,
    const float* __restrict__ W, const float* __restrict__ bias,
    float* __restrict__ C)
{
    gemm_tc<true, false, false>(tab, FEAT_, src, W, D_, bias, nullptr,
                                C, D_, NTOK, D_, FEAT_, blockIdx.y, blockIdx.x);
}

__global__ __launch_bounds__(256, 2) void k_gemm(
    const float* __restrict__ A, const float* __restrict__ B,
    const float* __restrict__ bias, float* __restrict__ C,
    int M, int N, int K)
{
    gemm_tc<false, false, false>(A, K, nullptr, B, N, bias, nullptr,
                                 C, N, M, N, K, blockIdx.y, blockIdx.x);
}

__global__ __launch_bounds__(256, 2) void k_pbv(
    const float* __restrict__ pb, const float* __restrict__ V,
    const float* __restrict__ kv, float* __restrict__ wv)
{
    const int b = blockIdx.z;
    gemm_tc<false, false, true>(pb + (size_t)b * T_ * T_, T_, nullptr,
                                V + (size_t)b * T_ * D_, D_,
                                nullptr, kv + (size_t)b * D_,
                                wv + (size_t)b * T_ * D_, D_,
                                T_, D_, T_, 0, blockIdx.x);
}

__global__ __launch_bounds__(256, 2) void k_moe1(
    const float* __restrict__ x, const float* __restrict__ W1,
    const float* __restrict__ b1)
{
    const int e = blockIdx.z;
    const int Me = g_cnt[e];
    if ((int)(blockIdx.y * BM) >= Me) return;
    gemm_tc<true, true, false>(x, D_, g_tok + g_off[e],
                               W1 + (size_t)e * D_ * FF_, FF_,
                               b1 + (size_t)e * FF_, nullptr,
                               g_h + (size_t)g_off[e] * FF_, FF_,
                               Me, FF_, D_, blockIdx.y, blockIdx.x);
}

__global__ __launch_bounds__(256, 2) void k_moe2(
    const float* __restrict__ W2, const float* __restrict__ b2)
{
    const int e = blockIdx.z;
    const int Me = g_cnt[e];
    if ((int)(blockIdx.y * BM) >= Me) return;
    gemm_tc<false, false, false>(g_h + (size_t)g_off[e] * FF_, FF_, nullptr,
                                 W2 + (size_t)e * FF_ * D_, D_,
                                 b2 + (size_t)e * D_, nullptr,
                                 g_eo + (size_t)g_off[e] * D_, D_,
                                 Me, D_, FF_, blockIdx.y, blockIdx.x);
}

// ---------------- Fourier positional bias ----------------
__global__ void k_pb(const float* __restrict__ frac,
                     const float* __restrict__ pbW,
                     const float* __restrict__ pbb,
                     const float* __restrict__ pba,
                     float* __restrict__ pb)
{
    __shared__ float w[NF_], ph[NF_], am[NF_];
    if (threadIdx.x < NF_) {
        w[threadIdx.x]  = pbW[threadIdx.x];
        ph[threadIdx.x] = pbb[threadIdx.x];
        am[threadIdx.x] = pba[threadIdx.x];
    }
    __syncthreads();
    const int idx = blockIdx.x * 256 + threadIdx.x;   // < 32*128*128
    const int j = idx & 127;
    const int i = (idx >> 7) & 127;
    const int b = idx >> 14;
    const float d = (frac[b * T_ + j] - frac[b * T_ + i]) * SCALE_;
    float s = 0.f;
#pragma unroll
    for (int f = 0; f < NF_; f++) s += am[f] * cosf(d * w[f] + ph[f]);
    pb[idx] = s;
}

// ---------------- kv reduction: kv[b,d] = sum_t K[b,t,d]*V[b,t,d] ----------------
__global__ void k_kv(const float* __restrict__ K, const float* __restrict__ V,
                     float* __restrict__ kv)
{
    const int b = blockIdx.x;
    const int d = threadIdx.x;     // 512 threads
    const float* Kb = K + (size_t)b * T_ * D_ + d;
    const float* Vb = V + (size_t)b * T_ * D_ + d;
    float s = 0.f;
#pragma unroll 8
    for (int t = 0; t < T_; t++) s += Kb[t * D_] * Vb[t * D_];
    kv[b * D_ + d] = s;
}

// ---------------- block reduction helper (256 threads) ----------------
__device__ __forceinline__ float blk_sum_256(float v, float* red) {
    const unsigned m = 0xffffffffu;
#pragma unroll
    for (int o = 16; o > 0; o >>= 1) v += __shfl_down_sync(m, v, o);
    if ((threadIdx.x & 31) == 0) red[threadIdx.x >> 5] = v;
    __syncthreads();
    if (threadIdx.x < 32) {
        float r = (threadIdx.x < 8) ? red[threadIdx.x] : 0.f;
#pragma unroll
        for (int o = 4; o > 0; o >>= 1) r += __shfl_down_sync(m, r, o);
        if (threadIdx.x == 0) red[0] = r;
    }
    __syncthreads();
    const float r = red[0];
    __syncthreads();
    return r;
}

// ---------------- LN1: out = LN(x + y) ----------------
__global__ void k_ln(const float* __restrict__ x, const float* __restrict__ y,
                     const float* __restrict__ g, const float* __restrict__ b,
                     float* __restrict__ out)
{
    __shared__ float red[8];
    const int t = blockIdx.x;
    const int tid = threadIdx.x;      // 256
    const float* xr = x + (size_t)t * D_;
    const float* yr = y + (size_t)t * D_;
    const float v0 = xr[tid]       + yr[tid];
    const float v1 = xr[tid + 256] + yr[tid + 256];
    const float mean = blk_sum_256(v0 + v1, red) * (1.f / D_);
    const float d0 = v0 - mean, d1 = v1 - mean;
    const float var = blk_sum_256(d0 * d0 + d1 * d1, red) * (1.f / D_);
    const float inv = rsqrtf(var + EPS_);
    out[(size_t)t * D_ + tid]       = d0 * inv * g[tid]       + b[tid];
    out[(size_t)t * D_ + tid + 256] = d1 * inv * g[tid + 256] + b[tid + 256];
}

// ---------------- gating: softmax + top-2 ----------------
__global__ void k_gate(const float* __restrict__ x, const float* __restrict__ gW,
                       const float* __restrict__ gb)
{
    __shared__ float xs[D_];
    __shared__ float lg[E_];
    const int t = blockIdx.x;
    const int tid = threadIdx.x;     // 256
    xs[tid]       = x[(size_t)t * D_ + tid];
    xs[tid + 256] = x[(size_t)t * D_ + tid + 256];
    __syncthreads();

    const int e = tid >> 5;          // one warp per expert
    const int lane = tid & 31;
    float s = 0.f;
    for (int k = lane; k < D_; k += 32) s += xs[k] * gW[k * E_ + e];
    const unsigned m = 0xffffffffu;
#pragma unroll
    for (int o = 16; o > 0; o >>= 1) s += __shfl_down_sync(m, s, o);
    if (lane == 0) lg[e] = s + gb[e];
    __syncthreads();

    if (tid == 0) {
        float mx = lg[0];
#pragma unroll
        for (int k = 1; k < E_; k++) mx = fmaxf(mx, lg[k]);
        float ex[E_]; float sum = 0.f;
#pragma unroll
        for (int k = 0; k < E_; k++) { ex[k] = expf(lg[k] - mx); sum += ex[k]; }
        const float inv = 1.f / sum;
        int e0 = 0; float p0 = ex[0];
#pragma unroll
        for (int k = 1; k < E_; k++) if (ex[k] > p0) { p0 = ex[k]; e0 = k; }
        int e1 = -1; float p1 = -1.f;
#pragma unroll
        for (int k = 0; k < E_; k++)
            if (k != e0 && ex[k] > p1) { p1 = ex[k]; e1 = k; }
        g_te[2 * t]     = e0; g_tw[2 * t]     = p0 * inv;
        g_te[2 * t + 1] = e1; g_tw[2 * t + 1] = p1 * inv;
        atomicAdd(&g_cnt[e0], 1);
        atomicAdd(&g_cnt[e1], 1);
    }
}

__global__ void k_zero8() {
    if (threadIdx.x < E_) g_cnt[threadIdx.x] = 0;
}

__global__ void k_scan() {
    if (threadIdx.x == 0) {
        int a = 0;
        for (int e = 0; e < E_; e++) { g_off[e] = a; g_cur[e] = a; a += g_cnt[e]; }
        g_off[E_] = a;
    }
}

__global__ void k_scatter() {
    const int t = blockIdx.x * 256 + threadIdx.x;
    if (t >= NTOK) return;
#pragma unroll
    for (int k = 0; k < 2; k++) {
        const int e = g_te[2 * t + k];
        const int p = atomicAdd(&g_cur[e], 1);
        g_tok[p] = t;
        g_pos[2 * t + k] = p;
    }
}

// ---------------- LN2: out = LN(x + w0*eo[p0] + w1*eo[p1]) ----------------
__global__ void k_ln2(const float* __restrict__ x,
                      const float* __restrict__ g, const float* __restrict__ b,
                      float* __restrict__ out)
{
    __shared__ float red[8];
    const int t = blockIdx.x;
    const int tid = threadIdx.x;     // 256
    const int p0 = g_pos[2 * t], p1 = g_pos[2 * t + 1];
    const float w0 = g_tw[2 * t], w1 = g_tw[2 * t + 1];
    const float* e0 = g_eo + (size_t)p0 * D_;
    const float* e1 = g_eo + (size_t)p1 * D_;
    const float* xr = x + (size_t)t * D_;
    const float v0 = xr[tid]       + w0 * e0[tid]       + w1 * e1[tid];
    const float v1 = xr[tid + 256] + w0 * e0[tid + 256] + w1 * e1[tid + 256];
    const float mean = blk_sum_256(v0 + v1, red) * (1.f / D_);
    const float d0 = v0 - mean, d1 = v1 - mean;
    const float var = blk_sum_256(d0 * d0 + d1 * d1, red) * (1.f / D_);
    const float inv = rsqrtf(var + EPS_);
    out[(size_t)t * D_ + tid]       = d0 * inv * g[tid]       + b[tid];
    out[(size_t)t * D_ + tid + 256] = d1 * inv * g[tid + 256] + b[tid + 256];
}

// ---------------- host launcher ----------------
extern "C" void kernel_launch(void* const* d_in, const int* in_sizes, int n_in,
                              void* d_out, int out_size)
{
    const int*   src  = (const int*)  d_in[0];
    const float* frac = (const float*)d_in[1];
    const float* tab  = (const float*)d_in[2];
    const float* Wm2v = (const float*)d_in[3];
    const float* bm2v = (const float*)d_in[4];
    const float* pbW  = (const float*)d_in[5];
    const float* pbb  = (const float*)d_in[6];
    const float* pba  = (const float*)d_in[7];
    const float* Wk   = (const float*)d_in[8];
    const float* bk   = (const float*)d_in[9];
    const float* Wv   = (const float*)d_in[10];
    const float* bv   = (const float*)d_in[11];
    const float* Wo   = (const float*)d_in[12];
    const float* bo   = (const float*)d_in[13];
    const float* ln1g = (const float*)d_in[14];
    const float* ln1b = (const float*)d_in[15];
    const float* ln2g = (const float*)d_in[16];
    const float* ln2b = (const float*)d_in[17];
    const float* gW   = (const float*)d_in[18];
    const float* gb   = (const float*)d_in[19];
    const float* eW1  = (const float*)d_in[20];
    const float* eb1  = (const float*)d_in[21];
    const float* eW2  = (const float*)d_in[22];
    const float* eb2  = (const float*)d_in[23];

    float *x, *pb, *Kb, *Vb, *kvb, *wv, *o;
    cudaGetSymbolAddress((void**)&x,   g_x);
    cudaGetSymbolAddress((void**)&pb,  g_pb);
    cudaGetSymbolAddress((void**)&Kb,  g_K);
    cudaGetSymbolAddress((void**)&Vb,  g_V);
    cudaGetSymbolAddress((void**)&kvb, g_kv);
    cudaGetSymbolAddress((void**)&wv,  g_wv);
    cudaGetSymbolAddress((void**)&o,   g_o);

    const dim3 g84(8, 32);        // N=512/64 tiles x M=4096/128 tiles

    // x = embed_table[src] @ W_m2v + b
    k_embed<<<g84, 256>>>(src, tab, Wm2v, bm2v, x);
    // positional bias
    k_pb<<<(B_ * T_ * T_) / 256, 256>>>(frac, pbW, pbb, pba, pb);

    for (int i = 0; i < NL_; i++) {
        const size_t wOff = (size_t)i * D_ * D_;
        k_gemm<<<g84, 256>>>(x,  Wk + wOff, bk + i * D_, Kb, NTOK, D_, D_);
        k_gemm<<<g84, 256>>>(x,  Wv + wOff, bv + i * D_, Vb, NTOK, D_, D_);
        k_kv<<<B_, 512>>>(Kb, Vb, kvb);
        k_pbv<<<dim3(8, 1, B_), 256>>>(pb, Vb, kvb, wv);
        k_gemm<<<g84, 256>>>(wv, Wo + wOff, bo + i * D_, o, NTOK, D_, D_);
        k_ln<<<NTOK, 256>>>(x, o, ln1g + i * D_, ln1b + i * D_, x);

        k_zero8<<<1, 32>>>();
        k_gate<<<NTOK, 256>>>(x, gW + (size_t)i * D_ * E_, gb + i * E_);
        k_scan<<<1, 1>>>();
        k_scatter<<<NTOK / 256, 256>>>();

        k_moe1<<<dim3(FF_ / BN, 32, E_), 256>>>(
            x, eW1 + (size_t)i * E_ * D_ * FF_, eb1 + (size_t)i * E_ * FF_);
        k_moe2<<<dim3(D_ / BN, 32, E_), 256>>>(
            eW2 + (size_t)i * E_ * FF_ * D_, eb2 + (size_t)i * E_ * D_);

        float* dst = (i == NL_ - 1) ? (float*)d_out : x;
        k_ln2<<<NTOK, 256>>>(x, ln2g + i * D_, ln2b + i * D_, dst);
    }
}

// round 7
// speedup vs baseline: 1.0112x; 1.0112x over previous
#include <cuda_runtime.h>
#include <cuda_bf16.h>

// ---------------- problem constants ----------------
#define B_   32
#define T_   128
#define D_   512
#define H_   8
#define HD_  64
#define FF_  2048
#define E_   8
#define NL_  3
#define NF_  16
#define FEAT_ 200
#define NTOK  4096          // B*T
#define NSLOT 8192          // NTOK*2 (top-2 slots)
#define SCALE_ 10.0f
#define EPS_   1e-5f

// ---------------- scratch (device globals; no allocation allowed) ----------------
__device__ float g_x  [NTOK * D_];
__device__ float g_pb [B_ * T_ * T_];
__device__ float g_K  [NTOK * D_];
__device__ float g_V  [NTOK * D_];
__device__ float g_kv [B_ * D_];
__device__ float g_wv [NTOK * D_];
__device__ float g_o  [NTOK * D_];
__device__ float g_h  [(NSLOT + 128) * FF_];
__device__ float g_eo [(NSLOT + 128) * D_];
__device__ int   g_te [NSLOT];
__device__ float g_tw [NSLOT];
__device__ int   g_cnt[E_];
__device__ int   g_off[E_ + 1];
__device__ int   g_cur[E_];
__device__ int   g_tok[NSLOT + 128];
__device__ int   g_pos[NSLOT];

// ---------------- bf16x3 tensor-core GEMM core: 128x64x16, 2 CTAs/SM ----------------
#define BM 128
#define BN 64
#define BK 16
#define AW 12      // A smem row stride in words (8 + 4 pad -> conflict-free frags)
#define BW 72      // B smem row stride in words (64 + 8 pad; 72 % 32 == 8, conflict-free)

__device__ __forceinline__ float4 ld4(const float* p) {
    return *reinterpret_cast<const float4*>(p);
}
__device__ __forceinline__ float2 ld2(const float* p) {
    return *reinterpret_cast<const float2*>(p);
}

// pack two floats as bf16x2 word: low half = lo, high half = hi
__device__ __forceinline__ unsigned pack2(float lo, float hi) {
    unsigned r;
    asm("cvt.rn.bf16x2.f32 %0, %1, %2;" : "=r"(r) : "f"(hi), "f"(lo));
    return r;
}

__device__ __forceinline__ void split_bf(float x, float& h, float& l) {
    h = __bfloat162float(__float2bfloat16_rn(x));
    l = x - h;
}

__device__ __forceinline__ void mma_bf16(float* c, const unsigned* a, const unsigned* b) {
    asm("mma.sync.aligned.m16n8k16.row.col.f32.bf16.bf16.f32 "
        "{%0,%1,%2,%3}, {%4,%5,%6,%7}, {%8,%9}, {%0,%1,%2,%3};"
        : "+f"(c[0]), "+f"(c[1]), "+f"(c[2]), "+f"(c[3])
        : "r"(a[0]), "r"(a[1]), "r"(a[2]), "r"(a[3]), "r"(b[0]), "r"(b[1]));
}

// C[M,N] = op( gather(A)[M,K] @ B[K,N] + bias + addvec )
// 256 threads = 8 warps (4m x 2n), each warp 32x32 of m16n8k16 tiles, hi/lo split.
template <bool GATHER, bool RELU, bool ADDVEC>
__device__ __forceinline__ void gemm_tc(
    const float* __restrict__ A, int lda, const int* __restrict__ rowmap,
    const float* __restrict__ B, int ldb,
    const float* __restrict__ bias, const float* __restrict__ addvec,
    float* __restrict__ C, int ldc,
    int M, int N, int K, int mtile, int ntile)
{
    __shared__ unsigned Ash[2][BM][AW];   // bf16x2 words: word j = k pair (2j, 2j+1)
    __shared__ unsigned Asl[2][BM][AW];
    __shared__ unsigned Bsh[2][8][BW];    // [kp][n]: word = k pair (2kp, 2kp+1) at col n
    __shared__ unsigned Bsl[2][8][BW];

    const int tid  = threadIdx.x;
    const int lane = tid & 31;
    const int warp = tid >> 5;
    const int wm = (warp >> 1) * 32;      // 0,32,64,96
    const int wn = (warp & 1) * 32;       // 0,32
    const int gq  = lane >> 2;            // 0..7
    const int tig = lane & 3;             // 0..3

    // A tile loader: thread handles rows ar0, ar0+64; floats k = ac..ac+3 -> words wc, wc+1
    const int ar0 = tid >> 2;             // 0..63
    const int ac  = (tid & 3) * 4;
    const int wc  = (tid & 3) * 2;
    int gm0 = mtile * BM + ar0;       if (gm0 > M - 1) gm0 = M - 1;
    int gm1 = mtile * BM + ar0 + 64;  if (gm1 > M - 1) gm1 = M - 1;
    const int ra0 = GATHER ? rowmap[gm0] : gm0;
    const int ra1 = GATHER ? rowmap[gm1] : gm1;
    const float* Ap0 = A + (size_t)ra0 * lda + ac;
    const float* Ap1 = A + (size_t)ra1 * lda + ac;

    // B tile loader: thread handles k-rows 2*kp, 2*kp+1; cols bc, bc+1
    const int kp = tid >> 5;              // 0..7
    const int bc = (tid & 31) * 2;        // 0..62
    const float* Bp = B + (size_t)(2 * kp) * ldb + ntile * BN + bc;

    float acc[2][4][4];
#pragma unroll
    for (int i = 0; i < 2; i++)
#pragma unroll
        for (int j = 0; j < 4; j++)
#pragma unroll
            for (int r = 0; r < 4; r++) acc[i][j][r] = 0.f;

    const int nk = (K + BK - 1) / BK;
    const float4 z4 = make_float4(0.f, 0.f, 0.f, 0.f);
    const float2 z2 = make_float2(0.f, 0.f);

    float4 a0v, a1v;
    float2 b0v, b1v;

    // prefetch tile 0 into regs (K is a multiple of 4; guards exact)
    a0v = (ac < K) ? ld4(Ap0) : z4;
    a1v = (ac < K) ? ld4(Ap1) : z4;
    b0v = (2 * kp < K) ? ld2(Bp) : z2;
    b1v = (2 * kp < K) ? ld2(Bp + ldb) : z2;

    auto store_stage = [&](int s, const float4& av0, const float4& av1,
                           const float2& bv0, const float2& bv1) {
        float h0, l0, h1, l1, h2, l2, h3, l3;
        split_bf(av0.x, h0, l0); split_bf(av0.y, h1, l1);
        split_bf(av0.z, h2, l2); split_bf(av0.w, h3, l3);
        *reinterpret_cast<uint2*>(&Ash[s][ar0][wc]) = make_uint2(pack2(h0, h1), pack2(h2, h3));
        *reinterpret_cast<uint2*>(&Asl[s][ar0][wc]) = make_uint2(pack2(l0, l1), pack2(l2, l3));
        split_bf(av1.x, h0, l0); split_bf(av1.y, h1, l1);
        split_bf(av1.z, h2, l2); split_bf(av1.w, h3, l3);
        *reinterpret_cast<uint2*>(&Ash[s][ar0 + 64][wc]) = make_uint2(pack2(h0, h1), pack2(h2, h3));
        *reinterpret_cast<uint2*>(&Asl[s][ar0 + 64][wc]) = make_uint2(pack2(l0, l1), pack2(l2, l3));
        float e0h, e0l, e1h, e1l;   // even-k (row 2kp)
        float o0h, o0l, o1h, o1l;   // odd-k  (row 2kp+1)
        split_bf(bv0.x, e0h, e0l); split_bf(bv0.y, e1h, e1l);
        split_bf(bv1.x, o0h, o0l); split_bf(bv1.y, o1h, o1l);
        *reinterpret_cast<uint2*>(&Bsh[s][kp][bc]) = make_uint2(pack2(e0h, o0h), pack2(e1h, o1h));
        *reinterpret_cast<uint2*>(&Bsl[s][kp][bc]) = make_uint2(pack2(e0l, o0l), pack2(e1l, o1l));
    };

    store_stage(0, a0v, a1v, b0v, b1v);
    __syncthreads();

    for (int kt = 0; kt < nk; kt++) {
        const int s = kt & 1;
        const bool more = (kt + 1 < nk);
        if (more) {
            const int kb = (kt + 1) * BK;
            a0v = (kb + ac < K) ? ld4(Ap0 + kb) : z4;
            a1v = (kb + ac < K) ? ld4(Ap1 + kb) : z4;
            b0v = (kb + 2 * kp < K) ? ld2(Bp + (size_t)kb * ldb) : z2;
            b1v = (kb + 2 * kp < K) ? ld2(Bp + (size_t)(kb + 1) * ldb) : z2;
        }

        unsigned ahi[2][4], alo[2][4], bhi[4][2], blo[4][2];
#pragma unroll
        for (int mt = 0; mt < 2; mt++) {
            const int r0 = wm + mt * 16 + gq;
            ahi[mt][0] = Ash[s][r0]    [tig];
            ahi[mt][1] = Ash[s][r0 + 8][tig];
            ahi[mt][2] = Ash[s][r0]    [tig + 4];
            ahi[mt][3] = Ash[s][r0 + 8][tig + 4];
            alo[mt][0] = Asl[s][r0]    [tig];
            alo[mt][1] = Asl[s][r0 + 8][tig];
            alo[mt][2] = Asl[s][r0]    [tig + 4];
            alo[mt][3] = Asl[s][r0 + 8][tig + 4];
        }
#pragma unroll
        for (int nt = 0; nt < 4; nt++) {
            const int nn = wn + nt * 8 + gq;
            bhi[nt][0] = Bsh[s][tig]    [nn];
            bhi[nt][1] = Bsh[s][tig + 4][nn];
            blo[nt][0] = Bsl[s][tig]    [nn];
            blo[nt][1] = Bsl[s][tig + 4][nn];
        }
        // phase-ordered MMAs: 8 independent acc tiles between writes to the
        // same accumulator -> HMMA latency hidden by independent issues.
#pragma unroll
        for (int mt = 0; mt < 2; mt++)
#pragma unroll
            for (int nt = 0; nt < 4; nt++)
                mma_bf16(acc[mt][nt], alo[mt], bhi[nt]);
#pragma unroll
        for (int mt = 0; mt < 2; mt++)
#pragma unroll
            for (int nt = 0; nt < 4; nt++)
                mma_bf16(acc[mt][nt], ahi[mt], blo[nt]);
#pragma unroll
        for (int mt = 0; mt < 2; mt++)
#pragma unroll
            for (int nt = 0; nt < 4; nt++)
                mma_bf16(acc[mt][nt], ahi[mt], bhi[nt]);

        if (more) {
            store_stage(s ^ 1, a0v, a1v, b0v, b1v);
            __syncthreads();
        }
    }

    // epilogue: c0:(g, 2t) c1:(g, 2t+1) c2:(g+8, 2t) c3:(g+8, 2t+1)
#pragma unroll
    for (int nt = 0; nt < 4; nt++) {
        const int gn = ntile * BN + wn + nt * 8 + 2 * tig;
        float bx = 0.f, by = 0.f;
        if (bias) { bx = bias[gn]; by = bias[gn + 1]; }
        if (ADDVEC) { bx += addvec[gn]; by += addvec[gn + 1]; }
#pragma unroll
        for (int mt = 0; mt < 2; mt++) {
            const int gm0w = mtile * BM + wm + mt * 16 + gq;
            float v0 = acc[mt][nt][0] + bx;
            float v1 = acc[mt][nt][1] + by;
            float v2 = acc[mt][nt][2] + bx;
            float v3 = acc[mt][nt][3] + by;
            if (RELU) {
                v0 = fmaxf(v0, 0.f); v1 = fmaxf(v1, 0.f);
                v2 = fmaxf(v2, 0.f); v3 = fmaxf(v3, 0.f);
            }
            if (gm0w < M)
                *reinterpret_cast<float2*>(C + (size_t)gm0w * ldc + gn) = make_float2(v0, v1);
            if (gm0w + 8 < M)
                *reinterpret_cast<float2*>(C + (size_t)(gm0w + 8) * ldc + gn) = make_float2(v2, v3);
        }
    }
}

// ---------------- GEMM kernel wrappers ----------------
__global__ __launch_bounds__(256, 2) void k_embed(
    const int* __restrict__ src, const float* __restrict__ tab,
    const float* __restrict__ W, const float* __restrict__ bias,
    float* __restrict__ C)
{
    gemm_tc<true, false, false>(tab, FEAT_, src, W, D_, bias, nullptr,
                                C, D_, NTOK, D_, FEAT_, blockIdx.y, blockIdx.x);
}

__global__ __launch_bounds__(256, 2) void k_gemm(
    const float* __restrict__ A, const float* __restrict__ B,
    const float* __restrict__ bias, float* __restrict__ C,
    int M, int N, int K)
{
    gemm_tc<false, false, false>(A, K, nullptr, B, N, bias, nullptr,
                                 C, N, M, N, K, blockIdx.y, blockIdx.x);
}

__global__ __launch_bounds__(256, 2) void k_pbv(
    const float* __restrict__ pb, const float* __restrict__ V,
    const float* __restrict__ kv, float* __restrict__ wv)
{
    const int b = blockIdx.z;
    gemm_tc<false, false, true>(pb + (size_t)b * T_ * T_, T_, nullptr,
                                V + (size_t)b * T_ * D_, D_,
                                nullptr, kv + (size_t)b * D_,
                                wv + (size_t)b * T_ * D_, D_,
                                T_, D_, T_, 0, blockIdx.x);
}

__global__ __launch_bounds__(256, 2) void k_moe1(
    const float* __restrict__ x, const float* __restrict__ W1,
    const float* __restrict__ b1)
{
    const int e = blockIdx.z;
    const int Me = g_cnt[e];
    if ((int)(blockIdx.y * BM) >= Me) return;
    gemm_tc<true, true, false>(x, D_, g_tok + g_off[e],
                               W1 + (size_t)e * D_ * FF_, FF_,
                               b1 + (size_t)e * FF_, nullptr,
                               g_h + (size_t)g_off[e] * FF_, FF_,
                               Me, FF_, D_, blockIdx.y, blockIdx.x);
}

__global__ __launch_bounds__(256, 2) void k_moe2(
    const float* __restrict__ W2, const float* __restrict__ b2)
{
    const int e = blockIdx.z;
    const int Me = g_cnt[e];
    if ((int)(blockIdx.y * BM) >= Me) return;
    gemm_tc<false, false, false>(g_h + (size_t)g_off[e] * FF_, FF_, nullptr,
                                 W2 + (size_t)e * FF_ * D_, D_,
                                 b2 + (size_t)e * D_, nullptr,
                                 g_eo + (size_t)g_off[e] * D_, D_,
                                 Me, D_, FF_, blockIdx.y, blockIdx.x);
}

// ---------------- Fourier positional bias ----------------
__global__ void k_pb(const float* __restrict__ frac,
                     const float* __restrict__ pbW,
                     const float* __restrict__ pbb,
                     const float* __restrict__ pba,
                     float* __restrict__ pb)
{
    __shared__ float w[NF_], ph[NF_], am[NF_];
    if (threadIdx.x < NF_) {
        w[threadIdx.x]  = pbW[threadIdx.x];
        ph[threadIdx.x] = pbb[threadIdx.x];
        am[threadIdx.x] = pba[threadIdx.x];
    }
    __syncthreads();
    const int idx = blockIdx.x * 256 + threadIdx.x;   // < 32*128*128
    const int j = idx & 127;
    const int i = (idx >> 7) & 127;
    const int b = idx >> 14;
    const float d = (frac[b * T_ + j] - frac[b * T_ + i]) * SCALE_;
    float s = 0.f;
#pragma unroll
    for (int f = 0; f < NF_; f++) s += am[f] * cosf(d * w[f] + ph[f]);
    pb[idx] = s;
}

// ---------------- kv reduction: kv[b,d] = sum_t K[b,t,d]*V[b,t,d] ----------------
__global__ void k_kv(const float* __restrict__ K, const float* __restrict__ V,
                     float* __restrict__ kv)
{
    const int b = blockIdx.x;
    const int d = threadIdx.x;     // 512 threads
    const float* Kb = K + (size_t)b * T_ * D_ + d;
    const float* Vb = V + (size_t)b * T_ * D_ + d;
    float s = 0.f;
#pragma unroll 8
    for (int t = 0; t < T_; t++) s += Kb[t * D_] * Vb[t * D_];
    kv[b * D_ + d] = s;
}

// ---------------- block reduction helper (256 threads) ----------------
__device__ __forceinline__ float blk_sum_256(float v, float* red) {
    const unsigned m = 0xffffffffu;
#pragma unroll
    for (int o = 16; o > 0; o >>= 1) v += __shfl_down_sync(m, v, o);
    if ((threadIdx.x & 31) == 0) red[threadIdx.x >> 5] = v;
    __syncthreads();
    if (threadIdx.x < 32) {
        float r = (threadIdx.x < 8) ? red[threadIdx.x] : 0.f;
#pragma unroll
        for (int o = 4; o > 0; o >>= 1) r += __shfl_down_sync(m, r, o);
        if (threadIdx.x == 0) red[0] = r;
    }
    __syncthreads();
    const float r = red[0];
    __syncthreads();
    return r;
}

// ---------------- LN1: out = LN(x + y) ----------------
__global__ void k_ln(const float* __restrict__ x, const float* __restrict__ y,
                     const float* __restrict__ g, const float* __restrict__ b,
                     float* __restrict__ out)
{
    __shared__ float red[8];
    const int t = blockIdx.x;
    const int tid = threadIdx.x;      // 256
    const float* xr = x + (size_t)t * D_;
    const float* yr = y + (size_t)t * D_;
    const float v0 = xr[tid]       + yr[tid];
    const float v1 = xr[tid + 256] + yr[tid + 256];
    const float mean = blk_sum_256(v0 + v1, red) * (1.f / D_);
    const float d0 = v0 - mean, d1 = v1 - mean;
    const float var = blk_sum_256(d0 * d0 + d1 * d1, red) * (1.f / D_);
    const float inv = rsqrtf(var + EPS_);
    out[(size_t)t * D_ + tid]       = d0 * inv * g[tid]       + b[tid];
    out[(size_t)t * D_ + tid + 256] = d1 * inv * g[tid + 256] + b[tid + 256];
}

// ---------------- gating: softmax + top-2 ----------------
__global__ void k_gate(const float* __restrict__ x, const float* __restrict__ gW,
                       const float* __restrict__ gb)
{
    __shared__ float xs[D_];
    __shared__ float lg[E_];
    const int t = blockIdx.x;
    const int tid = threadIdx.x;     // 256
    xs[tid]       = x[(size_t)t * D_ + tid];
    xs[tid + 256] = x[(size_t)t * D_ + tid + 256];
    __syncthreads();

    const int e = tid >> 5;          // one warp per expert
    const int lane = tid & 31;
    float s = 0.f;
    for (int k = lane; k < D_; k += 32) s += xs[k] * gW[k * E_ + e];
    const unsigned m = 0xffffffffu;
#pragma unroll
    for (int o = 16; o > 0; o >>= 1) s += __shfl_down_sync(m, s, o);
    if (lane == 0) lg[e] = s + gb[e];
    __syncthreads();

    if (tid == 0) {
        float mx = lg[0];
#pragma unroll
        for (int k = 1; k < E_; k++) mx = fmaxf(mx, lg[k]);
        float ex[E_]; float sum = 0.f;
#pragma unroll
        for (int k = 0; k < E_; k++) { ex[k] = expf(lg[k] - mx); sum += ex[k]; }
        const float inv = 1.f / sum;
        int e0 = 0; float p0 = ex[0];
#pragma unroll
        for (int k = 1; k < E_; k++) if (ex[k] > p0) { p0 = ex[k]; e0 = k; }
        int e1 = -1; float p1 = -1.f;
#pragma unroll
        for (int k = 0; k < E_; k++)
            if (k != e0 && ex[k] > p1) { p1 = ex[k]; e1 = k; }
        g_te[2 * t]     = e0; g_tw[2 * t]     = p0 * inv;
        g_te[2 * t + 1] = e1; g_tw[2 * t + 1] = p1 * inv;
        atomicAdd(&g_cnt[e0], 1);
        atomicAdd(&g_cnt[e1], 1);
    }
}

__global__ void k_zero8() {
    if (threadIdx.x < E_) g_cnt[threadIdx.x] = 0;
}

__global__ void k_scan() {
    if (threadIdx.x == 0) {
        int a = 0;
        for (int e = 0; e < E_; e++) { g_off[e] = a; g_cur[e] = a; a += g_cnt[e]; }
        g_off[E_] = a;
    }
}

__global__ void k_scatter() {
    const int t = blockIdx.x * 256 + threadIdx.x;
    if (t >= NTOK) return;
#pragma unroll
    for (int k = 0; k < 2; k++) {
        const int e = g_te[2 * t + k];
        const int p = atomicAdd(&g_cur[e], 1);
        g_tok[p] = t;
        g_pos[2 * t + k] = p;
    }
}

// ---------------- LN2: out = LN(x + w0*eo[p0] + w1*eo[p1]) ----------------
__global__ void k_ln2(const float* __restrict__ x,
                      const float* __restrict__ g, const float* __restrict__ b,
                      float* __restrict__ out)
{
    __shared__ float red[8];
    const int t = blockIdx.x;
    const int tid = threadIdx.x;     // 256
    const int p0 = g_pos[2 * t], p1 = g_pos[2 * t + 1];
    const float w0 = g_tw[2 * t], w1 = g_tw[2 * t + 1];
    const float* e0 = g_eo + (size_t)p0 * D_;
    const float* e1 = g_eo + (size_t)p1 * D_;
    const float* xr = x + (size_t)t * D_;
    const float v0 = xr[tid]       + w0 * e0[tid]       + w1 * e1[tid];
    const float v1 = xr[tid + 256] + w0 * e0[tid + 256] + w1 * e1[tid + 256];
    const float mean = blk_sum_256(v0 + v1, red) * (1.f / D_);
    const float d0 = v0 - mean, d1 = v1 - mean;
    const float var = blk_sum_256(d0 * d0 + d1 * d1, red) * (1.f / D_);
    const float inv = rsqrtf(var + EPS_);
    out[(size_t)t * D_ + tid]       = d0 * inv * g[tid]       + b[tid];
    out[(size_t)t * D_ + tid + 256] = d1 * inv * g[tid + 256] + b[tid + 256];
}

// ---------------- host launcher ----------------
extern "C" void kernel_launch(void* const* d_in, const int* in_sizes, int n_in,
                              void* d_out, int out_size)
{
    const int*   src  = (const int*)  d_in[0];
    const float* frac = (const float*)d_in[1];
    const float* tab  = (const float*)d_in[2];
    const float* Wm2v = (const float*)d_in[3];
    const float* bm2v = (const float*)d_in[4];
    const float* pbW  = (const float*)d_in[5];
    const float* pbb  = (const float*)d_in[6];
    const float* pba  = (const float*)d_in[7];
    const float* Wk   = (const float*)d_in[8];
    const float* bk   = (const float*)d_in[9];
    const float* Wv   = (const float*)d_in[10];
    const float* bv   = (const float*)d_in[11];
    const float* Wo   = (const float*)d_in[12];
    const float* bo   = (const float*)d_in[13];
    const float* ln1g = (const float*)d_in[14];
    const float* ln1b = (const float*)d_in[15];
    const float* ln2g = (const float*)d_in[16];
    const float* ln2b = (const float*)d_in[17];
    const float* gW   = (const float*)d_in[18];
    const float* gb   = (const float*)d_in[19];
    const float* eW1  = (const float*)d_in[20];
    const float* eb1  = (const float*)d_in[21];
    const float* eW2  = (const float*)d_in[22];
    const float* eb2  = (const float*)d_in[23];

    float *x, *pb, *Kb, *Vb, *kvb, *wv, *o;
    cudaGetSymbolAddress((void**)&x,   g_x);
    cudaGetSymbolAddress((void**)&pb,  g_pb);
    cudaGetSymbolAddress((void**)&Kb,  g_K);
    cudaGetSymbolAddress((void**)&Vb,  g_V);
    cudaGetSymbolAddress((void**)&kvb, g_kv);
    cudaGetSymbolAddress((void**)&wv,  g_wv);
    cudaGetSymbolAddress((void**)&o,   g_o);

    const dim3 g84(8, 32);        // N=512/64 tiles x M=4096/128 tiles

    // x = embed_table[src] @ W_m2v + b
    k_embed<<<g84, 256>>>(src, tab, Wm2v, bm2v, x);
    // positional bias
    k_pb<<<(B_ * T_ * T_) / 256, 256>>>(frac, pbW, pbb, pba, pb);

    for (int i = 0; i < NL_; i++) {
        const size_t wOff = (size_t)i * D_ * D_;
        k_gemm<<<g84, 256>>>(x,  Wk + wOff, bk + i * D_, Kb, NTOK, D_, D_);
        k_gemm<<<g84, 256>>>(x,  Wv + wOff, bv + i * D_, Vb, NTOK, D_, D_);
        k_kv<<<B_, 512>>>(Kb, Vb, kvb);
        k_pbv<<<dim3(8, 1, B_), 256>>>(pb, Vb, kvb, wv);
        k_gemm<<<g84, 256>>>(wv, Wo + wOff, bo + i * D_, o, NTOK, D_, D_);
        k_ln<<<NTOK, 256>>>(x, o, ln1g + i * D_, ln1b + i * D_, x);

        k_zero8<<<1, 32>>>();
        k_gate<<<NTOK, 256>>>(x, gW + (size_t)i * D_ * E_, gb + i * E_);
        k_scan<<<1, 1>>>();
        k_scatter<<<NTOK / 256, 256>>>();

        k_moe1<<<dim3(FF_ / BN, 32, E_), 256>>>(
            x, eW1 + (size_t)i * E_ * D_ * FF_, eb1 + (size_t)i * E_ * FF_);
        k_moe2<<<dim3(D_ / BN, 32, E_), 256>>>(
            eW2 + (size_t)i * E_ * FF_ * D_, eb2 + (size_t)i * E_ * D_);

        float* dst = (i == NL_ - 1) ? (float*)d_out : x;
        k_ln2<<<NTOK, 256>>>(x, ln2g + i * D_, ln2b + i * D_, dst);
    }
}

// round 9
// speedup vs baseline: 1.0872x; 1.0752x over previous
#include <cuda_runtime.h>
#include <cuda_bf16.h>
#include <cstdint>

// ---------------- problem constants ----------------
#define B_   32
#define T_   128
#define D_   512
#define FF_  2048
#define E_   8
#define NL_  3
#define NF_  16
#define FEAT_ 200
#define NTOK  4096          // B*T
#define NSLOT 8192          // NTOK*2 (top-2 slots)
#define SCALE_ 10.0f
#define EPS_   1e-5f

// ---------------- scratch (device globals; no allocation allowed) ----------------
__device__ float g_x  [NTOK * D_];
__device__ float g_pb [B_ * T_ * T_];
__device__ float g_K  [NTOK * D_];
__device__ float g_V  [NTOK * D_];
__device__ float g_kv [B_ * D_];
__device__ float g_wv [NTOK * D_];
__device__ float g_o  [NTOK * D_];
__device__ float g_h  [(NSLOT + 128) * FF_];
__device__ float g_eo [(NSLOT + 128) * D_];
__device__ int   g_te [NSLOT];
__device__ float g_tw [NSLOT];
__device__ int   g_cnt[E_];
__device__ int   g_off[E_ + 1];
__device__ int   g_cur[E_];
__device__ int   g_tok[NSLOT + 128];
__device__ int   g_pos[NSLOT];

// ---------------- bf16x3 mma.sync GEMM core with ldmatrix: 128x128x32 ----------------
#define BM 128
#define BN 128
#define BK 32
#define RSTRIDE 80            // bytes per smem row (64B data + 16B pad)
#define AH_OFF 0
#define AL_OFF 10240
#define BH_OFF 20480
#define BL_OFF 30720
#define STAGE_BYTES 40960
#define SMEM_SZ (2 * STAGE_BYTES)   // 81920 bytes dynamic

__device__ __forceinline__ uint32_t smem_u32(const void* p) {
    uint32_t a;
    asm("{ .reg .u64 t; cvta.to.shared.u64 t, %1; cvt.u32.u64 %0, t; }" : "=r"(a) : "l"(p));
    return a;
}

__device__ __forceinline__ float4 ld4(const float* p) {
    return *reinterpret_cast<const float4*>(p);
}

__device__ __forceinline__ unsigned pack2(float lo, float hi) {
    unsigned r;
    asm("cvt.rn.bf16x2.f32 %0, %1, %2;" : "=r"(r) : "f"(hi), "f"(lo));
    return r;
}

__device__ __forceinline__ void split_bf(float x, float& h, float& l) {
    h = __bfloat162float(__float2bfloat16_rn(x));
    l = x - h;
}

__device__ __forceinline__ void ldsm_x4(unsigned* r, uint32_t addr) {
    asm volatile("ldmatrix.sync.aligned.m8n8.x4.shared.b16 {%0,%1,%2,%3}, [%4];"
                 : "=r"(r[0]), "=r"(r[1]), "=r"(r[2]), "=r"(r[3]) : "r"(addr));
}

__device__ __forceinline__ void mma_bf16(float* c, const unsigned* a, const unsigned* b) {
    asm("mma.sync.aligned.m16n8k16.row.col.f32.bf16.bf16.f32 "
        "{%0,%1,%2,%3}, {%4,%5,%6,%7}, {%8,%9}, {%0,%1,%2,%3};"
        : "+f"(c[0]), "+f"(c[1]), "+f"(c[2]), "+f"(c[3])
        : "r"(a[0]), "r"(a[1]), "r"(a[2]), "r"(a[3]), "r"(b[0]), "r"(b[1]));
}

// C[M,N] = op( gather(A)[M,K] @ B[K,N] + bias + addvec )
// 256 threads = 8 warps (2m x 4n), warp tile 64x32, bf16 hi/lo split (bf16x3).
// A smem: [128 m][32 k] bf16 rows (RSTRIDE); B smem: [128 n][32 k] (transposed copy).
template <bool GATHER, bool RELU, bool ADDVEC>
__device__ __forceinline__ void gemm_tc(
    const float* __restrict__ A, int lda, const int* __restrict__ rowmap,
    const float* __restrict__ B, int ldb,
    const float* __restrict__ bias, const float* __restrict__ addvec,
    float* __restrict__ C, int ldc,
    int M, int N, int K, int mtile, int ntile)
{
    extern __shared__ char smem[];
    const int tid  = threadIdx.x;
    const int lane = tid & 31;
    const int warp = tid >> 5;
    const int wm = (warp >> 2) * 64;      // 0 or 64
    const int wn = (warp & 3) * 32;       // 0,32,64,96
    const int gq  = lane >> 2;            // 0..7
    const int tig = lane & 3;             // 0..3

    // ---- A loader mapping: thread -> (row ar, k-half kh) ----
    const int ar = tid >> 1;              // 0..127
    const int kh = tid & 1;               // 0/1 -> k 0..15 / 16..31
    int gma = mtile * BM + ar; if (gma > M - 1) gma = M - 1;
    const int raa = GATHER ? rowmap[gma] : gma;
    const float* ApBase = A + (size_t)raa * lda;

    // ---- B loader mapping: thread -> (col bn, k-half bkh); transpose into [n][k] ----
    const int bn  = tid & 127;            // 0..127
    const int bkh = tid >> 7;             // 0/1
    const int gnb = ntile * BN + bn;

    float acc[4][4][4];
#pragma unroll
    for (int i = 0; i < 4; i++)
#pragma unroll
        for (int j = 0; j < 4; j++)
#pragma unroll
            for (int r = 0; r < 4; r++) acc[i][j][r] = 0.f;

    const int nc = (K + BK - 1) / BK;
    const float4 z4 = make_float4(0.f, 0.f, 0.f, 0.f);

    float4 pa[4];
    float  pb[16];

    auto load_pref = [&](int ch) {
        const int ka = ch * BK + kh * 16;
#pragma unroll
        for (int q = 0; q < 4; q++) {
            const int kg = ka + 4 * q;
            pa[q] = (kg + 4 <= K) ? ld4(ApBase + kg) : z4;
        }
        const int kb = ch * BK + bkh * 16;
#pragma unroll
        for (int i = 0; i < 16; i++) {
            const int kg = kb + i;
            pb[i] = (kg < K) ? B[(size_t)kg * ldb + gnb] : 0.f;
        }
    };

    auto store_pref = [&](char* st) {
        // A rows
        unsigned wh[8], wl[8];
#pragma unroll
        for (int q = 0; q < 4; q++) {
            float h0, l0, h1, l1, h2, l2, h3, l3;
            split_bf(pa[q].x, h0, l0); split_bf(pa[q].y, h1, l1);
            split_bf(pa[q].z, h2, l2); split_bf(pa[q].w, h3, l3);
            wh[2 * q]     = pack2(h0, h1); wh[2 * q + 1] = pack2(h2, h3);
            wl[2 * q]     = pack2(l0, l1); wl[2 * q + 1] = pack2(l2, l3);
        }
        char* arow = st + ar * RSTRIDE + kh * 32;
        *reinterpret_cast<uint4*>(arow + AH_OFF)      = make_uint4(wh[0], wh[1], wh[2], wh[3]);
        *reinterpret_cast<uint4*>(arow + AH_OFF + 16) = make_uint4(wh[4], wh[5], wh[6], wh[7]);
        *reinterpret_cast<uint4*>(arow + AL_OFF)      = make_uint4(wl[0], wl[1], wl[2], wl[3]);
        *reinterpret_cast<uint4*>(arow + AL_OFF + 16) = make_uint4(wl[4], wl[5], wl[6], wl[7]);
        // B rows (transposed)
        unsigned vh[8], vl[8];
#pragma unroll
        for (int i = 0; i < 8; i++) {
            float h0, l0, h1, l1;
            split_bf(pb[2 * i], h0, l0); split_bf(pb[2 * i + 1], h1, l1);
            vh[i] = pack2(h0, h1); vl[i] = pack2(l0, l1);
        }
        char* brow = st + bn * RSTRIDE + bkh * 32;
        *reinterpret_cast<uint4*>(brow + BH_OFF)      = make_uint4(vh[0], vh[1], vh[2], vh[3]);
        *reinterpret_cast<uint4*>(brow + BH_OFF + 16) = make_uint4(vh[4], vh[5], vh[6], vh[7]);
        *reinterpret_cast<uint4*>(brow + BL_OFF)      = make_uint4(vl[0], vl[1], vl[2], vl[3]);
        *reinterpret_cast<uint4*>(brow + BL_OFF + 16) = make_uint4(vl[4], vl[5], vl[6], vl[7]);
    };

    auto compute_stage = [&](char* st) {
        const uint32_t u = smem_u32(st);
        // ldmatrix lane-address components
        const uint32_t arow = (uint32_t)((wm + (lane & 15)) * RSTRIDE + (lane >> 4) * 16);
        const uint32_t brow = (uint32_t)((wn + ((lane >> 4) & 1) * 8 + (lane & 7)) * RSTRIDE
                                         + ((lane >> 3) & 1) * 16);
#pragma unroll
        for (int ks = 0; ks < 2; ks++) {
            const uint32_t kb2 = ks * 32;    // byte offset of k16 subtile within row
            unsigned ah[4][4], al[4][4], bh[2][4], bl[2][4];
#pragma unroll
            for (int mt = 0; mt < 4; mt++) {
                const uint32_t off = arow + kb2 + (uint32_t)(mt * 16 * RSTRIDE);
                ldsm_x4(ah[mt], u + AH_OFF + off);
                ldsm_x4(al[mt], u + AL_OFF + off);
            }
#pragma unroll
            for (int p = 0; p < 2; p++) {
                const uint32_t off = brow + kb2 + (uint32_t)(p * 16 * RSTRIDE);
                ldsm_x4(bh[p], u + BH_OFF + off);
                ldsm_x4(bl[p], u + BL_OFF + off);
            }
            // phase-ordered bf16x3
#pragma unroll
            for (int mt = 0; mt < 4; mt++)
#pragma unroll
                for (int nt = 0; nt < 4; nt++)
                    mma_bf16(acc[mt][nt], al[mt], &bh[nt >> 1][(nt & 1) * 2]);
#pragma unroll
            for (int mt = 0; mt < 4; mt++)
#pragma unroll
                for (int nt = 0; nt < 4; nt++)
                    mma_bf16(acc[mt][nt], ah[mt], &bl[nt >> 1][(nt & 1) * 2]);
#pragma unroll
            for (int mt = 0; mt < 4; mt++)
#pragma unroll
                for (int nt = 0; nt < 4; nt++)
                    mma_bf16(acc[mt][nt], ah[mt], &bh[nt >> 1][(nt & 1) * 2]);
        }
    };

    load_pref(0);
    store_pref(smem);
    __syncthreads();

    for (int ch = 0; ch < nc; ch++) {
        char* st = smem + (ch & 1) * STAGE_BYTES;
        const bool more = (ch + 1 < nc);
        if (more) load_pref(ch + 1);
        compute_stage(st);
        if (more) {
            store_pref(smem + ((ch + 1) & 1) * STAGE_BYTES);
            __syncthreads();
        }
    }

    // ---- epilogue ----
#pragma unroll
    for (int nt = 0; nt < 4; nt++) {
        const int gn = ntile * BN + wn + nt * 8 + 2 * tig;
        float bx = 0.f, by = 0.f;
        if (bias) { bx = bias[gn]; by = bias[gn + 1]; }
        if (ADDVEC) { bx += addvec[gn]; by += addvec[gn + 1]; }
#pragma unroll
        for (int mt = 0; mt < 4; mt++) {
            const int gm0w = mtile * BM + wm + mt * 16 + gq;
            float v0 = acc[mt][nt][0] + bx;
            float v1 = acc[mt][nt][1] + by;
            float v2 = acc[mt][nt][2] + bx;
            float v3 = acc[mt][nt][3] + by;
            if (RELU) {
                v0 = fmaxf(v0, 0.f); v1 = fmaxf(v1, 0.f);
                v2 = fmaxf(v2, 0.f); v3 = fmaxf(v3, 0.f);
            }
            if (gm0w < M)
                *reinterpret_cast<float2*>(C + (size_t)gm0w * ldc + gn) = make_float2(v0, v1);
            if (gm0w + 8 < M)
                *reinterpret_cast<float2*>(C + (size_t)(gm0w + 8) * ldc + gn) = make_float2(v2, v3);
        }
    }
}

// ---------------- GEMM kernel wrappers ----------------
__global__ __launch_bounds__(256) void k_embed(
    const int* __restrict__ src, const float* __restrict__ tab,
    const float* __restrict__ W, const float* __restrict__ bias,
    float* __restrict__ C)
{
    gemm_tc<true, false, false>(tab, FEAT_, src, W, D_, bias, nullptr,
                                C, D_, NTOK, D_, FEAT_, blockIdx.y, blockIdx.x);
}

__global__ __launch_bounds__(256) void k_gemm(
    const float* __restrict__ A, const float* __restrict__ B,
    const float* __restrict__ bias, float* __restrict__ C,
    int M, int N, int K)
{
    gemm_tc<false, false, false>(A, K, nullptr, B, N, bias, nullptr,
                                 C, N, M, N, K, blockIdx.y, blockIdx.x);
}

__global__ __launch_bounds__(256) void k_pbv(
    const float* __restrict__ pb, const float* __restrict__ V,
    const float* __restrict__ kv, float* __restrict__ wv)
{
    const int b = blockIdx.z;
    gemm_tc<false, false, true>(pb + (size_t)b * T_ * T_, T_, nullptr,
                                V + (size_t)b * T_ * D_, D_,
                                nullptr, kv + (size_t)b * D_,
                                wv + (size_t)b * T_ * D_, D_,
                                T_, D_, T_, 0, blockIdx.x);
}

__global__ __launch_bounds__(256) void k_moe1(
    const float* __restrict__ x, const float* __restrict__ W1,
    const float* __restrict__ b1)
{
    const int e = blockIdx.z;
    const int Me = g_cnt[e];
    if ((int)(blockIdx.y * BM) >= Me) return;
    gemm_tc<true, true, false>(x, D_, g_tok + g_off[e],
                               W1 + (size_t)e * D_ * FF_, FF_,
                               b1 + (size_t)e * FF_, nullptr,
                               g_h + (size_t)g_off[e] * FF_, FF_,
                               Me, FF_, D_, blockIdx.y, blockIdx.x);
}

__global__ __launch_bounds__(256) void k_moe2(
    const float* __restrict__ W2, const float* __restrict__ b2)
{
    const int e = blockIdx.z;
    const int Me = g_cnt[e];
    if ((int)(blockIdx.y * BM) >= Me) return;
    gemm_tc<false, false, false>(g_h + (size_t)g_off[e] * FF_, FF_, nullptr,
                                 W2 + (size_t)e * FF_ * D_, D_,
                                 b2 + (size_t)e * D_, nullptr,
                                 g_eo + (size_t)g_off[e] * D_, D_,
                                 Me, D_, FF_, blockIdx.y, blockIdx.x);
}

// ---------------- Fourier positional bias ----------------
__global__ void k_pb(const float* __restrict__ frac,
                     const float* __restrict__ pbW,
                     const float* __restrict__ pbb,
                     const float* __restrict__ pba,
                     float* __restrict__ pb)
{
    __shared__ float w[NF_], ph[NF_], am[NF_];
    if (threadIdx.x < NF_) {
        w[threadIdx.x]  = pbW[threadIdx.x];
        ph[threadIdx.x] = pbb[threadIdx.x];
        am[threadIdx.x] = pba[threadIdx.x];
    }
    __syncthreads();
    const int idx = blockIdx.x * 256 + threadIdx.x;
    const int j = idx & 127;
    const int i = (idx >> 7) & 127;
    const int b = idx >> 14;
    const float d = (frac[b * T_ + j] - frac[b * T_ + i]) * SCALE_;
    float s = 0.f;
#pragma unroll
    for (int f = 0; f < NF_; f++) s += am[f] * cosf(d * w[f] + ph[f]);
    pb[idx] = s;
}

// ---------------- kv reduction ----------------
__global__ void k_kv(const float* __restrict__ K, const float* __restrict__ V,
                     float* __restrict__ kv)
{
    const int b = blockIdx.x;
    const int d = threadIdx.x;
    const float* Kb = K + (size_t)b * T_ * D_ + d;
    const float* Vb = V + (size_t)b * T_ * D_ + d;
    float s = 0.f;
#pragma unroll 8
    for (int t = 0; t < T_; t++) s += Kb[t * D_] * Vb[t * D_];
    kv[b * D_ + d] = s;
}

// ---------------- block reduction helper ----------------
__device__ __forceinline__ float blk_sum_256(float v, float* red) {
    const unsigned m = 0xffffffffu;
#pragma unroll
    for (int o = 16; o > 0; o >>= 1) v += __shfl_down_sync(m, v, o);
    if ((threadIdx.x & 31) == 0) red[threadIdx.x >> 5] = v;
    __syncthreads();
    if (threadIdx.x < 32) {
        float r = (threadIdx.x < 8) ? red[threadIdx.x] : 0.f;
#pragma unroll
        for (int o = 4; o > 0; o >>= 1) r += __shfl_down_sync(m, r, o);
        if (threadIdx.x == 0) red[0] = r;
    }
    __syncthreads();
    const float r = red[0];
    __syncthreads();
    return r;
}

// ---------------- LN1 ----------------
__global__ void k_ln(const float* __restrict__ x, const float* __restrict__ y,
                     const float* __restrict__ g, const float* __restrict__ b,
                     float* __restrict__ out)
{
    __shared__ float red[8];
    const int t = blockIdx.x;
    const int tid = threadIdx.x;
    const float* xr = x + (size_t)t * D_;
    const float* yr = y + (size_t)t * D_;
    const float v0 = xr[tid]       + yr[tid];
    const float v1 = xr[tid + 256] + yr[tid + 256];
    const float mean = blk_sum_256(v0 + v1, red) * (1.f / D_);
    const float d0 = v0 - mean, d1 = v1 - mean;
    const float var = blk_sum_256(d0 * d0 + d1 * d1, red) * (1.f / D_);
    const float inv = rsqrtf(var + EPS_);
    out[(size_t)t * D_ + tid]       = d0 * inv * g[tid]       + b[tid];
    out[(size_t)t * D_ + tid + 256] = d1 * inv * g[tid + 256] + b[tid + 256];
}

// ---------------- gating ----------------
__global__ void k_gate(const float* __restrict__ x, const float* __restrict__ gW,
                       const float* __restrict__ gb)
{
    __shared__ float xs[D_];
    __shared__ float lg[E_];
    const int t = blockIdx.x;
    const int tid = threadIdx.x;
    xs[tid]       = x[(size_t)t * D_ + tid];
    xs[tid + 256] = x[(size_t)t * D_ + tid + 256];
    __syncthreads();

    const int e = tid >> 5;
    const int lane = tid & 31;
    float s = 0.f;
    for (int k = lane; k < D_; k += 32) s += xs[k] * gW[k * E_ + e];
    const unsigned m = 0xffffffffu;
#pragma unroll
    for (int o = 16; o > 0; o >>= 1) s += __shfl_down_sync(m, s, o);
    if (lane == 0) lg[e] = s + gb[e];
    __syncthreads();

    if (tid == 0) {
        float mx = lg[0];
#pragma unroll
        for (int k = 1; k < E_; k++) mx = fmaxf(mx, lg[k]);
        float ex[E_]; float sum = 0.f;
#pragma unroll
        for (int k = 0; k < E_; k++) { ex[k] = expf(lg[k] - mx); sum += ex[k]; }
        const float inv = 1.f / sum;
        int e0 = 0; float p0 = ex[0];
#pragma unroll
        for (int k = 1; k < E_; k++) if (ex[k] > p0) { p0 = ex[k]; e0 = k; }
        int e1 = -1; float p1 = -1.f;
#pragma unroll
        for (int k = 0; k < E_; k++)
            if (k != e0 && ex[k] > p1) { p1 = ex[k]; e1 = k; }
        g_te[2 * t]     = e0; g_tw[2 * t]     = p0 * inv;
        g_te[2 * t + 1] = e1; g_tw[2 * t + 1] = p1 * inv;
        atomicAdd(&g_cnt[e0], 1);
        atomicAdd(&g_cnt[e1], 1);
    }
}

__global__ void k_zero8() {
    if (threadIdx.x < E_) g_cnt[threadIdx.x] = 0;
}

__global__ void k_scan() {
    if (threadIdx.x == 0) {
        int a = 0;
        for (int e = 0; e < E_; e++) { g_off[e] = a; g_cur[e] = a; a += g_cnt[e]; }
        g_off[E_] = a;
    }
}

__global__ void k_scatter() {
    const int t = blockIdx.x * 256 + threadIdx.x;
    if (t >= NTOK) return;
#pragma unroll
    for (int k = 0; k < 2; k++) {
        const int e = g_te[2 * t + k];
        const int p = atomicAdd(&g_cur[e], 1);
        g_tok[p] = t;
        g_pos[2 * t + k] = p;
    }
}

// ---------------- LN2 ----------------
__global__ void k_ln2(const float* __restrict__ x,
                      const float* __restrict__ g, const float* __restrict__ b,
                      float* __restrict__ out)
{
    __shared__ float red[8];
    const int t = blockIdx.x;
    const int tid = threadIdx.x;
    const int p0 = g_pos[2 * t], p1 = g_pos[2 * t + 1];
    const float w0 = g_tw[2 * t], w1 = g_tw[2 * t + 1];
    const float* e0 = g_eo + (size_t)p0 * D_;
    const float* e1 = g_eo + (size_t)p1 * D_;
    const float* xr = x + (size_t)t * D_;
    const float v0 = xr[tid]       + w0 * e0[tid]       + w1 * e1[tid];
    const float v1 = xr[tid + 256] + w0 * e0[tid + 256] + w1 * e1[tid + 256];
    const float mean = blk_sum_256(v0 + v1, red) * (1.f / D_);
    const float d0 = v0 - mean, d1 = v1 - mean;
    const float var = blk_sum_256(d0 * d0 + d1 * d1, red) * (1.f / D_);
    const float inv = rsqrtf(var + EPS_);
    out[(size_t)t * D_ + tid]       = d0 * inv * g[tid]       + b[tid];
    out[(size_t)t * D_ + tid + 256] = d1 * inv * g[tid + 256] + b[tid + 256];
}

// ---------------- host launcher ----------------
extern "C" void kernel_launch(void* const* d_in, const int* in_sizes, int n_in,
                              void* d_out, int out_size)
{
    const int*   src  = (const int*)  d_in[0];
    const float* frac = (const float*)d_in[1];
    const float* tab  = (const float*)d_in[2];
    const float* Wm2v = (const float*)d_in[3];
    const float* bm2v = (const float*)d_in[4];
    const float* pbW  = (const float*)d_in[5];
    const float* pbb  = (const float*)d_in[6];
    const float* pba  = (const float*)d_in[7];
    const float* Wk   = (const float*)d_in[8];
    const float* bk   = (const float*)d_in[9];
    const float* Wv   = (const float*)d_in[10];
    const float* bv   = (const float*)d_in[11];
    const float* Wo   = (const float*)d_in[12];
    const float* bo   = (const float*)d_in[13];
    const float* ln1g = (const float*)d_in[14];
    const float* ln1b = (const float*)d_in[15];
    const float* ln2g = (const float*)d_in[16];
    const float* ln2b = (const float*)d_in[17];
    const float* gW   = (const float*)d_in[18];
    const float* gb   = (const float*)d_in[19];
    const float* eW1  = (const float*)d_in[20];
    const float* eb1  = (const float*)d_in[21];
    const float* eW2  = (const float*)d_in[22];
    const float* eb2  = (const float*)d_in[23];

    float *x, *pb, *Kb, *Vb, *kvb, *wv, *o;
    cudaGetSymbolAddress((void**)&x,   g_x);
    cudaGetSymbolAddress((void**)&pb,  g_pb);
    cudaGetSymbolAddress((void**)&Kb,  g_K);
    cudaGetSymbolAddress((void**)&Vb,  g_V);
    cudaGetSymbolAddress((void**)&kvb, g_kv);
    cudaGetSymbolAddress((void**)&wv,  g_wv);
    cudaGetSymbolAddress((void**)&o,   g_o);

    static bool attr_done = false;
    if (!attr_done) {
        cudaFuncSetAttribute(k_embed, cudaFuncAttributeMaxDynamicSharedMemorySize, SMEM_SZ);
        cudaFuncSetAttribute(k_gemm,  cudaFuncAttributeMaxDynamicSharedMemorySize, SMEM_SZ);
        cudaFuncSetAttribute(k_pbv,   cudaFuncAttributeMaxDynamicSharedMemorySize, SMEM_SZ);
        cudaFuncSetAttribute(k_moe1,  cudaFuncAttributeMaxDynamicSharedMemorySize, SMEM_SZ);
        cudaFuncSetAttribute(k_moe2,  cudaFuncAttributeMaxDynamicSharedMemorySize, SMEM_SZ);
        attr_done = true;
    }

    const dim3 g44(4, 32);        // N=512/128 x M=4096/128

    k_embed<<<g44, 256, SMEM_SZ>>>(src, tab, Wm2v, bm2v, x);
    k_pb<<<(B_ * T_ * T_) / 256, 256>>>(frac, pbW, pbb, pba, pb);

    for (int i = 0; i < NL_; i++) {
        const size_t wOff = (size_t)i * D_ * D_;
        k_gemm<<<g44, 256, SMEM_SZ>>>(x,  Wk + wOff, bk + i * D_, Kb, NTOK, D_, D_);
        k_gemm<<<g44, 256, SMEM_SZ>>>(x,  Wv + wOff, bv + i * D_, Vb, NTOK, D_, D_);
        k_kv<<<B_, 512>>>(Kb, Vb, kvb);
        k_pbv<<<dim3(4, 1, B_), 256, SMEM_SZ>>>(pb, Vb, kvb, wv);
        k_gemm<<<g44, 256, SMEM_SZ>>>(wv, Wo + wOff, bo + i * D_, o, NTOK, D_, D_);
        k_ln<<<NTOK, 256>>>(x, o, ln1g + i * D_, ln1b + i * D_, x);

        k_zero8<<<1, 32>>>();
        k_gate<<<NTOK, 256>>>(x, gW + (size_t)i * D_ * E_, gb + i * E_);
        k_scan<<<1, 1>>>();
        k_scatter<<<NTOK / 256, 256>>>();

        k_moe1<<<dim3(FF_ / BN, 32, E_), 256, SMEM_SZ>>>(
            x, eW1 + (size_t)i * E_ * D_ * FF_, eb1 + (size_t)i * E_ * FF_);
        k_moe2<<<dim3(D_ / BN, 32, E_), 256, SMEM_SZ>>>(
            eW2 + (size_t)i * E_ * FF_ * D_, eb2 + (size_t)i * E_ * D_);

        float* dst = (i == NL_ - 1) ? (float*)d_out : x;
        k_ln2<<<NTOK, 256>>>(x, ln2g + i * D_, ln2b + i * D_, dst);
    }
}

// round 10
// speedup vs baseline: 1.1833x; 1.0884x over previous
#include <cuda_runtime.h>
#include <cuda_bf16.h>
#include <cstdint>

// ---------------- problem constants ----------------
#define B_   32
#define T_   128
#define D_   512
#define FF_  2048
#define E_   8
#define NL_  3
#define NF_  16
#define FEAT_ 200
#define VOCAB_ 119
#define NTOK  4096          // B*T
#define NSLOT 8192          // NTOK*2 (top-2 slots)
#define SCALE_ 10.0f
#define EPS_   1e-5f

// ---------------- fp32 scratch ----------------
__device__ float g_x  [NTOK * D_];
__device__ float g_K  [NTOK * D_];
__device__ float g_V  [NTOK * D_];
__device__ float g_kv [B_ * D_];
__device__ float g_o  [NTOK * D_];
__device__ float g_eo [(NSLOT + 128) * D_];
__device__ int   g_te [NSLOT];
__device__ float g_tw [NSLOT];
__device__ int   g_cnt[E_];
__device__ int   g_off[E_ + 1];
__device__ int   g_cur[E_];
__device__ int   g_tok[NSLOT + 128];
__device__ int   g_pos[NSLOT];

// ---------------- bf16 hi/lo scratch ----------------
__device__ __nv_bfloat16 g_th[VOCAB_ * FEAT_],  g_tl[VOCAB_ * FEAT_];
__device__ __nv_bfloat16 g_m2vh[FEAT_ * D_],    g_m2vl[FEAT_ * D_];
__device__ __nv_bfloat16 g_Wkh[NL_ * D_ * D_],  g_Wkl[NL_ * D_ * D_];
__device__ __nv_bfloat16 g_Wvh[NL_ * D_ * D_],  g_Wvl[NL_ * D_ * D_];
__device__ __nv_bfloat16 g_Woh[NL_ * D_ * D_],  g_Wol[NL_ * D_ * D_];
__device__ __nv_bfloat16 g_e1h[NL_ * E_ * D_ * FF_], g_e1l[NL_ * E_ * D_ * FF_];
__device__ __nv_bfloat16 g_e2h[NL_ * E_ * FF_ * D_], g_e2l[NL_ * E_ * FF_ * D_];
__device__ __nv_bfloat16 g_xh[NTOK * D_],  g_xl[NTOK * D_];
__device__ __nv_bfloat16 g_Vh[NTOK * D_],  g_Vl[NTOK * D_];
__device__ __nv_bfloat16 g_pbh[B_ * T_ * T_], g_pbl[B_ * T_ * T_];
__device__ __nv_bfloat16 g_wvh[NTOK * D_], g_wvl[NTOK * D_];
__device__ __nv_bfloat16 g_hh[(NSLOT + 128) * FF_], g_hl[(NSLOT + 128) * FF_];

// ---------------- helpers ----------------
__device__ __forceinline__ uint32_t smem_u32(const void* p) {
    uint32_t a;
    asm("{ .reg .u64 t; cvta.to.shared.u64 t, %1; cvt.u32.u64 %0, t; }" : "=r"(a) : "l"(p));
    return a;
}
__device__ __forceinline__ float4 ld4(const float* p) {
    return *reinterpret_cast<const float4*>(p);
}
__device__ __forceinline__ unsigned pack2(float lo, float hi) {
    unsigned r;
    asm("cvt.rn.bf16x2.f32 %0, %1, %2;" : "=r"(r) : "f"(hi), "f"(lo));
    return r;
}
__device__ __forceinline__ void split_bf(float x, float& h, float& l) {
    h = __bfloat162float(__float2bfloat16_rn(x));
    l = x - h;
}
__device__ __forceinline__ void ldsm_x4(unsigned* r, uint32_t addr) {
    asm volatile("ldmatrix.sync.aligned.m8n8.x4.shared.b16 {%0,%1,%2,%3}, [%4];"
                 : "=r"(r[0]), "=r"(r[1]), "=r"(r[2]), "=r"(r[3]) : "r"(addr));
}
__device__ __forceinline__ void ldsm_x4t(unsigned* r, uint32_t addr) {
    asm volatile("ldmatrix.sync.aligned.m8n8.x4.trans.shared.b16 {%0,%1,%2,%3}, [%4];"
                 : "=r"(r[0]), "=r"(r[1]), "=r"(r[2]), "=r"(r[3]) : "r"(addr));
}
__device__ __forceinline__ void mma_bf16(float* c, const unsigned* a, const unsigned* b) {
    asm("mma.sync.aligned.m16n8k16.row.col.f32.bf16.bf16.f32 "
        "{%0,%1,%2,%3}, {%4,%5,%6,%7}, {%8,%9}, {%0,%1,%2,%3};"
        : "+f"(c[0]), "+f"(c[1]), "+f"(c[2]), "+f"(c[3])
        : "r"(a[0]), "r"(a[1]), "r"(a[2]), "r"(a[3]), "r"(b[0]), "r"(b[1]));
}
__device__ __forceinline__ void cpa16(uint32_t dst, const void* src, int srcbytes) {
    asm volatile("cp.async.cg.shared.global [%0], [%1], 16, %2;"
                 :: "r"(dst), "l"(src), "r"(srcbytes) : "memory");
}

// ---------------- bf16x3 GEMM core: cp.async 4-stage, ldmatrix, 128x128x32 ----------------
#define BM 128
#define BN 128
#define BK 32
#define ASTR 80             // A row stride bytes (64B data + 16 pad)
#define BSTR 272            // B row stride bytes (256B data + 16 pad)
#define OFF_AH 0
#define OFF_AL 10240
#define OFF_BH 20480
#define OFF_BL 29184
#define STAGE  37888
#define NSTAGE 4
#define SMEM_SZ (NSTAGE * STAGE)   // 151552

// C[M,N] = op( gather(A)[M,K] @ B[K,N] + bias + addvec )
// A: bf16 hi/lo [m][k] row-major; B: bf16 hi/lo [k][n] row-major.
// 256 threads = 8 warps (2m x 4n), warp tile 64x32.
template <bool GATHER, bool RELU, bool ADDVEC, bool WF32, bool WSPLIT>
__device__ __forceinline__ void gemm_bf(
    const __nv_bfloat16* __restrict__ Ah, const __nv_bfloat16* __restrict__ Al,
    int lda, const int* __restrict__ rowmap,
    const __nv_bfloat16* __restrict__ Bh, const __nv_bfloat16* __restrict__ Bl,
    int ldb,
    const float* __restrict__ bias, const float* __restrict__ addvec,
    float* __restrict__ C, __nv_bfloat16* __restrict__ Ch, __nv_bfloat16* __restrict__ Cl,
    int ldc, int M, int N, int K, int mtile, int ntile)
{
    extern __shared__ char smem[];
    const uint32_t su = smem_u32(smem);
    const int tid  = threadIdx.x;
    const int lane = tid & 31;
    const int warp = tid >> 5;
    const int wm = (warp >> 2) * 64;      // 0 or 64
    const int wn = (warp & 3) * 32;       // 0,32,64,96
    const int gq  = lane >> 2;
    const int tig = lane & 3;

    // A loader: thread -> (row r, k-half)
    const int ar   = tid >> 1;
    const int half = tid & 1;
    int gma = mtile * BM + ar; if (gma > M - 1) gma = M - 1;
    const int raa = GATHER ? rowmap[gma] : gma;
    const __nv_bfloat16* pAh = Ah + (size_t)raa * lda;
    const __nv_bfloat16* pAl = Al + (size_t)raa * lda;

    // B loader: thread -> (k row kb, n chunk pair cb)
    const int kb = tid >> 3;              // 0..31
    const int cb = (tid & 7) * 2;         // 16B chunk index (8 n each)

    float acc[4][4][4];
#pragma unroll
    for (int i = 0; i < 4; i++)
#pragma unroll
        for (int j = 0; j < 4; j++)
#pragma unroll
            for (int r = 0; r < 4; r++) acc[i][j][r] = 0.f;

    const int nc = (K + BK - 1) / BK;

    auto issue = [&](int ch) {
        const uint32_t sb = su + (uint32_t)(ch & 3) * STAGE;
        const int k0 = ch * BK + half * 16;
        const int v0 = (k0 + 8  <= K) ? 16 : 0;
        const int v1 = (k0 + 16 <= K) ? 16 : 0;
        uint32_t da = sb + OFF_AH + ar * ASTR + half * 32;
        cpa16(da,      v0 ? (const void*)(pAh + k0)     : (const void*)Ah, v0);
        cpa16(da + 16, v1 ? (const void*)(pAh + k0 + 8) : (const void*)Ah, v1);
        da = sb + OFF_AL + ar * ASTR + half * 32;
        cpa16(da,      v0 ? (const void*)(pAl + k0)     : (const void*)Al, v0);
        cpa16(da + 16, v1 ? (const void*)(pAl + k0 + 8) : (const void*)Al, v1);

        const int gk = ch * BK + kb;
        const int vb = (gk < K) ? 16 : 0;
        const __nv_bfloat16* sbh = Bh + (size_t)gk * ldb + ntile * BN + cb * 8;
        const __nv_bfloat16* sbl = Bl + (size_t)gk * ldb + ntile * BN + cb * 8;
        uint32_t db = sb + OFF_BH + kb * BSTR + cb * 16;
        cpa16(db,      vb ? (const void*)sbh       : (const void*)Bh, vb);
        cpa16(db + 16, vb ? (const void*)(sbh + 8) : (const void*)Bh, vb);
        db = sb + OFF_BL + kb * BSTR + cb * 16;
        cpa16(db,      vb ? (const void*)sbl       : (const void*)Bl, vb);
        cpa16(db + 16, vb ? (const void*)(sbl + 8) : (const void*)Bl, vb);
        asm volatile("cp.async.commit_group;" ::: "memory");
    };

    // fragment address components
    const uint32_t a_l = (uint32_t)((wm + (lane & 15)) * ASTR + (lane >> 4) * 16);
    const uint32_t b_l = (uint32_t)((lane & 15) * BSTR + (lane >> 4) * 16);

    issue(0);
    issue(1);

    for (int ch = 0; ch < nc; ch++) {
        if (ch + 2 < nc) issue(ch + 2);
        const int rem = nc - 1 - ch;
        if (rem >= 2)      asm volatile("cp.async.wait_group 2;" ::: "memory");
        else if (rem == 1) asm volatile("cp.async.wait_group 1;" ::: "memory");
        else               asm volatile("cp.async.wait_group 0;" ::: "memory");
        __syncthreads();

        const uint32_t sb = su + (uint32_t)(ch & 3) * STAGE;
#pragma unroll
        for (int ks = 0; ks < 2; ks++) {
            unsigned ah[4][4], al[4][4], bh[2][4], bl[2][4];
#pragma unroll
            for (int mt = 0; mt < 4; mt++) {
                const uint32_t off = a_l + (uint32_t)(ks * 32 + mt * 16 * ASTR);
                ldsm_x4(ah[mt], sb + OFF_AH + off);
                ldsm_x4(al[mt], sb + OFF_AL + off);
            }
#pragma unroll
            for (int p = 0; p < 2; p++) {
                const uint32_t off = b_l + (uint32_t)(ks * 16 * BSTR + (wn + p * 16) * 2);
                ldsm_x4t(bh[p], sb + OFF_BH + off);
                ldsm_x4t(bl[p], sb + OFF_BL + off);
            }
#pragma unroll
            for (int mt = 0; mt < 4; mt++)
#pragma unroll
                for (int nt = 0; nt < 4; nt++)
                    mma_bf16(acc[mt][nt], al[mt], &bh[nt >> 1][(nt & 1) * 2]);
#pragma unroll
            for (int mt = 0; mt < 4; mt++)
#pragma unroll
                for (int nt = 0; nt < 4; nt++)
                    mma_bf16(acc[mt][nt], ah[mt], &bl[nt >> 1][(nt & 1) * 2]);
#pragma unroll
            for (int mt = 0; mt < 4; mt++)
#pragma unroll
                for (int nt = 0; nt < 4; nt++)
                    mma_bf16(acc[mt][nt], ah[mt], &bh[nt >> 1][(nt & 1) * 2]);
        }
    }

    // ---- epilogue ----
#pragma unroll
    for (int nt = 0; nt < 4; nt++) {
        const int gn = ntile * BN + wn + nt * 8 + 2 * tig;
        float bx = 0.f, by = 0.f;
        if (bias) { bx = bias[gn]; by = bias[gn + 1]; }
        if (ADDVEC) { bx += addvec[gn]; by += addvec[gn + 1]; }
#pragma unroll
        for (int mt = 0; mt < 4; mt++) {
            const int gm0 = mtile * BM + wm + mt * 16 + gq;
            float v0 = acc[mt][nt][0] + bx;
            float v1 = acc[mt][nt][1] + by;
            float v2 = acc[mt][nt][2] + bx;
            float v3 = acc[mt][nt][3] + by;
            if (RELU) {
                v0 = fmaxf(v0, 0.f); v1 = fmaxf(v1, 0.f);
                v2 = fmaxf(v2, 0.f); v3 = fmaxf(v3, 0.f);
            }
            if (gm0 < M) {
                if (WF32)
                    *reinterpret_cast<float2*>(C + (size_t)gm0 * ldc + gn) = make_float2(v0, v1);
                if (WSPLIT) {
                    float h0, l0, h1, l1;
                    split_bf(v0, h0, l0); split_bf(v1, h1, l1);
                    *reinterpret_cast<unsigned*>(Ch + (size_t)gm0 * ldc + gn) = pack2(h0, h1);
                    *reinterpret_cast<unsigned*>(Cl + (size_t)gm0 * ldc + gn) = pack2(l0, l1);
                }
            }
            if (gm0 + 8 < M) {
                if (WF32)
                    *reinterpret_cast<float2*>(C + (size_t)(gm0 + 8) * ldc + gn) = make_float2(v2, v3);
                if (WSPLIT) {
                    float h2, l2, h3, l3;
                    split_bf(v2, h2, l2); split_bf(v3, h3, l3);
                    *reinterpret_cast<unsigned*>(Ch + (size_t)(gm0 + 8) * ldc + gn) = pack2(h2, h3);
                    *reinterpret_cast<unsigned*>(Cl + (size_t)(gm0 + 8) * ldc + gn) = pack2(l2, l3);
                }
            }
        }
    }
}

// ---------------- split kernel: fp32 -> bf16 hi/lo ----------------
__global__ void k_split(const float* __restrict__ in,
                        __nv_bfloat16* __restrict__ oh,
                        __nv_bfloat16* __restrict__ ol, int n)
{
    const int i = (blockIdx.x * 256 + threadIdx.x) * 4;
    if (i >= n) return;
    const float4 v = ld4(in + i);
    float h0, l0, h1, l1, h2, l2, h3, l3;
    split_bf(v.x, h0, l0); split_bf(v.y, h1, l1);
    split_bf(v.z, h2, l2); split_bf(v.w, h3, l3);
    *reinterpret_cast<uint2*>(oh + i) = make_uint2(pack2(h0, h1), pack2(h2, h3));
    *reinterpret_cast<uint2*>(ol + i) = make_uint2(pack2(l0, l1), pack2(l2, l3));
}

// ---------------- GEMM wrappers ----------------
__global__ __launch_bounds__(256) void k_embed(
    const int* __restrict__ src, const float* __restrict__ bias, float* __restrict__ C)
{
    gemm_bf<true, false, false, true, true>(
        g_th, g_tl, FEAT_, src, g_m2vh, g_m2vl, D_, bias, nullptr,
        C, g_xh, g_xl, D_, NTOK, D_, FEAT_, blockIdx.y, blockIdx.x);
}

// projection: A = x split; C fp32 only
__global__ __launch_bounds__(256) void k_proj(
    const __nv_bfloat16* __restrict__ Bh, const __nv_bfloat16* __restrict__ Bl,
    const float* __restrict__ bias, float* __restrict__ C)
{
    gemm_bf<false, false, false, true, false>(
        g_xh, g_xl, D_, nullptr, Bh, Bl, D_, bias, nullptr,
        C, nullptr, nullptr, D_, NTOK, D_, D_, blockIdx.y, blockIdx.x);
}

// V projection: fp32 + split
__global__ __launch_bounds__(256) void k_projv(
    const __nv_bfloat16* __restrict__ Bh, const __nv_bfloat16* __restrict__ Bl,
    const float* __restrict__ bias, float* __restrict__ C)
{
    gemm_bf<false, false, false, true, true>(
        g_xh, g_xl, D_, nullptr, Bh, Bl, D_, bias, nullptr,
        C, g_Vh, g_Vl, D_, NTOK, D_, D_, blockIdx.y, blockIdx.x);
}

// pbv: A = pb split [T][T], B = V split [T][D], addvec = kv; C = wv split only
__global__ __launch_bounds__(256) void k_pbv(const float* __restrict__ kv)
{
    const int b = blockIdx.z;
    gemm_bf<false, false, true, false, true>(
        g_pbh + (size_t)b * T_ * T_, g_pbl + (size_t)b * T_ * T_, T_, nullptr,
        g_Vh + (size_t)b * T_ * D_, g_Vl + (size_t)b * T_ * D_, D_,
        nullptr, kv + (size_t)b * D_,
        nullptr, g_wvh + (size_t)b * T_ * D_, g_wvl + (size_t)b * T_ * D_, D_,
        T_, D_, T_, 0, blockIdx.x);
}

// Wo gemm: A = wv split; C fp32
__global__ __launch_bounds__(256) void k_wo(
    const __nv_bfloat16* __restrict__ Bh, const __nv_bfloat16* __restrict__ Bl,
    const float* __restrict__ bias, float* __restrict__ C)
{
    gemm_bf<false, false, false, true, false>(
        g_wvh, g_wvl, D_, nullptr, Bh, Bl, D_, bias, nullptr,
        C, nullptr, nullptr, D_, NTOK, D_, D_, blockIdx.y, blockIdx.x);
}

__global__ __launch_bounds__(256) void k_moe1(int layer, const float* __restrict__ b1)
{
    const int e = blockIdx.z;
    const int Me = g_cnt[e];
    if ((int)(blockIdx.y * BM) >= Me) return;
    const size_t woff = ((size_t)layer * E_ + e) * D_ * FF_;
    const size_t ooff = (size_t)g_off[e] * FF_;
    gemm_bf<true, true, false, false, true>(
        g_xh, g_xl, D_, g_tok + g_off[e],
        g_e1h + woff, g_e1l + woff, FF_,
        b1 + (size_t)e * FF_, nullptr,
        nullptr, g_hh + ooff, g_hl + ooff, FF_,
        Me, FF_, D_, blockIdx.y, blockIdx.x);
}

__global__ __launch_bounds__(256) void k_moe2(int layer, const float* __restrict__ b2)
{
    const int e = blockIdx.z;
    const int Me = g_cnt[e];
    if ((int)(blockIdx.y * BM) >= Me) return;
    const size_t woff = ((size_t)layer * E_ + e) * FF_ * D_;
    const size_t ioff = (size_t)g_off[e] * FF_;
    gemm_bf<false, false, false, true, false>(
        g_hh + ioff, g_hl + ioff, FF_, nullptr,
        g_e2h + woff, g_e2l + woff, D_,
        b2 + (size_t)e * D_, nullptr,
        g_eo + (size_t)g_off[e] * D_, nullptr, nullptr, D_,
        Me, D_, FF_, blockIdx.y, blockIdx.x);
}

// ---------------- Fourier positional bias (writes split) ----------------
__global__ void k_pb(const float* __restrict__ frac,
                     const float* __restrict__ pbW,
                     const float* __restrict__ pbb,
                     const float* __restrict__ pba)
{
    __shared__ float w[NF_], ph[NF_], am[NF_];
    if (threadIdx.x < NF_) {
        w[threadIdx.x]  = pbW[threadIdx.x];
        ph[threadIdx.x] = pbb[threadIdx.x];
        am[threadIdx.x] = pba[threadIdx.x];
    }
    __syncthreads();
    const int idx = blockIdx.x * 256 + threadIdx.x;
    const int j = idx & 127;
    const int i = (idx >> 7) & 127;
    const int b = idx >> 14;
    const float d = (frac[b * T_ + j] - frac[b * T_ + i]) * SCALE_;
    float s = 0.f;
#pragma unroll
    for (int f = 0; f < NF_; f++) s += am[f] * cosf(d * w[f] + ph[f]);
    float h, l;
    split_bf(s, h, l);
    g_pbh[idx] = __float2bfloat16_rn(h);
    g_pbl[idx] = __float2bfloat16_rn(l);
}

// ---------------- kv reduction ----------------
__global__ void k_kv(const float* __restrict__ K, const float* __restrict__ V,
                     float* __restrict__ kv)
{
    const int b = blockIdx.x;
    const int d = threadIdx.x;
    const float* Kb = K + (size_t)b * T_ * D_ + d;
    const float* Vb = V + (size_t)b * T_ * D_ + d;
    float s = 0.f;
#pragma unroll 8
    for (int t = 0; t < T_; t++) s += Kb[t * D_] * Vb[t * D_];
    kv[b * D_ + d] = s;
}

// ---------------- block reduction ----------------
__device__ __forceinline__ float blk_sum_256(float v, float* red) {
    const unsigned m = 0xffffffffu;
#pragma unroll
    for (int o = 16; o > 0; o >>= 1) v += __shfl_down_sync(m, v, o);
    if ((threadIdx.x & 31) == 0) red[threadIdx.x >> 5] = v;
    __syncthreads();
    if (threadIdx.x < 32) {
        float r = (threadIdx.x < 8) ? red[threadIdx.x] : 0.f;
#pragma unroll
        for (int o = 4; o > 0; o >>= 1) r += __shfl_down_sync(m, r, o);
        if (threadIdx.x == 0) red[0] = r;
    }
    __syncthreads();
    const float r = red[0];
    __syncthreads();
    return r;
}

__device__ __forceinline__ void ln_store(float* out, int t, int c, float v,
                                         const float* g, const float* b,
                                         float inv, float mean, bool wsplit) {
    const float r = (v - mean) * inv * g[c] + b[c];
    out[(size_t)t * D_ + c] = r;
    if (wsplit) {
        float h, l;
        split_bf(r, h, l);
        g_xh[(size_t)t * D_ + c] = __float2bfloat16_rn(h);
        g_xl[(size_t)t * D_ + c] = __float2bfloat16_rn(l);
    }
}

// ---------------- LN1: out = LN(x + y), writes fp32 + split ----------------
__global__ void k_ln(const float* __restrict__ x, const float* __restrict__ y,
                     const float* __restrict__ g, const float* __restrict__ b,
                     float* __restrict__ out)
{
    __shared__ float red[8];
    const int t = blockIdx.x;
    const int tid = threadIdx.x;
    const float* xr = x + (size_t)t * D_;
    const float* yr = y + (size_t)t * D_;
    const float v0 = xr[tid]       + yr[tid];
    const float v1 = xr[tid + 256] + yr[tid + 256];
    const float mean = blk_sum_256(v0 + v1, red) * (1.f / D_);
    const float d0 = v0 - mean, d1 = v1 - mean;
    const float var = blk_sum_256(d0 * d0 + d1 * d1, red) * (1.f / D_);
    const float inv = rsqrtf(var + EPS_);
    ln_store(out, t, tid,       v0, g, b, inv, mean, true);
    ln_store(out, t, tid + 256, v1, g, b, inv, mean, true);
}

// ---------------- gating ----------------
__global__ void k_gate(const float* __restrict__ x, const float* __restrict__ gW,
                       const float* __restrict__ gb)
{
    __shared__ float xs[D_];
    __shared__ float lg[E_];
    const int t = blockIdx.x;
    const int tid = threadIdx.x;
    xs[tid]       = x[(size_t)t * D_ + tid];
    xs[tid + 256] = x[(size_t)t * D_ + tid + 256];
    __syncthreads();

    const int e = tid >> 5;
    const int lane = tid & 31;
    float s = 0.f;
    for (int k = lane; k < D_; k += 32) s += xs[k] * gW[k * E_ + e];
    const unsigned m = 0xffffffffu;
#pragma unroll
    for (int o = 16; o > 0; o >>= 1) s += __shfl_down_sync(m, s, o);
    if (lane == 0) lg[e] = s + gb[e];
    __syncthreads();

    if (tid == 0) {
        float mx = lg[0];
#pragma unroll
        for (int k = 1; k < E_; k++) mx = fmaxf(mx, lg[k]);
        float ex[E_]; float sum = 0.f;
#pragma unroll
        for (int k = 0; k < E_; k++) { ex[k] = expf(lg[k] - mx); sum += ex[k]; }
        const float inv = 1.f / sum;
        int e0 = 0; float p0 = ex[0];
#pragma unroll
        for (int k = 1; k < E_; k++) if (ex[k] > p0) { p0 = ex[k]; e0 = k; }
        int e1 = -1; float p1 = -1.f;
#pragma unroll
        for (int k = 0; k < E_; k++)
            if (k != e0 && ex[k] > p1) { p1 = ex[k]; e1 = k; }
        g_te[2 * t]     = e0; g_tw[2 * t]     = p0 * inv;
        g_te[2 * t + 1] = e1; g_tw[2 * t + 1] = p1 * inv;
        atomicAdd(&g_cnt[e0], 1);
        atomicAdd(&g_cnt[e1], 1);
    }
}

__global__ void k_zero8() {
    if (threadIdx.x < E_) g_cnt[threadIdx.x] = 0;
}

__global__ void k_scan() {
    if (threadIdx.x == 0) {
        int a = 0;
        for (int e = 0; e < E_; e++) { g_off[e] = a; g_cur[e] = a; a += g_cnt[e]; }
        g_off[E_] = a;
    }
}

__global__ void k_scatter() {
    const int t = blockIdx.x * 256 + threadIdx.x;
    if (t >= NTOK) return;
#pragma unroll
    for (int k = 0; k < 2; k++) {
        const int e = g_te[2 * t + k];
        const int p = atomicAdd(&g_cur[e], 1);
        g_tok[p] = t;
        g_pos[2 * t + k] = p;
    }
}

// ---------------- LN2 ----------------
__global__ void k_ln2(const float* __restrict__ x,
                      const float* __restrict__ g, const float* __restrict__ b,
                      float* __restrict__ out, int wsplit)
{
    __shared__ float red[8];
    const int t = blockIdx.x;
    const int tid = threadIdx.x;
    const int p0 = g_pos[2 * t], p1 = g_pos[2 * t + 1];
    const float w0 = g_tw[2 * t], w1 = g_tw[2 * t + 1];
    const float* e0 = g_eo + (size_t)p0 * D_;
    const float* e1 = g_eo + (size_t)p1 * D_;
    const float* xr = x + (size_t)t * D_;
    const float v0 = xr[tid]       + w0 * e0[tid]       + w1 * e1[tid];
    const float v1 = xr[tid + 256] + w0 * e0[tid + 256] + w1 * e1[tid + 256];
    const float mean = blk_sum_256(v0 + v1, red) * (1.f / D_);
    const float d0 = v0 - mean, d1 = v1 - mean;
    const float var = blk_sum_256(d0 * d0 + d1 * d1, red) * (1.f / D_);
    const float inv = rsqrtf(var + EPS_);
    ln_store(out, t, tid,       v0, g, b, inv, mean, wsplit != 0);
    ln_store(out, t, tid + 256, v1, g, b, inv, mean, wsplit != 0);
}

// ---------------- host launcher ----------------
extern "C" void kernel_launch(void* const* d_in, const int* in_sizes, int n_in,
                              void* d_out, int out_size)
{
    const int*   src  = (const int*)  d_in[0];
    const float* frac = (const float*)d_in[1];
    const float* tab  = (const float*)d_in[2];
    const float* Wm2v = (const float*)d_in[3];
    const float* bm2v = (const float*)d_in[4];
    const float* pbW  = (const float*)d_in[5];
    const float* pbb  = (const float*)d_in[6];
    const float* pba  = (const float*)d_in[7];
    const float* Wk   = (const float*)d_in[8];
    const float* bk   = (const float*)d_in[9];
    const float* Wv   = (const float*)d_in[10];
    const float* bv   = (const float*)d_in[11];
    const float* Wo   = (const float*)d_in[12];
    const float* bo   = (const float*)d_in[13];
    const float* ln1g = (const float*)d_in[14];
    const float* ln1b = (const float*)d_in[15];
    const float* ln2g = (const float*)d_in[16];
    const float* ln2b = (const float*)d_in[17];
    const float* gW   = (const float*)d_in[18];
    const float* gb   = (const float*)d_in[19];
    const float* eW1  = (const float*)d_in[20];
    const float* eb1  = (const float*)d_in[21];
    const float* eW2  = (const float*)d_in[22];
    const float* eb2  = (const float*)d_in[23];

    float *x, *Kb, *Vb, *kvb, *o;
    cudaGetSymbolAddress((void**)&x,   g_x);
    cudaGetSymbolAddress((void**)&Kb,  g_K);
    cudaGetSymbolAddress((void**)&Vb,  g_V);
    cudaGetSymbolAddress((void**)&kvb, g_kv);
    cudaGetSymbolAddress((void**)&o,   g_o);

    __nv_bfloat16 *th, *tl, *m2vh, *m2vl, *Wkh, *Wkl, *Wvh, *Wvl, *Woh, *Wol;
    __nv_bfloat16 *e1h, *e1l, *e2h, *e2l;
    cudaGetSymbolAddress((void**)&th,   g_th);
    cudaGetSymbolAddress((void**)&tl,   g_tl);
    cudaGetSymbolAddress((void**)&m2vh, g_m2vh);
    cudaGetSymbolAddress((void**)&m2vl, g_m2vl);
    cudaGetSymbolAddress((void**)&Wkh,  g_Wkh);
    cudaGetSymbolAddress((void**)&Wkl,  g_Wkl);
    cudaGetSymbolAddress((void**)&Wvh,  g_Wvh);
    cudaGetSymbolAddress((void**)&Wvl,  g_Wvl);
    cudaGetSymbolAddress((void**)&Woh,  g_Woh);
    cudaGetSymbolAddress((void**)&Wol,  g_Wol);
    cudaGetSymbolAddress((void**)&e1h,  g_e1h);
    cudaGetSymbolAddress((void**)&e1l,  g_e1l);
    cudaGetSymbolAddress((void**)&e2h,  g_e2h);
    cudaGetSymbolAddress((void**)&e2l,  g_e2l);

    static bool attr_done = false;
    if (!attr_done) {
        cudaFuncSetAttribute(k_embed, cudaFuncAttributeMaxDynamicSharedMemorySize, SMEM_SZ);
        cudaFuncSetAttribute(k_proj,  cudaFuncAttributeMaxDynamicSharedMemorySize, SMEM_SZ);
        cudaFuncSetAttribute(k_projv, cudaFuncAttributeMaxDynamicSharedMemorySize, SMEM_SZ);
        cudaFuncSetAttribute(k_pbv,   cudaFuncAttributeMaxDynamicSharedMemorySize, SMEM_SZ);
        cudaFuncSetAttribute(k_wo,    cudaFuncAttributeMaxDynamicSharedMemorySize, SMEM_SZ);
        cudaFuncSetAttribute(k_moe1,  cudaFuncAttributeMaxDynamicSharedMemorySize, SMEM_SZ);
        cudaFuncSetAttribute(k_moe2,  cudaFuncAttributeMaxDynamicSharedMemorySize, SMEM_SZ);
        attr_done = true;
    }

    // weight splits (fp32 -> bf16 hi/lo)
    auto split = [&](const float* in, __nv_bfloat16* oh, __nv_bfloat16* ol, int n) {
        k_split<<<(n / 4 + 255) / 256, 256>>>(in, oh, ol, n);
    };
    split(tab,  th,   tl,   VOCAB_ * FEAT_);
    split(Wm2v, m2vh, m2vl, FEAT_ * D_);
    split(Wk,   Wkh,  Wkl,  NL_ * D_ * D_);
    split(Wv,   Wvh,  Wvl,  NL_ * D_ * D_);
    split(Wo,   Woh,  Wol,  NL_ * D_ * D_);
    split(eW1,  e1h,  e1l,  NL_ * E_ * D_ * FF_);
    split(eW2,  e2h,  e2l,  NL_ * E_ * FF_ * D_);

    const dim3 g44(4, 32);        // N=512/128 x M=4096/128

    k_embed<<<g44, 256, SMEM_SZ>>>(src, bm2v, x);
    k_pb<<<(B_ * T_ * T_) / 256, 256>>>(frac, pbW, pbb, pba);

    for (int i = 0; i < NL_; i++) {
        const size_t wOff = (size_t)i * D_ * D_;
        k_proj<<<g44, 256, SMEM_SZ>>>(Wkh + wOff, Wkl + wOff, bk + i * D_, Kb);
        k_projv<<<g44, 256, SMEM_SZ>>>(Wvh + wOff, Wvl + wOff, bv + i * D_, Vb);
        k_kv<<<B_, 512>>>(Kb, Vb, kvb);
        k_pbv<<<dim3(4, 1, B_), 256, SMEM_SZ>>>(kvb);
        k_wo<<<g44, 256, SMEM_SZ>>>(Woh + wOff, Wol + wOff, bo + i * D_, o);
        k_ln<<<NTOK, 256>>>(x, o, ln1g + i * D_, ln1b + i * D_, x);

        k_zero8<<<1, 32>>>();
        k_gate<<<NTOK, 256>>>(x, gW + (size_t)i * D_ * E_, gb + i * E_);
        k_scan<<<1, 1>>>();
        k_scatter<<<NTOK / 256, 256>>>();

        k_moe1<<<dim3(FF_ / BN, 32, E_), 256, SMEM_SZ>>>(i, eb1 + (size_t)i * E_ * FF_);
        k_moe2<<<dim3(D_ / BN, 32, E_), 256, SMEM_SZ>>>(i, eb2 + (size_t)i * E_ * D_);

        float* dst = (i == NL_ - 1) ? (float*)d_out : x;
        k_ln2<<<NTOK, 256>>>(x, ln2g + i * D_, ln2b + i * D_, dst,
                             (i == NL_ - 1) ? 0 : 1);
    }
}

// round 11
// speedup vs baseline: 1.1917x; 1.0071x over previous
#include <cuda_runtime.h>
#include <cuda_bf16.h>
#include <cstdint>

// ---------------- problem constants ----------------
#define B_   32
#define T_   128
#define D_   512
#define FF_  2048
#define E_   8
#define NL_  3
#define NF_  16
#define FEAT_ 200
#define VOCAB_ 119
#define NTOK  4096          // B*T
#define NSLOT 8192          // NTOK*2 (top-2 slots)
#define SCALE_ 10.0f
#define EPS_   1e-5f

// ---------------- fp32 scratch ----------------
__device__ float g_x  [NTOK * D_];
__device__ float g_K  [NTOK * D_];
__device__ float g_V  [NTOK * D_];
__device__ float g_kv [B_ * D_];
__device__ float g_o  [NTOK * D_];
__device__ float g_eo [(NSLOT + 128) * D_];
__device__ int   g_te [NSLOT];
__device__ float g_tw [NSLOT];
__device__ int   g_cnt[E_];
__device__ int   g_off[E_ + 1];
__device__ int   g_cur[E_];
__device__ int   g_tok[NSLOT + 128];
__device__ int   g_pos[NSLOT];

// ---------------- bf16 hi/lo scratch ----------------
__device__ __nv_bfloat16 g_th[VOCAB_ * FEAT_],  g_tl[VOCAB_ * FEAT_];
__device__ __nv_bfloat16 g_m2vh[FEAT_ * D_],    g_m2vl[FEAT_ * D_];
__device__ __nv_bfloat16 g_Wkh[NL_ * D_ * D_],  g_Wkl[NL_ * D_ * D_];
__device__ __nv_bfloat16 g_Wvh[NL_ * D_ * D_],  g_Wvl[NL_ * D_ * D_];
__device__ __nv_bfloat16 g_Woh[NL_ * D_ * D_],  g_Wol[NL_ * D_ * D_];
__device__ __nv_bfloat16 g_e1h[NL_ * E_ * D_ * FF_], g_e1l[NL_ * E_ * D_ * FF_];
__device__ __nv_bfloat16 g_e2h[NL_ * E_ * FF_ * D_], g_e2l[NL_ * E_ * FF_ * D_];
__device__ __nv_bfloat16 g_xh[NTOK * D_],  g_xl[NTOK * D_];
__device__ __nv_bfloat16 g_Vh[NTOK * D_],  g_Vl[NTOK * D_];
__device__ __nv_bfloat16 g_pbh[B_ * T_ * T_], g_pbl[B_ * T_ * T_];
__device__ __nv_bfloat16 g_wvh[NTOK * D_], g_wvl[NTOK * D_];
__device__ __nv_bfloat16 g_hh[(NSLOT + 128) * FF_], g_hl[(NSLOT + 128) * FF_];

// ---------------- helpers ----------------
__device__ __forceinline__ uint32_t smem_u32(const void* p) {
    uint32_t a;
    asm("{ .reg .u64 t; cvta.to.shared.u64 t, %1; cvt.u32.u64 %0, t; }" : "=r"(a) : "l"(p));
    return a;
}
__device__ __forceinline__ float4 ld4(const float* p) {
    return *reinterpret_cast<const float4*>(p);
}
__device__ __forceinline__ unsigned pack2(float lo, float hi) {
    unsigned r;
    asm("cvt.rn.bf16x2.f32 %0, %1, %2;" : "=r"(r) : "f"(hi), "f"(lo));
    return r;
}
__device__ __forceinline__ void split_bf(float x, float& h, float& l) {
    h = __bfloat162float(__float2bfloat16_rn(x));
    l = x - h;
}
__device__ __forceinline__ void ldsm_x4(unsigned* r, uint32_t addr) {
    asm volatile("ldmatrix.sync.aligned.m8n8.x4.shared.b16 {%0,%1,%2,%3}, [%4];"
                 : "=r"(r[0]), "=r"(r[1]), "=r"(r[2]), "=r"(r[3]) : "r"(addr));
}
__device__ __forceinline__ void ldsm_x4t(unsigned* r, uint32_t addr) {
    asm volatile("ldmatrix.sync.aligned.m8n8.x4.trans.shared.b16 {%0,%1,%2,%3}, [%4];"
                 : "=r"(r[0]), "=r"(r[1]), "=r"(r[2]), "=r"(r[3]) : "r"(addr));
}
__device__ __forceinline__ void mma_bf16(float* c, const unsigned* a, const unsigned* b) {
    asm("mma.sync.aligned.m16n8k16.row.col.f32.bf16.bf16.f32 "
        "{%0,%1,%2,%3}, {%4,%5,%6,%7}, {%8,%9}, {%0,%1,%2,%3};"
        : "+f"(c[0]), "+f"(c[1]), "+f"(c[2]), "+f"(c[3])
        : "r"(a[0]), "r"(a[1]), "r"(a[2]), "r"(a[3]), "r"(b[0]), "r"(b[1]));
}
__device__ __forceinline__ void cpa16(uint32_t dst, const void* src, int srcbytes) {
    asm volatile("cp.async.cg.shared.global [%0], [%1], 16, %2;"
                 :: "r"(dst), "l"(src), "r"(srcbytes) : "memory");
}

// ---------------- bf16x3 GEMM core: cp.async 4-stage, ldmatrix, 128x128x32 ----------------
#define BM 128
#define BN 128
#define BK 32
#define ASTR 80             // A row stride bytes (64B data + 16 pad)
#define BSTR 272            // B row stride bytes (256B data + 16 pad)
#define OFF_AH 0
#define OFF_AL 10240
#define OFF_BH 20480
#define OFF_BL 29184
#define STAGE  37888
#define NSTAGE 4
#define SMEM_SZ (NSTAGE * STAGE)   // 151552

// C[M,N] = op( gather(A)[M,K] @ B[K,N] + bias + addvec )
// A: bf16 hi/lo [m][k] row-major; B: bf16 hi/lo [k][n] row-major.
// 256 threads = 8 warps (2m x 4n), warp tile 64x32.
template <bool GATHER, bool RELU, bool ADDVEC, bool WF32, bool WSPLIT>
__device__ __forceinline__ void gemm_bf(
    const __nv_bfloat16* __restrict__ Ah, const __nv_bfloat16* __restrict__ Al,
    int lda, const int* __restrict__ rowmap,
    const __nv_bfloat16* __restrict__ Bh, const __nv_bfloat16* __restrict__ Bl,
    int ldb,
    const float* __restrict__ bias, const float* __restrict__ addvec,
    float* __restrict__ C, __nv_bfloat16* __restrict__ Ch, __nv_bfloat16* __restrict__ Cl,
    int ldc, int M, int N, int K, int mtile, int ntile)
{
    extern __shared__ char smem[];
    const uint32_t su = smem_u32(smem);
    const int tid  = threadIdx.x;
    const int lane = tid & 31;
    const int warp = tid >> 5;
    const int wm = (warp >> 2) * 64;      // 0 or 64
    const int wn = (warp & 3) * 32;       // 0,32,64,96
    const int gq  = lane >> 2;
    const int tig = lane & 3;

    // A loader: thread -> (row r, k-half)
    const int ar   = tid >> 1;
    const int half = tid & 1;
    int gma = mtile * BM + ar; if (gma > M - 1) gma = M - 1;
    const int raa = GATHER ? rowmap[gma] : gma;
    const __nv_bfloat16* pAh = Ah + (size_t)raa * lda;
    const __nv_bfloat16* pAl = Al + (size_t)raa * lda;

    // B loader: thread -> (k row kb, n chunk pair cb)
    const int kb = tid >> 3;              // 0..31
    const int cb = (tid & 7) * 2;         // 16B chunk index (8 n each)

    float acc[4][4][4];
#pragma unroll
    for (int i = 0; i < 4; i++)
#pragma unroll
        for (int j = 0; j < 4; j++)
#pragma unroll
            for (int r = 0; r < 4; r++) acc[i][j][r] = 0.f;

    const int nc = (K + BK - 1) / BK;

    auto issue = [&](int ch) {
        const uint32_t sb = su + (uint32_t)(ch & 3) * STAGE;
        const int k0 = ch * BK + half * 16;
        const int v0 = (k0 + 8  <= K) ? 16 : 0;
        const int v1 = (k0 + 16 <= K) ? 16 : 0;
        uint32_t da = sb + OFF_AH + ar * ASTR + half * 32;
        cpa16(da,      v0 ? (const void*)(pAh + k0)     : (const void*)Ah, v0);
        cpa16(da + 16, v1 ? (const void*)(pAh + k0 + 8) : (const void*)Ah, v1);
        da = sb + OFF_AL + ar * ASTR + half * 32;
        cpa16(da,      v0 ? (const void*)(pAl + k0)     : (const void*)Al, v0);
        cpa16(da + 16, v1 ? (const void*)(pAl + k0 + 8) : (const void*)Al, v1);

        const int gk = ch * BK + kb;
        const int vb = (gk < K) ? 16 : 0;
        const __nv_bfloat16* sbh = Bh + (size_t)gk * ldb + ntile * BN + cb * 8;
        const __nv_bfloat16* sbl = Bl + (size_t)gk * ldb + ntile * BN + cb * 8;
        uint32_t db = sb + OFF_BH + kb * BSTR + cb * 16;
        cpa16(db,      vb ? (const void*)sbh       : (const void*)Bh, vb);
        cpa16(db + 16, vb ? (const void*)(sbh + 8) : (const void*)Bh, vb);
        db = sb + OFF_BL + kb * BSTR + cb * 16;
        cpa16(db,      vb ? (const void*)sbl       : (const void*)Bl, vb);
        cpa16(db + 16, vb ? (const void*)(sbl + 8) : (const void*)Bl, vb);
        asm volatile("cp.async.commit_group;" ::: "memory");
    };

    // fragment address components
    const uint32_t a_l = (uint32_t)((wm + (lane & 15)) * ASTR + (lane >> 4) * 16);
    const uint32_t b_l = (uint32_t)((lane & 15) * BSTR + (lane >> 4) * 16);

    issue(0);
    issue(1);

    for (int ch = 0; ch < nc; ch++) {
        if (ch + 2 < nc) issue(ch + 2);
        const int rem = nc - 1 - ch;
        if (rem >= 2)      asm volatile("cp.async.wait_group 2;" ::: "memory");
        else if (rem == 1) asm volatile("cp.async.wait_group 1;" ::: "memory");
        else               asm volatile("cp.async.wait_group 0;" ::: "memory");
        __syncthreads();

        const uint32_t sb = su + (uint32_t)(ch & 3) * STAGE;
#pragma unroll
        for (int ks = 0; ks < 2; ks++) {
            unsigned ah[4][4], al[4][4], bh[2][4], bl[2][4];
#pragma unroll
            for (int mt = 0; mt < 4; mt++) {
                const uint32_t off = a_l + (uint32_t)(ks * 32 + mt * 16 * ASTR);
                ldsm_x4(ah[mt], sb + OFF_AH + off);
                ldsm_x4(al[mt], sb + OFF_AL + off);
            }
#pragma unroll
            for (int p = 0; p < 2; p++) {
                const uint32_t off = b_l + (uint32_t)(ks * 16 * BSTR + (wn + p * 16) * 2);
                ldsm_x4t(bh[p], sb + OFF_BH + off);
                ldsm_x4t(bl[p], sb + OFF_BL + off);
            }
#pragma unroll
            for (int mt = 0; mt < 4; mt++)
#pragma unroll
                for (int nt = 0; nt < 4; nt++)
                    mma_bf16(acc[mt][nt], al[mt], &bh[nt >> 1][(nt & 1) * 2]);
#pragma unroll
            for (int mt = 0; mt < 4; mt++)
#pragma unroll
                for (int nt = 0; nt < 4; nt++)
                    mma_bf16(acc[mt][nt], ah[mt], &bl[nt >> 1][(nt & 1) * 2]);
#pragma unroll
            for (int mt = 0; mt < 4; mt++)
#pragma unroll
                for (int nt = 0; nt < 4; nt++)
                    mma_bf16(acc[mt][nt], ah[mt], &bh[nt >> 1][(nt & 1) * 2]);
        }
    }

    // ---- epilogue ----
#pragma unroll
    for (int nt = 0; nt < 4; nt++) {
        const int gn = ntile * BN + wn + nt * 8 + 2 * tig;
        float bx = 0.f, by = 0.f;
        if (bias) { bx = bias[gn]; by = bias[gn + 1]; }
        if (ADDVEC) { bx += addvec[gn]; by += addvec[gn + 1]; }
#pragma unroll
        for (int mt = 0; mt < 4; mt++) {
            const int gm0 = mtile * BM + wm + mt * 16 + gq;
            float v0 = acc[mt][nt][0] + bx;
            float v1 = acc[mt][nt][1] + by;
            float v2 = acc[mt][nt][2] + bx;
            float v3 = acc[mt][nt][3] + by;
            if (RELU) {
                v0 = fmaxf(v0, 0.f); v1 = fmaxf(v1, 0.f);
                v2 = fmaxf(v2, 0.f); v3 = fmaxf(v3, 0.f);
            }
            if (gm0 < M) {
                if (WF32)
                    *reinterpret_cast<float2*>(C + (size_t)gm0 * ldc + gn) = make_float2(v0, v1);
                if (WSPLIT) {
                    float h0, l0, h1, l1;
                    split_bf(v0, h0, l0); split_bf(v1, h1, l1);
                    *reinterpret_cast<unsigned*>(Ch + (size_t)gm0 * ldc + gn) = pack2(h0, h1);
                    *reinterpret_cast<unsigned*>(Cl + (size_t)gm0 * ldc + gn) = pack2(l0, l1);
                }
            }
            if (gm0 + 8 < M) {
                if (WF32)
                    *reinterpret_cast<float2*>(C + (size_t)(gm0 + 8) * ldc + gn) = make_float2(v2, v3);
                if (WSPLIT) {
                    float h2, l2, h3, l3;
                    split_bf(v2, h2, l2); split_bf(v3, h3, l3);
                    *reinterpret_cast<unsigned*>(Ch + (size_t)(gm0 + 8) * ldc + gn) = pack2(h2, h3);
                    *reinterpret_cast<unsigned*>(Cl + (size_t)(gm0 + 8) * ldc + gn) = pack2(l2, l3);
                }
            }
        }
    }
}

// ---------------- split kernel v2: grid-stride, 8 floats/thread/iter, 16B stores ----------------
__global__ void k_split(const float* __restrict__ in,
                        __nv_bfloat16* __restrict__ oh,
                        __nv_bfloat16* __restrict__ ol, int n)
{
    const int stride = gridDim.x * blockDim.x * 8;
    for (int i = (blockIdx.x * blockDim.x + threadIdx.x) * 8; i < n; i += stride) {
        const float4 v0 = ld4(in + i);
        const float4 v1 = ld4(in + i + 4);
        float h0, l0, h1, l1, h2, l2, h3, l3;
        float h4, l4, h5, l5, h6, l6, h7, l7;
        split_bf(v0.x, h0, l0); split_bf(v0.y, h1, l1);
        split_bf(v0.z, h2, l2); split_bf(v0.w, h3, l3);
        split_bf(v1.x, h4, l4); split_bf(v1.y, h5, l5);
        split_bf(v1.z, h6, l6); split_bf(v1.w, h7, l7);
        *reinterpret_cast<uint4*>(oh + i) =
            make_uint4(pack2(h0, h1), pack2(h2, h3), pack2(h4, h5), pack2(h6, h7));
        *reinterpret_cast<uint4*>(ol + i) =
            make_uint4(pack2(l0, l1), pack2(l2, l3), pack2(l4, l5), pack2(l6, l7));
    }
}

// ---------------- GEMM wrappers ----------------
__global__ __launch_bounds__(256) void k_embed(
    const int* __restrict__ src, const float* __restrict__ bias, float* __restrict__ C)
{
    gemm_bf<true, false, false, true, true>(
        g_th, g_tl, FEAT_, src, g_m2vh, g_m2vl, D_, bias, nullptr,
        C, g_xh, g_xl, D_, NTOK, D_, FEAT_, blockIdx.y, blockIdx.x);
}

// fused K+V projection: z=0 -> K (fp32), z=1 -> V (fp32 + split)
__global__ __launch_bounds__(256) void k_projkv(
    const __nv_bfloat16* __restrict__ Wkh, const __nv_bfloat16* __restrict__ Wkl,
    const __nv_bfloat16* __restrict__ Wvh, const __nv_bfloat16* __restrict__ Wvl,
    const float* __restrict__ bk, const float* __restrict__ bv,
    float* __restrict__ K, float* __restrict__ V)
{
    if (blockIdx.z == 0) {
        gemm_bf<false, false, false, true, false>(
            g_xh, g_xl, D_, nullptr, Wkh, Wkl, D_, bk, nullptr,
            K, nullptr, nullptr, D_, NTOK, D_, D_, blockIdx.y, blockIdx.x);
    } else {
        gemm_bf<false, false, false, true, true>(
            g_xh, g_xl, D_, nullptr, Wvh, Wvl, D_, bv, nullptr,
            V, g_Vh, g_Vl, D_, NTOK, D_, D_, blockIdx.y, blockIdx.x);
    }
}

// pbv: A = pb split [T][T], B = V split [T][D], addvec = kv; C = wv split only
__global__ __launch_bounds__(256) void k_pbv(const float* __restrict__ kv)
{
    const int b = blockIdx.z;
    gemm_bf<false, false, true, false, true>(
        g_pbh + (size_t)b * T_ * T_, g_pbl + (size_t)b * T_ * T_, T_, nullptr,
        g_Vh + (size_t)b * T_ * D_, g_Vl + (size_t)b * T_ * D_, D_,
        nullptr, kv + (size_t)b * D_,
        nullptr, g_wvh + (size_t)b * T_ * D_, g_wvl + (size_t)b * T_ * D_, D_,
        T_, D_, T_, 0, blockIdx.x);
}

// Wo gemm: A = wv split; C fp32
__global__ __launch_bounds__(256) void k_wo(
    const __nv_bfloat16* __restrict__ Bh, const __nv_bfloat16* __restrict__ Bl,
    const float* __restrict__ bias, float* __restrict__ C)
{
    gemm_bf<false, false, false, true, false>(
        g_wvh, g_wvl, D_, nullptr, Bh, Bl, D_, bias, nullptr,
        C, nullptr, nullptr, D_, NTOK, D_, D_, blockIdx.y, blockIdx.x);
}

__global__ __launch_bounds__(256) void k_moe1(int layer, const float* __restrict__ b1)
{
    const int e = blockIdx.z;
    const int Me = g_cnt[e];
    if ((int)(blockIdx.y * BM) >= Me) return;
    const size_t woff = ((size_t)layer * E_ + e) * D_ * FF_;
    const size_t ooff = (size_t)g_off[e] * FF_;
    gemm_bf<true, true, false, false, true>(
        g_xh, g_xl, D_, g_tok + g_off[e],
        g_e1h + woff, g_e1l + woff, FF_,
        b1 + (size_t)e * FF_, nullptr,
        nullptr, g_hh + ooff, g_hl + ooff, FF_,
        Me, FF_, D_, blockIdx.y, blockIdx.x);
}

__global__ __launch_bounds__(256) void k_moe2(int layer, const float* __restrict__ b2)
{
    const int e = blockIdx.z;
    const int Me = g_cnt[e];
    if ((int)(blockIdx.y * BM) >= Me) return;
    const size_t woff = ((size_t)layer * E_ + e) * FF_ * D_;
    const size_t ioff = (size_t)g_off[e] * FF_;
    gemm_bf<false, false, false, true, false>(
        g_hh + ioff, g_hl + ioff, FF_, nullptr,
        g_e2h + woff, g_e2l + woff, D_,
        b2 + (size_t)e * D_, nullptr,
        g_eo + (size_t)g_off[e] * D_, nullptr, nullptr, D_,
        Me, D_, FF_, blockIdx.y, blockIdx.x);
}

// ---------------- Fourier positional bias (writes split) ----------------
__global__ void k_pb(const float* __restrict__ frac,
                     const float* __restrict__ pbW,
                     const float* __restrict__ pbb,
                     const float* __restrict__ pba)
{
    __shared__ float w[NF_], ph[NF_], am[NF_];
    if (threadIdx.x < NF_) {
        w[threadIdx.x]  = pbW[threadIdx.x];
        ph[threadIdx.x] = pbb[threadIdx.x];
        am[threadIdx.x] = pba[threadIdx.x];
    }
    __syncthreads();
    const int idx = blockIdx.x * 256 + threadIdx.x;
    const int j = idx & 127;
    const int i = (idx >> 7) & 127;
    const int b = idx >> 14;
    const float d = (frac[b * T_ + j] - frac[b * T_ + i]) * SCALE_;
    float s = 0.f;
#pragma unroll
    for (int f = 0; f < NF_; f++) s += am[f] * cosf(d * w[f] + ph[f]);
    float h, l;
    split_bf(s, h, l);
    g_pbh[idx] = __float2bfloat16_rn(h);
    g_pbl[idx] = __float2bfloat16_rn(l);
}

// ---------------- kv reduction ----------------
__global__ void k_kv(const float* __restrict__ K, const float* __restrict__ V,
                     float* __restrict__ kv)
{
    const int b = blockIdx.x;
    const int d = threadIdx.x;
    const float* Kb = K + (size_t)b * T_ * D_ + d;
    const float* Vb = V + (size_t)b * T_ * D_ + d;
    float s = 0.f;
#pragma unroll 8
    for (int t = 0; t < T_; t++) s += Kb[t * D_] * Vb[t * D_];
    kv[b * D_ + d] = s;
}

// ---------------- block reduction ----------------
__device__ __forceinline__ float blk_sum_256(float v, float* red) {
    const unsigned m = 0xffffffffu;
#pragma unroll
    for (int o = 16; o > 0; o >>= 1) v += __shfl_down_sync(m, v, o);
    if ((threadIdx.x & 31) == 0) red[threadIdx.x >> 5] = v;
    __syncthreads();
    if (threadIdx.x < 32) {
        float r = (threadIdx.x < 8) ? red[threadIdx.x] : 0.f;
#pragma unroll
        for (int o = 4; o > 0; o >>= 1) r += __shfl_down_sync(m, r, o);
        if (threadIdx.x == 0) red[0] = r;
    }
    __syncthreads();
    const float r = red[0];
    __syncthreads();
    return r;
}

__device__ __forceinline__ void ln_store(float* out, int t, int c, float v,
                                         const float* g, const float* b,
                                         float inv, float mean, bool wsplit) {
    const float r = (v - mean) * inv * g[c] + b[c];
    out[(size_t)t * D_ + c] = r;
    if (wsplit) {
        float h, l;
        split_bf(r, h, l);
        g_xh[(size_t)t * D_ + c] = __float2bfloat16_rn(h);
        g_xl[(size_t)t * D_ + c] = __float2bfloat16_rn(l);
    }
}

// ---------------- LN1: out = LN(x + y), writes fp32 + split ----------------
__global__ void k_ln(const float* __restrict__ x, const float* __restrict__ y,
                     const float* __restrict__ g, const float* __restrict__ b,
                     float* __restrict__ out)
{
    __shared__ float red[8];
    const int t = blockIdx.x;
    const int tid = threadIdx.x;
    const float* xr = x + (size_t)t * D_;
    const float* yr = y + (size_t)t * D_;
    const float v0 = xr[tid]       + yr[tid];
    const float v1 = xr[tid + 256] + yr[tid + 256];
    const float mean = blk_sum_256(v0 + v1, red) * (1.f / D_);
    const float d0 = v0 - mean, d1 = v1 - mean;
    const float var = blk_sum_256(d0 * d0 + d1 * d1, red) * (1.f / D_);
    const float inv = rsqrtf(var + EPS_);
    ln_store(out, t, tid,       v0, g, b, inv, mean, true);
    ln_store(out, t, tid + 256, v1, g, b, inv, mean, true);
}

// ---------------- gating ----------------
__global__ void k_gate(const float* __restrict__ x, const float* __restrict__ gW,
                       const float* __restrict__ gb)
{
    __shared__ float xs[D_];
    __shared__ float lg[E_];
    const int t = blockIdx.x;
    const int tid = threadIdx.x;
    xs[tid]       = x[(size_t)t * D_ + tid];
    xs[tid + 256] = x[(size_t)t * D_ + tid + 256];
    __syncthreads();

    const int e = tid >> 5;
    const int lane = tid & 31;
    float s = 0.f;
    for (int k = lane; k < D_; k += 32) s += xs[k] * gW[k * E_ + e];
    const unsigned m = 0xffffffffu;
#pragma unroll
    for (int o = 16; o > 0; o >>= 1) s += __shfl_down_sync(m, s, o);
    if (lane == 0) lg[e] = s + gb[e];
    __syncthreads();

    if (tid == 0) {
        float mx = lg[0];
#pragma unroll
        for (int k = 1; k < E_; k++) mx = fmaxf(mx, lg[k]);
        float ex[E_]; float sum = 0.f;
#pragma unroll
        for (int k = 0; k < E_; k++) { ex[k] = expf(lg[k] - mx); sum += ex[k]; }
        const float inv = 1.f / sum;
        int e0 = 0; float p0 = ex[0];
#pragma unroll
        for (int k = 1; k < E_; k++) if (ex[k] > p0) { p0 = ex[k]; e0 = k; }
        int e1 = -1; float p1 = -1.f;
#pragma unroll
        for (int k = 0; k < E_; k++)
            if (k != e0 && ex[k] > p1) { p1 = ex[k]; e1 = k; }
        g_te[2 * t]     = e0; g_tw[2 * t]     = p0 * inv;
        g_te[2 * t + 1] = e1; g_tw[2 * t + 1] = p1 * inv;
        atomicAdd(&g_cnt[e0], 1);
        atomicAdd(&g_cnt[e1], 1);
    }
}

__global__ void k_zero8() {
    if (threadIdx.x < E_) g_cnt[threadIdx.x] = 0;
}

__global__ void k_scan() {
    if (threadIdx.x == 0) {
        int a = 0;
        for (int e = 0; e < E_; e++) { g_off[e] = a; g_cur[e] = a; a += g_cnt[e]; }
        g_off[E_] = a;
    }
}

__global__ void k_scatter() {
    const int t = blockIdx.x * 256 + threadIdx.x;
    if (t >= NTOK) return;
#pragma unroll
    for (int k = 0; k < 2; k++) {
        const int e = g_te[2 * t + k];
        const int p = atomicAdd(&g_cur[e], 1);
        g_tok[p] = t;
        g_pos[2 * t + k] = p;
    }
}

// ---------------- LN2 ----------------
__global__ void k_ln2(const float* __restrict__ x,
                      const float* __restrict__ g, const float* __restrict__ b,
                      float* __restrict__ out, int wsplit)
{
    __shared__ float red[8];
    const int t = blockIdx.x;
    const int tid = threadIdx.x;
    const int p0 = g_pos[2 * t], p1 = g_pos[2 * t + 1];
    const float w0 = g_tw[2 * t], w1 = g_tw[2 * t + 1];
    const float* e0 = g_eo + (size_t)p0 * D_;
    const float* e1 = g_eo + (size_t)p1 * D_;
    const float* xr = x + (size_t)t * D_;
    const float v0 = xr[tid]       + w0 * e0[tid]       + w1 * e1[tid];
    const float v1 = xr[tid + 256] + w0 * e0[tid + 256] + w1 * e1[tid + 256];
    const float mean = blk_sum_256(v0 + v1, red) * (1.f / D_);
    const float d0 = v0 - mean, d1 = v1 - mean;
    const float var = blk_sum_256(d0 * d0 + d1 * d1, red) * (1.f / D_);
    const float inv = rsqrtf(var + EPS_);
    ln_store(out, t, tid,       v0, g, b, inv, mean, wsplit != 0);
    ln_store(out, t, tid + 256, v1, g, b, inv, mean, wsplit != 0);
}

// ---------------- host launcher ----------------
extern "C" void kernel_launch(void* const* d_in, const int* in_sizes, int n_in,
                              void* d_out, int out_size)
{
    const int*   src  = (const int*)  d_in[0];
    const float* frac = (const float*)d_in[1];
    const float* tab  = (const float*)d_in[2];
    const float* Wm2v = (const float*)d_in[3];
    const float* bm2v = (const float*)d_in[4];
    const float* pbW  = (const float*)d_in[5];
    const float* pbb  = (const float*)d_in[6];
    const float* pba  = (const float*)d_in[7];
    const float* Wk   = (const float*)d_in[8];
    const float* bk   = (const float*)d_in[9];
    const float* Wv   = (const float*)d_in[10];
    const float* bv   = (const float*)d_in[11];
    const float* Wo   = (const float*)d_in[12];
    const float* bo   = (const float*)d_in[13];
    const float* ln1g = (const float*)d_in[14];
    const float* ln1b = (const float*)d_in[15];
    const float* ln2g = (const float*)d_in[16];
    const float* ln2b = (const float*)d_in[17];
    const float* gW   = (const float*)d_in[18];
    const float* gb   = (const float*)d_in[19];
    const float* eW1  = (const float*)d_in[20];
    const float* eb1  = (const float*)d_in[21];
    const float* eW2  = (const float*)d_in[22];
    const float* eb2  = (const float*)d_in[23];

    float *x, *Kb, *Vb, *kvb, *o;
    cudaGetSymbolAddress((void**)&x,   g_x);
    cudaGetSymbolAddress((void**)&Kb,  g_K);
    cudaGetSymbolAddress((void**)&Vb,  g_V);
    cudaGetSymbolAddress((void**)&kvb, g_kv);
    cudaGetSymbolAddress((void**)&o,   g_o);

    __nv_bfloat16 *th, *tl, *m2vh, *m2vl, *Wkh, *Wkl, *Wvh, *Wvl, *Woh, *Wol;
    __nv_bfloat16 *e1h, *e1l, *e2h, *e2l;
    cudaGetSymbolAddress((void**)&th,   g_th);
    cudaGetSymbolAddress((void**)&tl,   g_tl);
    cudaGetSymbolAddress((void**)&m2vh, g_m2vh);
    cudaGetSymbolAddress((void**)&m2vl, g_m2vl);
    cudaGetSymbolAddress((void**)&Wkh,  g_Wkh);
    cudaGetSymbolAddress((void**)&Wkl,  g_Wkl);
    cudaGetSymbolAddress((void**)&Wvh,  g_Wvh);
    cudaGetSymbolAddress((void**)&Wvl,  g_Wvl);
    cudaGetSymbolAddress((void**)&Woh,  g_Woh);
    cudaGetSymbolAddress((void**)&Wol,  g_Wol);
    cudaGetSymbolAddress((void**)&e1h,  g_e1h);
    cudaGetSymbolAddress((void**)&e1l,  g_e1l);
    cudaGetSymbolAddress((void**)&e2h,  g_e2h);
    cudaGetSymbolAddress((void**)&e2l,  g_e2l);

    static bool attr_done = false;
    if (!attr_done) {
        cudaFuncSetAttribute(k_embed,  cudaFuncAttributeMaxDynamicSharedMemorySize, SMEM_SZ);
        cudaFuncSetAttribute(k_projkv, cudaFuncAttributeMaxDynamicSharedMemorySize, SMEM_SZ);
        cudaFuncSetAttribute(k_pbv,    cudaFuncAttributeMaxDynamicSharedMemorySize, SMEM_SZ);
        cudaFuncSetAttribute(k_wo,     cudaFuncAttributeMaxDynamicSharedMemorySize, SMEM_SZ);
        cudaFuncSetAttribute(k_moe1,   cudaFuncAttributeMaxDynamicSharedMemorySize, SMEM_SZ);
        cudaFuncSetAttribute(k_moe2,   cudaFuncAttributeMaxDynamicSharedMemorySize, SMEM_SZ);
        attr_done = true;
    }

    // weight splits (fp32 -> bf16 hi/lo), grid-stride
    auto split = [&](const float* in, __nv_bfloat16* oh, __nv_bfloat16* ol, int n) {
        int grid = (n / 8 + 255) / 256;
        if (grid > 4736) grid = 4736;
        k_split<<<grid, 256>>>(in, oh, ol, n);
    };
    split(tab,  th,   tl,   VOCAB_ * FEAT_);
    split(Wm2v, m2vh, m2vl, FEAT_ * D_);
    split(Wk,   Wkh,  Wkl,  NL_ * D_ * D_);
    split(Wv,   Wvh,  Wvl,  NL_ * D_ * D_);
    split(Wo,   Woh,  Wol,  NL_ * D_ * D_);
    split(eW1,  e1h,  e1l,  NL_ * E_ * D_ * FF_);
    split(eW2,  e2h,  e2l,  NL_ * E_ * FF_ * D_);

    const dim3 g44(4, 32);        // N=512/128 x M=4096/128

    k_embed<<<g44, 256, SMEM_SZ>>>(src, bm2v, x);
    k_pb<<<(B_ * T_ * T_) / 256, 256>>>(frac, pbW, pbb, pba);

    for (int i = 0; i < NL_; i++) {
        const size_t wOff = (size_t)i * D_ * D_;
        k_projkv<<<dim3(4, 32, 2), 256, SMEM_SZ>>>(
            Wkh + wOff, Wkl + wOff, Wvh + wOff, Wvl + wOff,
            bk + i * D_, bv + i * D_, Kb, Vb);
        k_kv<<<B_, 512>>>(Kb, Vb, kvb);
        k_pbv<<<dim3(4, 1, B_), 256, SMEM_SZ>>>(kvb);
        k_wo<<<g44, 256, SMEM_SZ>>>(Woh + wOff, Wol + wOff, bo + i * D_, o);
        k_ln<<<NTOK, 256>>>(x, o, ln1g + i * D_, ln1b + i * D_, x);

        k_zero8<<<1, 32>>>();
        k_gate<<<NTOK, 256>>>(x, gW + (size_t)i * D_ * E_, gb + i * E_);
        k_scan<<<1, 1>>>();
        k_scatter<<<NTOK / 256, 256>>>();

        k_moe1<<<dim3(FF_ / BN, 32, E_), 256, SMEM_SZ>>>(i, eb1 + (size_t)i * E_ * FF_);
        k_moe2<<<dim3(D_ / BN, 32, E_), 256, SMEM_SZ>>>(i, eb2 + (size_t)i * E_ * D_);

        float* dst = (i == NL_ - 1) ? (float*)d_out : x;
        k_ln2<<<NTOK, 256>>>(x, ln2g + i * D_, ln2b + i * D_, dst,
                             (i == NL_ - 1) ? 0 : 1);
    }
}

// round 12
// speedup vs baseline: 1.3501x; 1.1329x over previous
#include <cuda_runtime.h>
#include <cuda_bf16.h>
#include <cstdint>

// ---------------- problem constants ----------------
#define B_   32
#define T_   128
#define D_   512
#define FF_  2048
#define E_   8
#define NL_  3
#define NF_  16
#define FEAT_ 200
#define VOCAB_ 119
#define NTOK  4096          // B*T
#define NSLOT 8192          // NTOK*2 (top-2 slots)
#define SCALE_ 10.0f
#define EPS_   1e-5f

// ---------------- fp32 scratch ----------------
__device__ float g_x  [NTOK * D_];
__device__ float g_K  [NTOK * D_];
__device__ float g_V  [NTOK * D_];
__device__ float g_kv [B_ * D_];
__device__ float g_o  [NTOK * D_];
__device__ float g_eo [(NSLOT + 128) * D_];
__device__ int   g_te [NSLOT];
__device__ float g_tw [NSLOT];
__device__ int   g_cntA[NL_ * E_];
__device__ int   g_off[E_ + 1];
__device__ int   g_cur[E_];
__device__ int   g_tok[NSLOT + 128];
__device__ int   g_pos[NSLOT];

// ---------------- bf16 hi/lo scratch ----------------
__device__ __nv_bfloat16 g_th[VOCAB_ * FEAT_],  g_tl[VOCAB_ * FEAT_];
__device__ __nv_bfloat16 g_m2vh[FEAT_ * D_],    g_m2vl[FEAT_ * D_];
__device__ __nv_bfloat16 g_Wkh[NL_ * D_ * D_],  g_Wkl[NL_ * D_ * D_];
__device__ __nv_bfloat16 g_Wvh[NL_ * D_ * D_],  g_Wvl[NL_ * D_ * D_];
__device__ __nv_bfloat16 g_Woh[NL_ * D_ * D_],  g_Wol[NL_ * D_ * D_];
__device__ __nv_bfloat16 g_e1h[NL_ * E_ * D_ * FF_], g_e1l[NL_ * E_ * D_ * FF_];
__device__ __nv_bfloat16 g_e2h[NL_ * E_ * FF_ * D_], g_e2l[NL_ * E_ * FF_ * D_];
__device__ __nv_bfloat16 g_xh[NTOK * D_],  g_xl[NTOK * D_];
__device__ __nv_bfloat16 g_Vh[NTOK * D_],  g_Vl[NTOK * D_];
__device__ __nv_bfloat16 g_pbh[B_ * T_ * T_], g_pbl[B_ * T_ * T_];
__device__ __nv_bfloat16 g_wvh[NTOK * D_], g_wvl[NTOK * D_];
__device__ __nv_bfloat16 g_hh[(NSLOT + 128) * FF_], g_hl[(NSLOT + 128) * FF_];

// ---------------- helpers ----------------
__device__ __forceinline__ uint32_t smem_u32(const void* p) {
    uint32_t a;
    asm("{ .reg .u64 t; cvta.to.shared.u64 t, %1; cvt.u32.u64 %0, t; }" : "=r"(a) : "l"(p));
    return a;
}
__device__ __forceinline__ float4 ld4(const float* p) {
    return *reinterpret_cast<const float4*>(p);
}
__device__ __forceinline__ unsigned pack2(float lo, float hi) {
    unsigned r;
    asm("cvt.rn.bf16x2.f32 %0, %1, %2;" : "=r"(r) : "f"(hi), "f"(lo));
    return r;
}
__device__ __forceinline__ void split_bf(float x, float& h, float& l) {
    h = __bfloat162float(__float2bfloat16_rn(x));
    l = x - h;
}
__device__ __forceinline__ void ldsm_x4(unsigned* r, uint32_t addr) {
    asm volatile("ldmatrix.sync.aligned.m8n8.x4.shared.b16 {%0,%1,%2,%3}, [%4];"
                 : "=r"(r[0]), "=r"(r[1]), "=r"(r[2]), "=r"(r[3]) : "r"(addr));
}
__device__ __forceinline__ void ldsm_x4t(unsigned* r, uint32_t addr) {
    asm volatile("ldmatrix.sync.aligned.m8n8.x4.trans.shared.b16 {%0,%1,%2,%3}, [%4];"
                 : "=r"(r[0]), "=r"(r[1]), "=r"(r[2]), "=r"(r[3]) : "r"(addr));
}
__device__ __forceinline__ void mma_bf16(float* c, const unsigned* a, const unsigned* b) {
    asm("mma.sync.aligned.m16n8k16.row.col.f32.bf16.bf16.f32 "
        "{%0,%1,%2,%3}, {%4,%5,%6,%7}, {%8,%9}, {%0,%1,%2,%3};"
        : "+f"(c[0]), "+f"(c[1]), "+f"(c[2]), "+f"(c[3])
        : "r"(a[0]), "r"(a[1]), "r"(a[2]), "r"(a[3]), "r"(b[0]), "r"(b[1]));
}
__device__ __forceinline__ void cpa16(uint32_t dst, const void* src, int srcbytes) {
    asm volatile("cp.async.cg.shared.global [%0], [%1], 16, %2;"
                 :: "r"(dst), "l"(src), "r"(srcbytes) : "memory");
}

// ---------------- bf16x3 GEMM core: cp.async 3-stage, ldmatrix, 128x128x32, 2 CTA/SM ----------------
#define BM 128
#define BN 128
#define BK 32
#define ASTR 80             // A row stride bytes (64B data + 16 pad)
#define BSTR 272            // B row stride bytes (256B data + 16 pad)
#define OFF_AH 0
#define OFF_AL 10240
#define OFF_BH 20480
#define OFF_BL 29184
#define STAGE  37888
#define NSTAGE 3
#define SMEM_SZ (NSTAGE * STAGE)   // 113664 -> 2 CTAs/SM

// C[M,N] = op( gather(A)[M,K] @ B[K,N] + bias + addvec )
// A: bf16 hi/lo [m][k] row-major; B: bf16 hi/lo [k][n] row-major.
// 256 threads = 8 warps (2m x 4n), warp tile 64x32.
template <bool GATHER, bool RELU, bool ADDVEC, bool WF32, bool WSPLIT>
__device__ __forceinline__ void gemm_bf(
    const __nv_bfloat16* __restrict__ Ah, const __nv_bfloat16* __restrict__ Al,
    int lda, const int* __restrict__ rowmap,
    const __nv_bfloat16* __restrict__ Bh, const __nv_bfloat16* __restrict__ Bl,
    int ldb,
    const float* __restrict__ bias, const float* __restrict__ addvec,
    float* __restrict__ C, __nv_bfloat16* __restrict__ Ch, __nv_bfloat16* __restrict__ Cl,
    int ldc, int M, int N, int K, int mtile, int ntile)
{
    extern __shared__ char smem[];
    const uint32_t su = smem_u32(smem);
    const int tid  = threadIdx.x;
    const int lane = tid & 31;
    const int warp = tid >> 5;
    const int wm = (warp >> 2) * 64;      // 0 or 64
    const int wn = (warp & 3) * 32;       // 0,32,64,96
    const int gq  = lane >> 2;
    const int tig = lane & 3;

    // A loader: thread -> (row r, k-half)
    const int ar   = tid >> 1;
    const int half = tid & 1;
    int gma = mtile * BM + ar; if (gma > M - 1) gma = M - 1;
    const int raa = GATHER ? rowmap[gma] : gma;
    const __nv_bfloat16* pAh = Ah + (size_t)raa * lda;
    const __nv_bfloat16* pAl = Al + (size_t)raa * lda;

    // B loader: thread -> (k row kb, n chunk pair cb)
    const int kb = tid >> 3;              // 0..31
    const int cb = (tid & 7) * 2;         // 16B chunk index (8 n each)

    float acc[4][4][4];
#pragma unroll
    for (int i = 0; i < 4; i++)
#pragma unroll
        for (int j = 0; j < 4; j++)
#pragma unroll
            for (int r = 0; r < 4; r++) acc[i][j][r] = 0.f;

    const int nc = (K + BK - 1) / BK;

    auto issue = [&](int ch) {
        const uint32_t sb = su + (uint32_t)(ch % NSTAGE) * STAGE;
        const int k0 = ch * BK + half * 16;
        const int v0 = (k0 + 8  <= K) ? 16 : 0;
        const int v1 = (k0 + 16 <= K) ? 16 : 0;
        uint32_t da = sb + OFF_AH + ar * ASTR + half * 32;
        cpa16(da,      v0 ? (const void*)(pAh + k0)     : (const void*)Ah, v0);
        cpa16(da + 16, v1 ? (const void*)(pAh + k0 + 8) : (const void*)Ah, v1);
        da = sb + OFF_AL + ar * ASTR + half * 32;
        cpa16(da,      v0 ? (const void*)(pAl + k0)     : (const void*)Al, v0);
        cpa16(da + 16, v1 ? (const void*)(pAl + k0 + 8) : (const void*)Al, v1);

        const int gk = ch * BK + kb;
        const int vb = (gk < K) ? 16 : 0;
        const __nv_bfloat16* sbh = Bh + (size_t)gk * ldb + ntile * BN + cb * 8;
        const __nv_bfloat16* sbl = Bl + (size_t)gk * ldb + ntile * BN + cb * 8;
        uint32_t db = sb + OFF_BH + kb * BSTR + cb * 16;
        cpa16(db,      vb ? (const void*)sbh       : (const void*)Bh, vb);
        cpa16(db + 16, vb ? (const void*)(sbh + 8) : (const void*)Bh, vb);
        db = sb + OFF_BL + kb * BSTR + cb * 16;
        cpa16(db,      vb ? (const void*)sbl       : (const void*)Bl, vb);
        cpa16(db + 16, vb ? (const void*)(sbl + 8) : (const void*)Bl, vb);
        asm volatile("cp.async.commit_group;" ::: "memory");
    };

    // fragment address components
    const uint32_t a_l = (uint32_t)((wm + (lane & 15)) * ASTR + (lane >> 4) * 16);
    const uint32_t b_l = (uint32_t)((lane & 15) * BSTR + (lane >> 4) * 16);

    issue(0);

    for (int ch = 0; ch < nc; ch++) {
        if (ch + 1 < nc) {
            issue(ch + 1);
            asm volatile("cp.async.wait_group 1;" ::: "memory");
        } else {
            asm volatile("cp.async.wait_group 0;" ::: "memory");
        }
        __syncthreads();

        const uint32_t sb = su + (uint32_t)(ch % NSTAGE) * STAGE;
#pragma unroll
        for (int ks = 0; ks < 2; ks++) {
            unsigned ah[4][4], al[4][4], bh[2][4], bl[2][4];
#pragma unroll
            for (int mt = 0; mt < 4; mt++) {
                const uint32_t off = a_l + (uint32_t)(ks * 32 + mt * 16 * ASTR);
                ldsm_x4(ah[mt], sb + OFF_AH + off);
                ldsm_x4(al[mt], sb + OFF_AL + off);
            }
#pragma unroll
            for (int p = 0; p < 2; p++) {
                const uint32_t off = b_l + (uint32_t)(ks * 16 * BSTR + (wn + p * 16) * 2);
                ldsm_x4t(bh[p], sb + OFF_BH + off);
                ldsm_x4t(bl[p], sb + OFF_BL + off);
            }
#pragma unroll
            for (int mt = 0; mt < 4; mt++)
#pragma unroll
                for (int nt = 0; nt < 4; nt++)
                    mma_bf16(acc[mt][nt], al[mt], &bh[nt >> 1][(nt & 1) * 2]);
#pragma unroll
            for (int mt = 0; mt < 4; mt++)
#pragma unroll
                for (int nt = 0; nt < 4; nt++)
                    mma_bf16(acc[mt][nt], ah[mt], &bl[nt >> 1][(nt & 1) * 2]);
#pragma unroll
            for (int mt = 0; mt < 4; mt++)
#pragma unroll
                for (int nt = 0; nt < 4; nt++)
                    mma_bf16(acc[mt][nt], ah[mt], &bh[nt >> 1][(nt & 1) * 2]);
        }
    }

    // ---- epilogue ----
#pragma unroll
    for (int nt = 0; nt < 4; nt++) {
        const int gn = ntile * BN + wn + nt * 8 + 2 * tig;
        float bx = 0.f, by = 0.f;
        if (bias) { bx = bias[gn]; by = bias[gn + 1]; }
        if (ADDVEC) { bx += addvec[gn]; by += addvec[gn + 1]; }
#pragma unroll
        for (int mt = 0; mt < 4; mt++) {
            const int gm0 = mtile * BM + wm + mt * 16 + gq;
            float v0 = acc[mt][nt][0] + bx;
            float v1 = acc[mt][nt][1] + by;
            float v2 = acc[mt][nt][2] + bx;
            float v3 = acc[mt][nt][3] + by;
            if (RELU) {
                v0 = fmaxf(v0, 0.f); v1 = fmaxf(v1, 0.f);
                v2 = fmaxf(v2, 0.f); v3 = fmaxf(v3, 0.f);
            }
            if (gm0 < M) {
                if (WF32)
                    *reinterpret_cast<float2*>(C + (size_t)gm0 * ldc + gn) = make_float2(v0, v1);
                if (WSPLIT) {
                    float h0, l0, h1, l1;
                    split_bf(v0, h0, l0); split_bf(v1, h1, l1);
                    *reinterpret_cast<unsigned*>(Ch + (size_t)gm0 * ldc + gn) = pack2(h0, h1);
                    *reinterpret_cast<unsigned*>(Cl + (size_t)gm0 * ldc + gn) = pack2(l0, l1);
                }
            }
            if (gm0 + 8 < M) {
                if (WF32)
                    *reinterpret_cast<float2*>(C + (size_t)(gm0 + 8) * ldc + gn) = make_float2(v2, v3);
                if (WSPLIT) {
                    float h2, l2, h3, l3;
                    split_bf(v2, h2, l2); split_bf(v3, h3, l3);
                    *reinterpret_cast<unsigned*>(Ch + (size_t)(gm0 + 8) * ldc + gn) = pack2(h2, h3);
                    *reinterpret_cast<unsigned*>(Cl + (size_t)(gm0 + 8) * ldc + gn) = pack2(l2, l3);
                }
            }
        }
    }
}

// ---------------- split kernel: grid-stride, 8 floats/thread/iter, 16B stores ----------------
__global__ void k_split(const float* __restrict__ in,
                        __nv_bfloat16* __restrict__ oh,
                        __nv_bfloat16* __restrict__ ol, int n)
{
    const int stride = gridDim.x * blockDim.x * 8;
    for (int i = (blockIdx.x * blockDim.x + threadIdx.x) * 8; i < n; i += stride) {
        const float4 v0 = ld4(in + i);
        const float4 v1 = ld4(in + i + 4);
        float h0, l0, h1, l1, h2, l2, h3, l3;
        float h4, l4, h5, l5, h6, l6, h7, l7;
        split_bf(v0.x, h0, l0); split_bf(v0.y, h1, l1);
        split_bf(v0.z, h2, l2); split_bf(v0.w, h3, l3);
        split_bf(v1.x, h4, l4); split_bf(v1.y, h5, l5);
        split_bf(v1.z, h6, l6); split_bf(v1.w, h7, l7);
        *reinterpret_cast<uint4*>(oh + i) =
            make_uint4(pack2(h0, h1), pack2(h2, h3), pack2(h4, h5), pack2(h6, h7));
        *reinterpret_cast<uint4*>(ol + i) =
            make_uint4(pack2(l0, l1), pack2(l2, l3), pack2(l4, l5), pack2(l6, l7));
    }
}

// ---------------- GEMM wrappers ----------------
__global__ __launch_bounds__(256, 2) void k_embed(
    const int* __restrict__ src, const float* __restrict__ bias, float* __restrict__ C)
{
    gemm_bf<true, false, false, true, true>(
        g_th, g_tl, FEAT_, src, g_m2vh, g_m2vl, D_, bias, nullptr,
        C, g_xh, g_xl, D_, NTOK, D_, FEAT_, blockIdx.y, blockIdx.x);
}

// fused K+V projection: z=0 -> K (fp32), z=1 -> V (fp32 + split)
__global__ __launch_bounds__(256, 2) void k_projkv(
    const __nv_bfloat16* __restrict__ Wkh, const __nv_bfloat16* __restrict__ Wkl,
    const __nv_bfloat16* __restrict__ Wvh, const __nv_bfloat16* __restrict__ Wvl,
    const float* __restrict__ bk, const float* __restrict__ bv,
    float* __restrict__ K, float* __restrict__ V)
{
    if (blockIdx.z == 0) {
        gemm_bf<false, false, false, true, false>(
            g_xh, g_xl, D_, nullptr, Wkh, Wkl, D_, bk, nullptr,
            K, nullptr, nullptr, D_, NTOK, D_, D_, blockIdx.y, blockIdx.x);
    } else {
        gemm_bf<false, false, false, true, true>(
            g_xh, g_xl, D_, nullptr, Wvh, Wvl, D_, bv, nullptr,
            V, g_Vh, g_Vl, D_, NTOK, D_, D_, blockIdx.y, blockIdx.x);
    }
}

// pbv: A = pb split [T][T], B = V split [T][D], addvec = kv; C = wv split only
__global__ __launch_bounds__(256, 2) void k_pbv(const float* __restrict__ kv)
{
    const int b = blockIdx.z;
    gemm_bf<false, false, true, false, true>(
        g_pbh + (size_t)b * T_ * T_, g_pbl + (size_t)b * T_ * T_, T_, nullptr,
        g_Vh + (size_t)b * T_ * D_, g_Vl + (size_t)b * T_ * D_, D_,
        nullptr, kv + (size_t)b * D_,
        nullptr, g_wvh + (size_t)b * T_ * D_, g_wvl + (size_t)b * T_ * D_, D_,
        T_, D_, T_, 0, blockIdx.x);
}

// Wo gemm: A = wv split; C fp32
__global__ __launch_bounds__(256, 2) void k_wo(
    const __nv_bfloat16* __restrict__ Bh, const __nv_bfloat16* __restrict__ Bl,
    const float* __restrict__ bias, float* __restrict__ C)
{
    gemm_bf<false, false, false, true, false>(
        g_wvh, g_wvl, D_, nullptr, Bh, Bl, D_, bias, nullptr,
        C, nullptr, nullptr, D_, NTOK, D_, D_, blockIdx.y, blockIdx.x);
}

__global__ __launch_bounds__(256, 2) void k_moe1(int layer, const float* __restrict__ b1)
{
    const int e = blockIdx.z;
    const int Me = g_off[e + 1] - g_off[e];
    if ((int)(blockIdx.y * BM) >= Me) return;
    const size_t woff = ((size_t)layer * E_ + e) * D_ * FF_;
    const size_t ooff = (size_t)g_off[e] * FF_;
    gemm_bf<true, true, false, false, true>(
        g_xh, g_xl, D_, g_tok + g_off[e],
        g_e1h + woff, g_e1l + woff, FF_,
        b1 + (size_t)e * FF_, nullptr,
        nullptr, g_hh + ooff, g_hl + ooff, FF_,
        Me, FF_, D_, blockIdx.y, blockIdx.x);
}

__global__ __launch_bounds__(256, 2) void k_moe2(int layer, const float* __restrict__ b2)
{
    const int e = blockIdx.z;
    const int Me = g_off[e + 1] - g_off[e];
    if ((int)(blockIdx.y * BM) >= Me) return;
    const size_t woff = ((size_t)layer * E_ + e) * FF_ * D_;
    const size_t ioff = (size_t)g_off[e] * FF_;
    gemm_bf<false, false, false, true, false>(
        g_hh + ioff, g_hl + ioff, FF_, nullptr,
        g_e2h + woff, g_e2l + woff, D_,
        b2 + (size_t)e * D_, nullptr,
        g_eo + (size_t)g_off[e] * D_, nullptr, nullptr, D_,
        Me, D_, FF_, blockIdx.y, blockIdx.x);
}

// ---------------- Fourier positional bias (writes split) ----------------
__global__ void k_pb(const float* __restrict__ frac,
                     const float* __restrict__ pbW,
                     const float* __restrict__ pbb,
                     const float* __restrict__ pba)
{
    __shared__ float w[NF_], ph[NF_], am[NF_];
    if (threadIdx.x < NF_) {
        w[threadIdx.x]  = pbW[threadIdx.x];
        ph[threadIdx.x] = pbb[threadIdx.x];
        am[threadIdx.x] = pba[threadIdx.x];
    }
    __syncthreads();
    const int idx = blockIdx.x * 256 + threadIdx.x;
    const int j = idx & 127;
    const int i = (idx >> 7) & 127;
    const int b = idx >> 14;
    const float d = (frac[b * T_ + j] - frac[b * T_ + i]) * SCALE_;
    float s = 0.f;
#pragma unroll
    for (int f = 0; f < NF_; f++) s += am[f] * cosf(d * w[f] + ph[f]);
    float h, l;
    split_bf(s, h, l);
    g_pbh[idx] = __float2bfloat16_rn(h);
    g_pbl[idx] = __float2bfloat16_rn(l);
}

// ---------------- kv reduction ----------------
__global__ void k_kv(const float* __restrict__ K, const float* __restrict__ V,
                     float* __restrict__ kv)
{
    const int b = blockIdx.x;
    const int d = threadIdx.x;
    const float* Kb = K + (size_t)b * T_ * D_ + d;
    const float* Vb = V + (size_t)b * T_ * D_ + d;
    float s = 0.f;
#pragma unroll 8
    for (int t = 0; t < T_; t++) s += Kb[t * D_] * Vb[t * D_];
    kv[b * D_ + d] = s;
}

// ---------------- block reduction ----------------
__device__ __forceinline__ float blk_sum_256(float v, float* red) {
    const unsigned m = 0xffffffffu;
#pragma unroll
    for (int o = 16; o > 0; o >>= 1) v += __shfl_down_sync(m, v, o);
    if ((threadIdx.x & 31) == 0) red[threadIdx.x >> 5] = v;
    __syncthreads();
    if (threadIdx.x < 32) {
        float r = (threadIdx.x < 8) ? red[threadIdx.x] : 0.f;
#pragma unroll
        for (int o = 4; o > 0; o >>= 1) r += __shfl_down_sync(m, r, o);
        if (threadIdx.x == 0) red[0] = r;
    }
    __syncthreads();
    const float r = red[0];
    __syncthreads();
    return r;
}

__device__ __forceinline__ void ln_store(float* out, int t, int c, float v,
                                         const float* g, const float* b,
                                         float inv, float mean, bool wsplit) {
    const float r = (v - mean) * inv * g[c] + b[c];
    out[(size_t)t * D_ + c] = r;
    if (wsplit) {
        float h, l;
        split_bf(r, h, l);
        g_xh[(size_t)t * D_ + c] = __float2bfloat16_rn(h);
        g_xl[(size_t)t * D_ + c] = __float2bfloat16_rn(l);
    }
}

// ---------------- LN1: out = LN(x + y), writes fp32 + split ----------------
__global__ void k_ln(const float* __restrict__ x, const float* __restrict__ y,
                     const float* __restrict__ g, const float* __restrict__ b,
                     float* __restrict__ out)
{
    __shared__ float red[8];
    const int t = blockIdx.x;
    const int tid = threadIdx.x;
    const float* xr = x + (size_t)t * D_;
    const float* yr = y + (size_t)t * D_;
    const float v0 = xr[tid]       + yr[tid];
    const float v1 = xr[tid + 256] + yr[tid + 256];
    const float mean = blk_sum_256(v0 + v1, red) * (1.f / D_);
    const float d0 = v0 - mean, d1 = v1 - mean;
    const float var = blk_sum_256(d0 * d0 + d1 * d1, red) * (1.f / D_);
    const float inv = rsqrtf(var + EPS_);
    ln_store(out, t, tid,       v0, g, b, inv, mean, true);
    ln_store(out, t, tid + 256, v1, g, b, inv, mean, true);
}

// ---------------- gating ----------------
__global__ void k_gate(const float* __restrict__ x, const float* __restrict__ gW,
                       const float* __restrict__ gb, int layer)
{
    __shared__ float xs[D_];
    __shared__ float lg[E_];
    const int t = blockIdx.x;
    const int tid = threadIdx.x;
    xs[tid]       = x[(size_t)t * D_ + tid];
    xs[tid + 256] = x[(size_t)t * D_ + tid + 256];
    __syncthreads();

    const int e = tid >> 5;
    const int lane = tid & 31;
    float s = 0.f;
    for (int k = lane; k < D_; k += 32) s += xs[k] * gW[k * E_ + e];
    const unsigned m = 0xffffffffu;
#pragma unroll
    for (int o = 16; o > 0; o >>= 1) s += __shfl_down_sync(m, s, o);
    if (lane == 0) lg[e] = s + gb[e];
    __syncthreads();

    if (tid == 0) {
        float mx = lg[0];
#pragma unroll
        for (int k = 1; k < E_; k++) mx = fmaxf(mx, lg[k]);
        float ex[E_]; float sum = 0.f;
#pragma unroll
        for (int k = 0; k < E_; k++) { ex[k] = expf(lg[k] - mx); sum += ex[k]; }
        const float inv = 1.f / sum;
        int e0 = 0; float p0 = ex[0];
#pragma unroll
        for (int k = 1; k < E_; k++) if (ex[k] > p0) { p0 = ex[k]; e0 = k; }
        int e1 = -1; float p1 = -1.f;
#pragma unroll
        for (int k = 0; k < E_; k++)
            if (k != e0 && ex[k] > p1) { p1 = ex[k]; e1 = k; }
        g_te[2 * t]     = e0; g_tw[2 * t]     = p0 * inv;
        g_te[2 * t + 1] = e1; g_tw[2 * t + 1] = p1 * inv;
        atomicAdd(&g_cntA[layer * E_ + e0], 1);
        atomicAdd(&g_cntA[layer * E_ + e1], 1);
    }
}

__global__ void k_zero_all() {
    if (threadIdx.x < NL_ * E_) g_cntA[threadIdx.x] = 0;
}

__global__ void k_scan(int layer) {
    if (threadIdx.x == 0) {
        int a = 0;
        for (int e = 0; e < E_; e++) {
            g_off[e] = a; g_cur[e] = a;
            a += g_cntA[layer * E_ + e];
        }
        g_off[E_] = a;
    }
}

__global__ void k_scatter() {
    const int t = blockIdx.x * 256 + threadIdx.x;
    if (t >= NTOK) return;
#pragma unroll
    for (int k = 0; k < 2; k++) {
        const int e = g_te[2 * t + k];
        const int p = atomicAdd(&g_cur[e], 1);
        g_tok[p] = t;
        g_pos[2 * t + k] = p;
    }
}

// ---------------- LN2 ----------------
__global__ void k_ln2(const float* __restrict__ x,
                      const float* __restrict__ g, const float* __restrict__ b,
                      float* __restrict__ out, int wsplit)
{
    __shared__ float red[8];
    const int t = blockIdx.x;
    const int tid = threadIdx.x;
    const int p0 = g_pos[2 * t], p1 = g_pos[2 * t + 1];
    const float w0 = g_tw[2 * t], w1 = g_tw[2 * t + 1];
    const float* e0 = g_eo + (size_t)p0 * D_;
    const float* e1 = g_eo + (size_t)p1 * D_;
    const float* xr = x + (size_t)t * D_;
    const float v0 = xr[tid]       + w0 * e0[tid]       + w1 * e1[tid];
    const float v1 = xr[tid + 256] + w0 * e0[tid + 256] + w1 * e1[tid + 256];
    const float mean = blk_sum_256(v0 + v1, red) * (1.f / D_);
    const float d0 = v0 - mean, d1 = v1 - mean;
    const float var = blk_sum_256(d0 * d0 + d1 * d1, red) * (1.f / D_);
    const float inv = rsqrtf(var + EPS_);
    ln_store(out, t, tid,       v0, g, b, inv, mean, wsplit != 0);
    ln_store(out, t, tid + 256, v1, g, b, inv, mean, wsplit != 0);
}

// ---------------- host launcher ----------------
extern "C" void kernel_launch(void* const* d_in, const int* in_sizes, int n_in,
                              void* d_out, int out_size)
{
    const int*   src  = (const int*)  d_in[0];
    const float* frac = (const float*)d_in[1];
    const float* tab  = (const float*)d_in[2];
    const float* Wm2v = (const float*)d_in[3];
    const float* bm2v = (const float*)d_in[4];
    const float* pbW  = (const float*)d_in[5];
    const float* pbb  = (const float*)d_in[6];
    const float* pba  = (const float*)d_in[7];
    const float* Wk   = (const float*)d_in[8];
    const float* bk   = (const float*)d_in[9];
    const float* Wv   = (const float*)d_in[10];
    const float* bv   = (const float*)d_in[11];
    const float* Wo   = (const float*)d_in[12];
    const float* bo   = (const float*)d_in[13];
    const float* ln1g = (const float*)d_in[14];
    const float* ln1b = (const float*)d_in[15];
    const float* ln2g = (const float*)d_in[16];
    const float* ln2b = (const float*)d_in[17];
    const float* gW   = (const float*)d_in[18];
    const float* gb   = (const float*)d_in[19];
    const float* eW1  = (const float*)d_in[20];
    const float* eb1  = (const float*)d_in[21];
    const float* eW2  = (const float*)d_in[22];
    const float* eb2  = (const float*)d_in[23];

    float *x, *Kb, *Vb, *kvb, *o;
    cudaGetSymbolAddress((void**)&x,   g_x);
    cudaGetSymbolAddress((void**)&Kb,  g_K);
    cudaGetSymbolAddress((void**)&Vb,  g_V);
    cudaGetSymbolAddress((void**)&kvb, g_kv);
    cudaGetSymbolAddress((void**)&o,   g_o);

    __nv_bfloat16 *th, *tl, *m2vh, *m2vl, *Wkh, *Wkl, *Wvh, *Wvl, *Woh, *Wol;
    __nv_bfloat16 *e1h, *e1l, *e2h, *e2l;
    cudaGetSymbolAddress((void**)&th,   g_th);
    cudaGetSymbolAddress((void**)&tl,   g_tl);
    cudaGetSymbolAddress((void**)&m2vh, g_m2vh);
    cudaGetSymbolAddress((void**)&m2vl, g_m2vl);
    cudaGetSymbolAddress((void**)&Wkh,  g_Wkh);
    cudaGetSymbolAddress((void**)&Wkl,  g_Wkl);
    cudaGetSymbolAddress((void**)&Wvh,  g_Wvh);
    cudaGetSymbolAddress((void**)&Wvl,  g_Wvl);
    cudaGetSymbolAddress((void**)&Woh,  g_Woh);
    cudaGetSymbolAddress((void**)&Wol,  g_Wol);
    cudaGetSymbolAddress((void**)&e1h,  g_e1h);
    cudaGetSymbolAddress((void**)&e1l,  g_e1l);
    cudaGetSymbolAddress((void**)&e2h,  g_e2h);
    cudaGetSymbolAddress((void**)&e2l,  g_e2l);

    static bool attr_done = false;
    if (!attr_done) {
        cudaFuncSetAttribute(k_embed,  cudaFuncAttributeMaxDynamicSharedMemorySize, SMEM_SZ);
        cudaFuncSetAttribute(k_projkv, cudaFuncAttributeMaxDynamicSharedMemorySize, SMEM_SZ);
        cudaFuncSetAttribute(k_pbv,    cudaFuncAttributeMaxDynamicSharedMemorySize, SMEM_SZ);
        cudaFuncSetAttribute(k_wo,     cudaFuncAttributeMaxDynamicSharedMemorySize, SMEM_SZ);
        cudaFuncSetAttribute(k_moe1,   cudaFuncAttributeMaxDynamicSharedMemorySize, SMEM_SZ);
        cudaFuncSetAttribute(k_moe2,   cudaFuncAttributeMaxDynamicSharedMemorySize, SMEM_SZ);
        attr_done = true;
    }

    // weight splits (fp32 -> bf16 hi/lo), grid-stride
    auto split = [&](const float* in, __nv_bfloat16* oh, __nv_bfloat16* ol, int n) {
        int grid = (n / 8 + 255) / 256;
        if (grid > 4736) grid = 4736;
        k_split<<<grid, 256>>>(in, oh, ol, n);
    };
    split(tab,  th,   tl,   VOCAB_ * FEAT_);
    split(Wm2v, m2vh, m2vl, FEAT_ * D_);
    split(Wk,   Wkh,  Wkl,  NL_ * D_ * D_);
    split(Wv,   Wvh,  Wvl,  NL_ * D_ * D_);
    split(Wo,   Woh,  Wol,  NL_ * D_ * D_);
    split(eW1,  e1h,  e1l,  NL_ * E_ * D_ * FF_);
    split(eW2,  e2h,  e2l,  NL_ * E_ * FF_ * D_);
    k_zero_all<<<1, 32>>>();

    const dim3 g44(4, 32);        // N=512/128 x M=4096/128

    k_embed<<<g44, 256, SMEM_SZ>>>(src, bm2v, x);
    k_pb<<<(B_ * T_ * T_) / 256, 256>>>(frac, pbW, pbb, pba);

    for (int i = 0; i < NL_; i++) {
        const size_t wOff = (size_t)i * D_ * D_;
        k_projkv<<<dim3(4, 32, 2), 256, SMEM_SZ>>>(
            Wkh + wOff, Wkl + wOff, Wvh + wOff, Wvl + wOff,
            bk + i * D_, bv + i * D_, Kb, Vb);
        k_kv<<<B_, 512>>>(Kb, Vb, kvb);
        k_pbv<<<dim3(4, 1, B_), 256, SMEM_SZ>>>(kvb);
        k_wo<<<g44, 256, SMEM_SZ>>>(Woh + wOff, Wol + wOff, bo + i * D_, o);
        k_ln<<<NTOK, 256>>>(x, o, ln1g + i * D_, ln1b + i * D_, x);

        k_gate<<<NTOK, 256>>>(x, gW + (size_t)i * D_ * E_, gb + i * E_, i);
        k_scan<<<1, 1>>>(i);
        k_scatter<<<NTOK / 256, 256>>>();

        k_moe1<<<dim3(FF_ / BN, 32, E_), 256, SMEM_SZ>>>(i, eb1 + (size_t)i * E_ * FF_);
        k_moe2<<<dim3(D_ / BN, 32, E_), 256, SMEM_SZ>>>(i, eb2 + (size_t)i * E_ * D_);

        float* dst = (i == NL_ - 1) ? (float*)d_out : x;
        k_ln2<<<NTOK, 256>>>(x, ln2g + i * D_, ln2b + i * D_, dst,
                             (i == NL_ - 1) ? 0 : 1);
    }
}

// round 13
// speedup vs baseline: 1.3995x; 1.0366x over previous
#include <cuda_runtime.h>
#include <cuda_bf16.h>
#include <cstdint>

// ---------------- problem constants ----------------
#define B_   32
#define T_   128
#define D_   512
#define FF_  2048
#define E_   8
#define NL_  3
#define NF_  16
#define FEAT_ 200
#define VOCAB_ 119
#define NTOK  4096          // B*T
#define NSLOT 8192          // NTOK*2 (top-2 slots)
#define SCALE_ 10.0f
#define EPS_   1e-5f

// ---------------- fp32 scratch ----------------
__device__ float g_x  [NTOK * D_];
__device__ float g_K  [NTOK * D_];
__device__ float g_V  [NTOK * D_];
__device__ float g_kv [B_ * D_];
__device__ float g_o  [NTOK * D_];
__device__ float g_eo [(NSLOT + 128) * D_];
__device__ int   g_te [NSLOT];
__device__ float g_tw [NSLOT];
__device__ int   g_cntA[NL_ * E_];
__device__ int   g_off[E_ + 1];
__device__ int   g_cur[E_];
__device__ int   g_tok[NSLOT + 128];
__device__ int   g_pos[NSLOT];

// ---------------- bf16 hi/lo scratch ----------------
__device__ __nv_bfloat16 g_th[VOCAB_ * FEAT_],  g_tl[VOCAB_ * FEAT_];
__device__ __nv_bfloat16 g_m2vh[FEAT_ * D_],    g_m2vl[FEAT_ * D_];
__device__ __nv_bfloat16 g_Wkh[NL_ * D_ * D_],  g_Wkl[NL_ * D_ * D_];
__device__ __nv_bfloat16 g_Wvh[NL_ * D_ * D_],  g_Wvl[NL_ * D_ * D_];
__device__ __nv_bfloat16 g_Woh[NL_ * D_ * D_],  g_Wol[NL_ * D_ * D_];
__device__ __nv_bfloat16 g_e1h[NL_ * E_ * D_ * FF_], g_e1l[NL_ * E_ * D_ * FF_];
__device__ __nv_bfloat16 g_e2h[NL_ * E_ * FF_ * D_], g_e2l[NL_ * E_ * FF_ * D_];
__device__ __nv_bfloat16 g_xh[NTOK * D_],  g_xl[NTOK * D_];
__device__ __nv_bfloat16 g_Vh[NTOK * D_],  g_Vl[NTOK * D_];
__device__ __nv_bfloat16 g_pbh[B_ * T_ * T_], g_pbl[B_ * T_ * T_];
__device__ __nv_bfloat16 g_wvh[NTOK * D_], g_wvl[NTOK * D_];
__device__ __nv_bfloat16 g_hh[(NSLOT + 128) * FF_], g_hl[(NSLOT + 128) * FF_];

// ---------------- helpers ----------------
__device__ __forceinline__ uint32_t smem_u32(const void* p) {
    uint32_t a;
    asm("{ .reg .u64 t; cvta.to.shared.u64 t, %1; cvt.u32.u64 %0, t; }" : "=r"(a) : "l"(p));
    return a;
}
__device__ __forceinline__ float4 ld4(const float* p) {
    return *reinterpret_cast<const float4*>(p);
}
__device__ __forceinline__ unsigned pack2(float lo, float hi) {
    unsigned r;
    asm("cvt.rn.bf16x2.f32 %0, %1, %2;" : "=r"(r) : "f"(hi), "f"(lo));
    return r;
}
__device__ __forceinline__ void split_bf(float x, float& h, float& l) {
    h = __bfloat162float(__float2bfloat16_rn(x));
    l = x - h;
}
__device__ __forceinline__ void ldsm_x4(unsigned* r, uint32_t addr) {
    asm volatile("ldmatrix.sync.aligned.m8n8.x4.shared.b16 {%0,%1,%2,%3}, [%4];"
                 : "=r"(r[0]), "=r"(r[1]), "=r"(r[2]), "=r"(r[3]) : "r"(addr));
}
__device__ __forceinline__ void ldsm_x4t(unsigned* r, uint32_t addr) {
    asm volatile("ldmatrix.sync.aligned.m8n8.x4.trans.shared.b16 {%0,%1,%2,%3}, [%4];"
                 : "=r"(r[0]), "=r"(r[1]), "=r"(r[2]), "=r"(r[3]) : "r"(addr));
}
__device__ __forceinline__ void mma_bf16(float* c, const unsigned* a, const unsigned* b) {
    asm("mma.sync.aligned.m16n8k16.row.col.f32.bf16.bf16.f32 "
        "{%0,%1,%2,%3}, {%4,%5,%6,%7}, {%8,%9}, {%0,%1,%2,%3};"
        : "+f"(c[0]), "+f"(c[1]), "+f"(c[2]), "+f"(c[3])
        : "r"(a[0]), "r"(a[1]), "r"(a[2]), "r"(a[3]), "r"(b[0]), "r"(b[1]));
}
__device__ __forceinline__ void cpa16(uint32_t dst, const void* src, int srcbytes) {
    asm volatile("cp.async.cg.shared.global [%0], [%1], 16, %2;"
                 :: "r"(dst), "l"(src), "r"(srcbytes) : "memory");
}

// ---------------- bf16x3 GEMM core: cp.async 3-stage, ldmatrix, BMx128x32 ----------------
#define BN 128
#define BK 32
#define ASTR 80             // A row stride bytes (64B data + 16 pad)
#define BSTR 272            // B row stride bytes (256B data + 16 pad)
#define NSTAGE 3
// MT = m-tiles per warp (4 -> BM128, 2 -> BM64)
#define STG_MT4 37888
#define STG_MT2 27648
#define SMEM4 (NSTAGE * STG_MT4)   // 113664 -> 2 CTAs/SM
#define SMEM2 (NSTAGE * STG_MT2)   // 82944  -> 2 CTAs/SM

// C[M,N] = op( gather(A)[M,K] @ B[K,N] + bias + addvec )
// A: bf16 hi/lo [m][k] row-major; B: bf16 hi/lo [k][n] row-major.
// 256 threads = 8 warps (2m x 4n), warp tile (MT*16) x 32.
template <int MT, bool GATHER, bool RELU, bool ADDVEC, bool WF32, bool WSPLIT>
__device__ __forceinline__ void gemm_bf(
    const __nv_bfloat16* __restrict__ Ah, const __nv_bfloat16* __restrict__ Al,
    int lda, const int* __restrict__ rowmap,
    const __nv_bfloat16* __restrict__ Bh, const __nv_bfloat16* __restrict__ Bl,
    int ldb,
    const float* __restrict__ bias, const float* __restrict__ addvec,
    float* __restrict__ C, __nv_bfloat16* __restrict__ Ch, __nv_bfloat16* __restrict__ Cl,
    int ldc, int M, int N, int K, int mtile, int ntile)
{
    constexpr int BMv = MT * 32;
    constexpr int ABYTES = BMv * ASTR;
    constexpr int OFFAL = ABYTES;
    constexpr int OFFBH = 2 * ABYTES;
    constexpr int OFFBL = OFFBH + 32 * BSTR;
    constexpr int STG   = OFFBL + 32 * BSTR;
    constexpr int NCH   = BMv / 64;          // A 16B-chunks per thread

    extern __shared__ char smem[];
    const uint32_t su = smem_u32(smem);
    const int tid  = threadIdx.x;
    const int lane = tid & 31;
    const int warp = tid >> 5;
    const int wm = (warp >> 2) * (MT * 16);
    const int wn = (warp & 3) * 32;
    const int gq  = lane >> 2;
    const int tig = lane & 3;

    // A loader: each thread owns NCH 16B chunks (row, k-quarter)
    int arow[NCH]; int aq[NCH];
    const __nv_bfloat16* pAh[NCH];
    const __nv_bfloat16* pAl[NCH];
#pragma unroll
    for (int c = 0; c < NCH; c++) {
        const int chunk = tid + c * 256;
        const int r = chunk >> 2;
        const int q = chunk & 3;
        int gm = mtile * BMv + r; if (gm > M - 1) gm = M - 1;
        const int ra = GATHER ? rowmap[gm] : gm;
        arow[c] = r; aq[c] = q;
        pAh[c] = Ah + (size_t)ra * lda + q * 8;
        pAl[c] = Al + (size_t)ra * lda + q * 8;
    }

    // B loader: thread -> (k row kb, n chunk pair cb)
    const int kb = tid >> 3;              // 0..31
    const int cb = (tid & 7) * 2;         // 16B chunk index (8 n each)

    float acc[MT][4][4];
#pragma unroll
    for (int i = 0; i < MT; i++)
#pragma unroll
        for (int j = 0; j < 4; j++)
#pragma unroll
            for (int r = 0; r < 4; r++) acc[i][j][r] = 0.f;

    const int nc = (K + BK - 1) / BK;

    auto issue = [&](int ch) {
        const uint32_t sb = su + (uint32_t)(ch % NSTAGE) * STG;
#pragma unroll
        for (int c = 0; c < NCH; c++) {
            const int k0 = ch * BK + aq[c] * 8;
            const int v = (k0 + 8 <= K) ? 16 : 0;
            const uint32_t da = sb + arow[c] * ASTR + aq[c] * 16;
            cpa16(da,         v ? (const void*)(pAh[c] + ch * BK) : (const void*)Ah, v);
            cpa16(da + OFFAL, v ? (const void*)(pAl[c] + ch * BK) : (const void*)Al, v);
        }
        const int gk = ch * BK + kb;
        const int vb = (gk < K) ? 16 : 0;
        const __nv_bfloat16* sbh = Bh + (size_t)gk * ldb + ntile * BN + cb * 8;
        const __nv_bfloat16* sbl = Bl + (size_t)gk * ldb + ntile * BN + cb * 8;
        uint32_t db = sb + OFFBH + kb * BSTR + cb * 16;
        cpa16(db,      vb ? (const void*)sbh       : (const void*)Bh, vb);
        cpa16(db + 16, vb ? (const void*)(sbh + 8) : (const void*)Bh, vb);
        db = sb + OFFBL + kb * BSTR + cb * 16;
        cpa16(db,      vb ? (const void*)sbl       : (const void*)Bl, vb);
        cpa16(db + 16, vb ? (const void*)(sbl + 8) : (const void*)Bl, vb);
        asm volatile("cp.async.commit_group;" ::: "memory");
    };

    // fragment address components
    const uint32_t a_l = (uint32_t)((wm + (lane & 15)) * ASTR + (lane >> 4) * 16);
    const uint32_t b_l = (uint32_t)((lane & 15) * BSTR + (lane >> 4) * 16);

    issue(0);

    for (int ch = 0; ch < nc; ch++) {
        if (ch + 1 < nc) {
            issue(ch + 1);
            asm volatile("cp.async.wait_group 1;" ::: "memory");
        } else {
            asm volatile("cp.async.wait_group 0;" ::: "memory");
        }
        __syncthreads();

        const uint32_t sb = su + (uint32_t)(ch % NSTAGE) * STG;
#pragma unroll
        for (int ks = 0; ks < 2; ks++) {
            unsigned ah[MT][4], al[MT][4], bh[2][4], bl[2][4];
#pragma unroll
            for (int mt = 0; mt < MT; mt++) {
                const uint32_t off = a_l + (uint32_t)(ks * 32 + mt * 16 * ASTR);
                ldsm_x4(ah[mt], sb + off);
                ldsm_x4(al[mt], sb + OFFAL + off);
            }
#pragma unroll
            for (int p = 0; p < 2; p++) {
                const uint32_t off = b_l + (uint32_t)(ks * 16 * BSTR + (wn + p * 16) * 2);
                ldsm_x4t(bh[p], sb + OFFBH + off);
                ldsm_x4t(bl[p], sb + OFFBL + off);
            }
#pragma unroll
            for (int mt = 0; mt < MT; mt++)
#pragma unroll
                for (int nt = 0; nt < 4; nt++)
                    mma_bf16(acc[mt][nt], al[mt], &bh[nt >> 1][(nt & 1) * 2]);
#pragma unroll
            for (int mt = 0; mt < MT; mt++)
#pragma unroll
                for (int nt = 0; nt < 4; nt++)
                    mma_bf16(acc[mt][nt], ah[mt], &bl[nt >> 1][(nt & 1) * 2]);
#pragma unroll
            for (int mt = 0; mt < MT; mt++)
#pragma unroll
                for (int nt = 0; nt < 4; nt++)
                    mma_bf16(acc[mt][nt], ah[mt], &bh[nt >> 1][(nt & 1) * 2]);
        }
    }

    // ---- epilogue ----
#pragma unroll
    for (int nt = 0; nt < 4; nt++) {
        const int gn = ntile * BN + wn + nt * 8 + 2 * tig;
        float bx = 0.f, by = 0.f;
        if (bias) { bx = bias[gn]; by = bias[gn + 1]; }
        if (ADDVEC) { bx += addvec[gn]; by += addvec[gn + 1]; }
#pragma unroll
        for (int mt = 0; mt < MT; mt++) {
            const int gm0 = mtile * BMv + wm + mt * 16 + gq;
            float v0 = acc[mt][nt][0] + bx;
            float v1 = acc[mt][nt][1] + by;
            float v2 = acc[mt][nt][2] + bx;
            float v3 = acc[mt][nt][3] + by;
            if (RELU) {
                v0 = fmaxf(v0, 0.f); v1 = fmaxf(v1, 0.f);
                v2 = fmaxf(v2, 0.f); v3 = fmaxf(v3, 0.f);
            }
            if (gm0 < M) {
                if (WF32)
                    *reinterpret_cast<float2*>(C + (size_t)gm0 * ldc + gn) = make_float2(v0, v1);
                if (WSPLIT) {
                    float h0, l0, h1, l1;
                    split_bf(v0, h0, l0); split_bf(v1, h1, l1);
                    *reinterpret_cast<unsigned*>(Ch + (size_t)gm0 * ldc + gn) = pack2(h0, h1);
                    *reinterpret_cast<unsigned*>(Cl + (size_t)gm0 * ldc + gn) = pack2(l0, l1);
                }
            }
            if (gm0 + 8 < M) {
                if (WF32)
                    *reinterpret_cast<float2*>(C + (size_t)(gm0 + 8) * ldc + gn) = make_float2(v2, v3);
                if (WSPLIT) {
                    float h2, l2, h3, l3;
                    split_bf(v2, h2, l2); split_bf(v3, h3, l3);
                    *reinterpret_cast<unsigned*>(Ch + (size_t)(gm0 + 8) * ldc + gn) = pack2(h2, h3);
                    *reinterpret_cast<unsigned*>(Cl + (size_t)(gm0 + 8) * ldc + gn) = pack2(l2, l3);
                }
            }
        }
    }
}

// ---------------- fused split kernel: all weight arrays in one launch ----------------
struct SJob { const float* in; __nv_bfloat16* oh; __nv_bfloat16* ol; int n; };
struct SJobs { SJob j[7]; };

__global__ void k_split_all(SJobs js)
{
    const SJob job = js.j[blockIdx.y];
    const int stride = gridDim.x * blockDim.x * 8;
    for (int i = (blockIdx.x * blockDim.x + threadIdx.x) * 8; i < job.n; i += stride) {
        const float4 v0 = ld4(job.in + i);
        const float4 v1 = ld4(job.in + i + 4);
        float h0, l0, h1, l1, h2, l2, h3, l3;
        float h4, l4, h5, l5, h6, l6, h7, l7;
        split_bf(v0.x, h0, l0); split_bf(v0.y, h1, l1);
        split_bf(v0.z, h2, l2); split_bf(v0.w, h3, l3);
        split_bf(v1.x, h4, l4); split_bf(v1.y, h5, l5);
        split_bf(v1.z, h6, l6); split_bf(v1.w, h7, l7);
        *reinterpret_cast<uint4*>(job.oh + i) =
            make_uint4(pack2(h0, h1), pack2(h2, h3), pack2(h4, h5), pack2(h6, h7));
        *reinterpret_cast<uint4*>(job.ol + i) =
            make_uint4(pack2(l0, l1), pack2(l2, l3), pack2(l4, l5), pack2(l6, l7));
    }
}

// ---------------- GEMM wrappers ----------------
__global__ __launch_bounds__(256, 2) void k_embed(
    const int* __restrict__ src, const float* __restrict__ bias, float* __restrict__ C)
{
    gemm_bf<2, true, false, false, true, true>(
        g_th, g_tl, FEAT_, src, g_m2vh, g_m2vl, D_, bias, nullptr,
        C, g_xh, g_xl, D_, NTOK, D_, FEAT_, blockIdx.y, blockIdx.x);
}

// fused K+V projection: z=0 -> K (fp32), z=1 -> V (fp32 + split)
__global__ __launch_bounds__(256, 2) void k_projkv(
    const __nv_bfloat16* __restrict__ Wkh, const __nv_bfloat16* __restrict__ Wkl,
    const __nv_bfloat16* __restrict__ Wvh, const __nv_bfloat16* __restrict__ Wvl,
    const float* __restrict__ bk, const float* __restrict__ bv,
    float* __restrict__ K, float* __restrict__ V)
{
    if (blockIdx.z == 0) {
        gemm_bf<4, false, false, false, true, false>(
            g_xh, g_xl, D_, nullptr, Wkh, Wkl, D_, bk, nullptr,
            K, nullptr, nullptr, D_, NTOK, D_, D_, blockIdx.y, blockIdx.x);
    } else {
        gemm_bf<4, false, false, false, true, true>(
            g_xh, g_xl, D_, nullptr, Wvh, Wvl, D_, bv, nullptr,
            V, g_Vh, g_Vl, D_, NTOK, D_, D_, blockIdx.y, blockIdx.x);
    }
}

// pbv: A = pb split [T][T], B = V split [T][D], addvec = kv; C = wv split only
__global__ __launch_bounds__(256, 2) void k_pbv(const float* __restrict__ kv)
{
    const int b = blockIdx.z;
    gemm_bf<2, false, false, true, false, true>(
        g_pbh + (size_t)b * T_ * T_, g_pbl + (size_t)b * T_ * T_, T_, nullptr,
        g_Vh + (size_t)b * T_ * D_, g_Vl + (size_t)b * T_ * D_, D_,
        nullptr, kv + (size_t)b * D_,
        nullptr, g_wvh + (size_t)b * T_ * D_, g_wvl + (size_t)b * T_ * D_, D_,
        T_, D_, T_, blockIdx.y, blockIdx.x);
}

// Wo gemm: A = wv split; C fp32
__global__ __launch_bounds__(256, 2) void k_wo(
    const __nv_bfloat16* __restrict__ Bh, const __nv_bfloat16* __restrict__ Bl,
    const float* __restrict__ bias, float* __restrict__ C)
{
    gemm_bf<2, false, false, false, true, false>(
        g_wvh, g_wvl, D_, nullptr, Bh, Bl, D_, bias, nullptr,
        C, nullptr, nullptr, D_, NTOK, D_, D_, blockIdx.y, blockIdx.x);
}

__global__ __launch_bounds__(256, 2) void k_moe1(int layer, const float* __restrict__ b1)
{
    const int e = blockIdx.z;
    const int Me = g_off[e + 1] - g_off[e];
    if ((int)(blockIdx.y * 128) >= Me) return;
    const size_t woff = ((size_t)layer * E_ + e) * D_ * FF_;
    const size_t ooff = (size_t)g_off[e] * FF_;
    gemm_bf<4, true, true, false, false, true>(
        g_xh, g_xl, D_, g_tok + g_off[e],
        g_e1h + woff, g_e1l + woff, FF_,
        b1 + (size_t)e * FF_, nullptr,
        nullptr, g_hh + ooff, g_hl + ooff, FF_,
        Me, FF_, D_, blockIdx.y, blockIdx.x);
}

__global__ __launch_bounds__(256, 2) void k_moe2(int layer, const float* __restrict__ b2)
{
    const int e = blockIdx.z;
    const int Me = g_off[e + 1] - g_off[e];
    if ((int)(blockIdx.y * 128) >= Me) return;
    const size_t woff = ((size_t)layer * E_ + e) * FF_ * D_;
    const size_t ioff = (size_t)g_off[e] * FF_;
    gemm_bf<4, false, false, false, true, false>(
        g_hh + ioff, g_hl + ioff, FF_, nullptr,
        g_e2h + woff, g_e2l + woff, D_,
        b2 + (size_t)e * D_, nullptr,
        g_eo + (size_t)g_off[e] * D_, nullptr, nullptr, D_,
        Me, D_, FF_, blockIdx.y, blockIdx.x);
}

// ---------------- Fourier positional bias (writes split) ----------------
__global__ void k_pb(const float* __restrict__ frac,
                     const float* __restrict__ pbW,
                     const float* __restrict__ pbb,
                     const float* __restrict__ pba)
{
    __shared__ float w[NF_], ph[NF_], am[NF_];
    if (threadIdx.x < NF_) {
        w[threadIdx.x]  = pbW[threadIdx.x];
        ph[threadIdx.x] = pbb[threadIdx.x];
        am[threadIdx.x] = pba[threadIdx.x];
    }
    __syncthreads();
    const int idx = blockIdx.x * 256 + threadIdx.x;
    const int j = idx & 127;
    const int i = (idx >> 7) & 127;
    const int b = idx >> 14;
    const float d = (frac[b * T_ + j] - frac[b * T_ + i]) * SCALE_;
    float s = 0.f;
#pragma unroll
    for (int f = 0; f < NF_; f++) s += am[f] * cosf(d * w[f] + ph[f]);
    float h, l;
    split_bf(s, h, l);
    g_pbh[idx] = __float2bfloat16_rn(h);
    g_pbl[idx] = __float2bfloat16_rn(l);
}

// ---------------- kv reduction ----------------
__global__ void k_kv(const float* __restrict__ K, const float* __restrict__ V,
                     float* __restrict__ kv)
{
    const int b = blockIdx.x;
    const int d = threadIdx.x;
    const float* Kb = K + (size_t)b * T_ * D_ + d;
    const float* Vb = V + (size_t)b * T_ * D_ + d;
    float s = 0.f;
#pragma unroll 8
    for (int t = 0; t < T_; t++) s += Kb[t * D_] * Vb[t * D_];
    kv[b * D_ + d] = s;
}

// ---------------- block reduction ----------------
__device__ __forceinline__ float blk_sum_256(float v, float* red) {
    const unsigned m = 0xffffffffu;
#pragma unroll
    for (int o = 16; o > 0; o >>= 1) v += __shfl_down_sync(m, v, o);
    if ((threadIdx.x & 31) == 0) red[threadIdx.x >> 5] = v;
    __syncthreads();
    if (threadIdx.x < 32) {
        float r = (threadIdx.x < 8) ? red[threadIdx.x] : 0.f;
#pragma unroll
        for (int o = 4; o > 0; o >>= 1) r += __shfl_down_sync(m, r, o);
        if (threadIdx.x == 0) red[0] = r;
    }
    __syncthreads();
    const float r = red[0];
    __syncthreads();
    return r;
}

__device__ __forceinline__ void ln_store(float* out, int t, int c, float v,
                                         const float* g, const float* b,
                                         float inv, float mean, bool wsplit) {
    const float r = (v - mean) * inv * g[c] + b[c];
    out[(size_t)t * D_ + c] = r;
    if (wsplit) {
        float h, l;
        split_bf(r, h, l);
        g_xh[(size_t)t * D_ + c] = __float2bfloat16_rn(h);
        g_xl[(size_t)t * D_ + c] = __float2bfloat16_rn(l);
    }
}

// ---------------- LN1: out = LN(x + y), writes fp32 + split ----------------
__global__ void k_ln(const float* __restrict__ x, const float* __restrict__ y,
                     const float* __restrict__ g, const float* __restrict__ b,
                     float* __restrict__ out)
{
    __shared__ float red[8];
    const int t = blockIdx.x;
    const int tid = threadIdx.x;
    const float* xr = x + (size_t)t * D_;
    const float* yr = y + (size_t)t * D_;
    const float v0 = xr[tid]       + yr[tid];
    const float v1 = xr[tid + 256] + yr[tid + 256];
    const float mean = blk_sum_256(v0 + v1, red) * (1.f / D_);
    const float d0 = v0 - mean, d1 = v1 - mean;
    const float var = blk_sum_256(d0 * d0 + d1 * d1, red) * (1.f / D_);
    const float inv = rsqrtf(var + EPS_);
    ln_store(out, t, tid,       v0, g, b, inv, mean, true);
    ln_store(out, t, tid + 256, v1, g, b, inv, mean, true);
}

// ---------------- gating ----------------
__global__ void k_gate(const float* __restrict__ x, const float* __restrict__ gW,
                       const float* __restrict__ gb, int layer)
{
    __shared__ float xs[D_];
    __shared__ float lg[E_];
    const int t = blockIdx.x;
    const int tid = threadIdx.x;
    xs[tid]       = x[(size_t)t * D_ + tid];
    xs[tid + 256] = x[(size_t)t * D_ + tid + 256];
    __syncthreads();

    const int e = tid >> 5;
    const int lane = tid & 31;
    float s = 0.f;
    for (int k = lane; k < D_; k += 32) s += xs[k] * gW[k * E_ + e];
    const unsigned m = 0xffffffffu;
#pragma unroll
    for (int o = 16; o > 0; o >>= 1) s += __shfl_down_sync(m, s, o);
    if (lane == 0) lg[e] = s + gb[e];
    __syncthreads();

    if (tid == 0) {
        float mx = lg[0];
#pragma unroll
        for (int k = 1; k < E_; k++) mx = fmaxf(mx, lg[k]);
        float ex[E_]; float sum = 0.f;
#pragma unroll
        for (int k = 0; k < E_; k++) { ex[k] = expf(lg[k] - mx); sum += ex[k]; }
        const float inv = 1.f / sum;
        int e0 = 0; float p0 = ex[0];
#pragma unroll
        for (int k = 1; k < E_; k++) if (ex[k] > p0) { p0 = ex[k]; e0 = k; }
        int e1 = -1; float p1 = -1.f;
#pragma unroll
        for (int k = 0; k < E_; k++)
            if (k != e0 && ex[k] > p1) { p1 = ex[k]; e1 = k; }
        g_te[2 * t]     = e0; g_tw[2 * t]     = p0 * inv;
        g_te[2 * t + 1] = e1; g_tw[2 * t + 1] = p1 * inv;
        atomicAdd(&g_cntA[layer * E_ + e0], 1);
        atomicAdd(&g_cntA[layer * E_ + e1], 1);
    }
}

__global__ void k_zero_all() {
    if (threadIdx.x < NL_ * E_) g_cntA[threadIdx.x] = 0;
}

__global__ void k_scan(int layer) {
    if (threadIdx.x == 0) {
        int a = 0;
        for (int e = 0; e < E_; e++) {
            g_off[e] = a; g_cur[e] = a;
            a += g_cntA[layer * E_ + e];
        }
        g_off[E_] = a;
    }
}

__global__ void k_scatter() {
    const int t = blockIdx.x * 256 + threadIdx.x;
    if (t >= NTOK) return;
#pragma unroll
    for (int k = 0; k < 2; k++) {
        const int e = g_te[2 * t + k];
        const int p = atomicAdd(&g_cur[e], 1);
        g_tok[p] = t;
        g_pos[2 * t + k] = p;
    }
}

// ---------------- LN2 ----------------
__global__ void k_ln2(const float* __restrict__ x,
                      const float* __restrict__ g, const float* __restrict__ b,
                      float* __restrict__ out, int wsplit)
{
    __shared__ float red[8];
    const int t = blockIdx.x;
    const int tid = threadIdx.x;
    const int p0 = g_pos[2 * t], p1 = g_pos[2 * t + 1];
    const float w0 = g_tw[2 * t], w1 = g_tw[2 * t + 1];
    const float* e0 = g_eo + (size_t)p0 * D_;
    const float* e1 = g_eo + (size_t)p1 * D_;
    const float* xr = x + (size_t)t * D_;
    const float v0 = xr[tid]       + w0 * e0[tid]       + w1 * e1[tid];
    const float v1 = xr[tid + 256] + w0 * e0[tid + 256] + w1 * e1[tid + 256];
    const float mean = blk_sum_256(v0 + v1, red) * (1.f / D_);
    const float d0 = v0 - mean, d1 = v1 - mean;
    const float var = blk_sum_256(d0 * d0 + d1 * d1, red) * (1.f / D_);
    const float inv = rsqrtf(var + EPS_);
    ln_store(out, t, tid,       v0, g, b, inv, mean, wsplit != 0);
    ln_store(out, t, tid + 256, v1, g, b, inv, mean, wsplit != 0);
}

// ---------------- host launcher ----------------
extern "C" void kernel_launch(void* const* d_in, const int* in_sizes, int n_in,
                              void* d_out, int out_size)
{
    const int*   src  = (const int*)  d_in[0];
    const float* frac = (const float*)d_in[1];
    const float* tab  = (const float*)d_in[2];
    const float* Wm2v = (const float*)d_in[3];
    const float* bm2v = (const float*)d_in[4];
    const float* pbW  = (const float*)d_in[5];
    const float* pbb  = (const float*)d_in[6];
    const float* pba  = (const float*)d_in[7];
    const float* Wk   = (const float*)d_in[8];
    const float* bk   = (const float*)d_in[9];
    const float* Wv   = (const float*)d_in[10];
    const float* bv   = (const float*)d_in[11];
    const float* Wo   = (const float*)d_in[12];
    const float* bo   = (const float*)d_in[13];
    const float* ln1g = (const float*)d_in[14];
    const float* ln1b = (const float*)d_in[15];
    const float* ln2g = (const float*)d_in[16];
    const float* ln2b = (const float*)d_in[17];
    const float* gW   = (const float*)d_in[18];
    const float* gb   = (const float*)d_in[19];
    const float* eW1  = (const float*)d_in[20];
    const float* eb1  = (const float*)d_in[21];
    const float* eW2  = (const float*)d_in[22];
    const float* eb2  = (const float*)d_in[23];

    float *x, *Kb, *Vb, *kvb, *o;
    cudaGetSymbolAddress((void**)&x,   g_x);
    cudaGetSymbolAddress((void**)&Kb,  g_K);
    cudaGetSymbolAddress((void**)&Vb,  g_V);
    cudaGetSymbolAddress((void**)&kvb, g_kv);
    cudaGetSymbolAddress((void**)&o,   g_o);

    __nv_bfloat16 *th, *tl, *m2vh, *m2vl, *Wkh, *Wkl, *Wvh, *Wvl, *Woh, *Wol;
    __nv_bfloat16 *e1h, *e1l, *e2h, *e2l;
    cudaGetSymbolAddress((void**)&th,   g_th);
    cudaGetSymbolAddress((void**)&tl,   g_tl);
    cudaGetSymbolAddress((void**)&m2vh, g_m2vh);
    cudaGetSymbolAddress((void**)&m2vl, g_m2vl);
    cudaGetSymbolAddress((void**)&Wkh,  g_Wkh);
    cudaGetSymbolAddress((void**)&Wkl,  g_Wkl);
    cudaGetSymbolAddress((void**)&Wvh,  g_Wvh);
    cudaGetSymbolAddress((void**)&Wvl,  g_Wvl);
    cudaGetSymbolAddress((void**)&Woh,  g_Woh);
    cudaGetSymbolAddress((void**)&Wol,  g_Wol);
    cudaGetSymbolAddress((void**)&e1h,  g_e1h);
    cudaGetSymbolAddress((void**)&e1l,  g_e1l);
    cudaGetSymbolAddress((void**)&e2h,  g_e2h);
    cudaGetSymbolAddress((void**)&e2l,  g_e2l);

    static bool attr_done = false;
    if (!attr_done) {
        cudaFuncSetAttribute(k_embed,  cudaFuncAttributeMaxDynamicSharedMemorySize, SMEM2);
        cudaFuncSetAttribute(k_projkv, cudaFuncAttributeMaxDynamicSharedMemorySize, SMEM4);
        cudaFuncSetAttribute(k_pbv,    cudaFuncAttributeMaxDynamicSharedMemorySize, SMEM2);
        cudaFuncSetAttribute(k_wo,     cudaFuncAttributeMaxDynamicSharedMemorySize, SMEM2);
        cudaFuncSetAttribute(k_moe1,   cudaFuncAttributeMaxDynamicSharedMemorySize, SMEM4);
        cudaFuncSetAttribute(k_moe2,   cudaFuncAttributeMaxDynamicSharedMemorySize, SMEM4);
        attr_done = true;
    }

    // weight splits (fp32 -> bf16 hi/lo): ONE launch for all arrays
    SJobs js;
    js.j[0] = { tab,  th,   tl,   VOCAB_ * FEAT_ };
    js.j[1] = { Wm2v, m2vh, m2vl, FEAT_ * D_ };
    js.j[2] = { Wk,   Wkh,  Wkl,  NL_ * D_ * D_ };
    js.j[3] = { Wv,   Wvh,  Wvl,  NL_ * D_ * D_ };
    js.j[4] = { Wo,   Woh,  Wol,  NL_ * D_ * D_ };
    js.j[5] = { eW1,  e1h,  e1l,  NL_ * E_ * D_ * FF_ };
    js.j[6] = { eW2,  e2h,  e2l,  NL_ * E_ * FF_ * D_ };
    k_split_all<<<dim3(1024, 7), 256>>>(js);
    k_zero_all<<<1, 32>>>();

    k_embed<<<dim3(4, 64), 256, SMEM2>>>(src, bm2v, x);
    k_pb<<<(B_ * T_ * T_) / 256, 256>>>(frac, pbW, pbb, pba);

    for (int i = 0; i < NL_; i++) {
        const size_t wOff = (size_t)i * D_ * D_;
        k_projkv<<<dim3(4, 32, 2), 256, SMEM4>>>(
            Wkh + wOff, Wkl + wOff, Wvh + wOff, Wvl + wOff,
            bk + i * D_, bv + i * D_, Kb, Vb);
        k_kv<<<B_, 512>>>(Kb, Vb, kvb);
        k_pbv<<<dim3(4, 2, B_), 256, SMEM2>>>(kvb);
        k_wo<<<dim3(4, 64), 256, SMEM2>>>(Woh + wOff, Wol + wOff, bo + i * D_, o);
        k_ln<<<NTOK, 256>>>(x, o, ln1g + i * D_, ln1b + i * D_, x);

        k_gate<<<NTOK, 256>>>(x, gW + (size_t)i * D_ * E_, gb + i * E_, i);
        k_scan<<<1, 1>>>(i);
        k_scatter<<<NTOK / 256, 256>>>();

        k_moe1<<<dim3(FF_ / BN, 32, E_), 256, SMEM4>>>(i, eb1 + (size_t)i * E_ * FF_);
        k_moe2<<<dim3(D_ / BN, 32, E_), 256, SMEM4>>>(i, eb2 + (size_t)i * E_ * D_);

        float* dst = (i == NL_ - 1) ? (float*)d_out : x;
        k_ln2<<<NTOK, 256>>>(x, ln2g + i * D_, ln2b + i * D_, dst,
                             (i == NL_ - 1) ? 0 : 1);
    }
}

// round 15
// speedup vs baseline: 1.4176x; 1.0129x over previous
#include <cuda_runtime.h>
#include <cuda_bf16.h>
#include <cstdint>

// ---------------- problem constants ----------------
#define B_   32
#define T_   128
#define D_   512
#define FF_  2048
#define E_   8
#define NL_  3
#define NF_  16
#define FEAT_ 200
#define VOCAB_ 119
#define NTOK  4096          // B*T
#define NSLOT 8192          // NTOK*2 (top-2 slots)
#define SCALE_ 10.0f
#define EPS_   1e-5f

// ---------------- fp32 scratch ----------------
__device__ float g_x  [NTOK * D_];
__device__ float g_K  [NTOK * D_];
__device__ float g_V  [NTOK * D_];
__device__ float g_kv [B_ * D_];
__device__ float g_o  [NTOK * D_];
__device__ float g_eo [(NSLOT + 128) * D_];
__device__ int   g_te [NSLOT];
__device__ float g_tw [NSLOT];
__device__ int   g_cntA[NL_ * E_];
__device__ int   g_off[E_ + 1];
__device__ int   g_cur[E_];
__device__ int   g_tok[NSLOT + 128];
__device__ int   g_pos[NSLOT];

// ---------------- bf16 hi/lo scratch ----------------
__device__ __nv_bfloat16 g_th[VOCAB_ * FEAT_],  g_tl[VOCAB_ * FEAT_];
__device__ __nv_bfloat16 g_m2vh[FEAT_ * D_],    g_m2vl[FEAT_ * D_];
__device__ __nv_bfloat16 g_Wkh[NL_ * D_ * D_],  g_Wkl[NL_ * D_ * D_];
__device__ __nv_bfloat16 g_Wvh[NL_ * D_ * D_],  g_Wvl[NL_ * D_ * D_];
__device__ __nv_bfloat16 g_Woh[NL_ * D_ * D_],  g_Wol[NL_ * D_ * D_];
__device__ __nv_bfloat16 g_e1h[NL_ * E_ * D_ * FF_], g_e1l[NL_ * E_ * D_ * FF_];
__device__ __nv_bfloat16 g_e2h[NL_ * E_ * FF_ * D_], g_e2l[NL_ * E_ * FF_ * D_];
__device__ __nv_bfloat16 g_xh[NTOK * D_],  g_xl[NTOK * D_];
__device__ __nv_bfloat16 g_Vh[NTOK * D_],  g_Vl[NTOK * D_];
__device__ __nv_bfloat16 g_pbh[B_ * T_ * T_], g_pbl[B_ * T_ * T_];
__device__ __nv_bfloat16 g_wvh[NTOK * D_], g_wvl[NTOK * D_];
__device__ __nv_bfloat16 g_hh[(NSLOT + 128) * FF_], g_hl[(NSLOT + 128) * FF_];

// ---------------- helpers ----------------
__device__ __forceinline__ uint32_t smem_u32(const void* p) {
    uint32_t a;
    asm("{ .reg .u64 t; cvta.to.shared.u64 t, %1; cvt.u32.u64 %0, t; }" : "=r"(a) : "l"(p));
    return a;
}
__device__ __forceinline__ float4 ld4(const float* p) {
    return *reinterpret_cast<const float4*>(p);
}
__device__ __forceinline__ unsigned pack2(float lo, float hi) {
    unsigned r;
    asm("cvt.rn.bf16x2.f32 %0, %1, %2;" : "=r"(r) : "f"(hi), "f"(lo));
    return r;
}
__device__ __forceinline__ void split_bf(float x, float& h, float& l) {
    h = __bfloat162float(__float2bfloat16_rn(x));
    l = x - h;
}
__device__ __forceinline__ void ldsm_x4(unsigned* r, uint32_t addr) {
    asm volatile("ldmatrix.sync.aligned.m8n8.x4.shared.b16 {%0,%1,%2,%3}, [%4];"
                 : "=r"(r[0]), "=r"(r[1]), "=r"(r[2]), "=r"(r[3]) : "r"(addr));
}
__device__ __forceinline__ void ldsm_x4t(unsigned* r, uint32_t addr) {
    asm volatile("ldmatrix.sync.aligned.m8n8.x4.trans.shared.b16 {%0,%1,%2,%3}, [%4];"
                 : "=r"(r[0]), "=r"(r[1]), "=r"(r[2]), "=r"(r[3]) : "r"(addr));
}
__device__ __forceinline__ void mma_bf16(float* c, const unsigned* a, const unsigned* b) {
    asm("mma.sync.aligned.m16n8k16.row.col.f32.bf16.bf16.f32 "
        "{%0,%1,%2,%3}, {%4,%5,%6,%7}, {%8,%9}, {%0,%1,%2,%3};"
        : "+f"(c[0]), "+f"(c[1]), "+f"(c[2]), "+f"(c[3])
        : "r"(a[0]), "r"(a[1]), "r"(a[2]), "r"(a[3]), "r"(b[0]), "r"(b[1]));
}
__device__ __forceinline__ void cpa16(uint32_t dst, const void* src, int srcbytes) {
    asm volatile("cp.async.cg.shared.global [%0], [%1], 16, %2;"
                 :: "r"(dst), "l"(src), "r"(srcbytes) : "memory");
}

// ---------------- bf16x3 GEMM core: cp.async 3-stage (depth 1), ldmatrix ----------------
#define BN 128
#define BK 32
#define ASTR 80             // A row stride bytes (64B data + 16 pad)
#define BSTR 272            // B row stride bytes (256B data + 16 pad)
#define NSTAGE 3
#define STG_MT4 37888
#define STG_MT2 27648
#define SMEM4 (NSTAGE * STG_MT4)   // 113664 -> 2 CTAs/SM
#define SMEM2 (NSTAGE * STG_MT2)   // 82944  -> 2 CTAs/SM

// C[M,N] = op( gather(A)[M,K] @ B[K,N] + bias + addvec )
template <int MT, bool GATHER, bool RELU, bool ADDVEC, bool WF32, bool WSPLIT>
__device__ __forceinline__ void gemm_bf(
    const __nv_bfloat16* __restrict__ Ah, const __nv_bfloat16* __restrict__ Al,
    int lda, const int* __restrict__ rowmap,
    const __nv_bfloat16* __restrict__ Bh, const __nv_bfloat16* __restrict__ Bl,
    int ldb,
    const float* __restrict__ bias, const float* __restrict__ addvec,
    float* __restrict__ C, __nv_bfloat16* __restrict__ Ch, __nv_bfloat16* __restrict__ Cl,
    int ldc, int M, int N, int K, int mtile, int ntile)
{
    constexpr int BMv = MT * 32;
    constexpr int ABYTES = BMv * ASTR;
    constexpr int OFFAL = ABYTES;
    constexpr int OFFBH = 2 * ABYTES;
    constexpr int OFFBL = OFFBH + 32 * BSTR;
    constexpr int STG   = OFFBL + 32 * BSTR;
    constexpr int NCH   = BMv / 64;          // A 16B-chunks per thread

    extern __shared__ char smem[];
    const uint32_t su = smem_u32(smem);
    const int tid  = threadIdx.x;
    const int lane = tid & 31;
    const int warp = tid >> 5;
    const int wm = (warp >> 2) * (MT * 16);
    const int wn = (warp & 3) * 32;
    const int gq  = lane >> 2;
    const int tig = lane & 3;

    // A loader: each thread owns NCH 16B chunks (row, k-quarter)
    int arow[NCH]; int aq[NCH];
    const __nv_bfloat16* pAh[NCH];
    const __nv_bfloat16* pAl[NCH];
#pragma unroll
    for (int c = 0; c < NCH; c++) {
        const int chunk = tid + c * 256;
        const int r = chunk >> 2;
        const int q = chunk & 3;
        int gm = mtile * BMv + r; if (gm > M - 1) gm = M - 1;
        const int ra = GATHER ? rowmap[gm] : gm;
        arow[c] = r; aq[c] = q;
        pAh[c] = Ah + (size_t)ra * lda + q * 8;
        pAl[c] = Al + (size_t)ra * lda + q * 8;
    }

    // B loader
    const int kb = tid >> 3;              // 0..31
    const int cb = (tid & 7) * 2;

    float acc[MT][4][4];
#pragma unroll
    for (int i = 0; i < MT; i++)
#pragma unroll
        for (int j = 0; j < 4; j++)
#pragma unroll
            for (int r = 0; r < 4; r++) acc[i][j][r] = 0.f;

    const int nc = (K + BK - 1) / BK;

    auto issue = [&](int ch) {
        const uint32_t sb = su + (uint32_t)(ch % NSTAGE) * STG;
#pragma unroll
        for (int c = 0; c < NCH; c++) {
            const int k0 = ch * BK + aq[c] * 8;
            const int v = (k0 + 8 <= K) ? 16 : 0;
            const uint32_t da = sb + arow[c] * ASTR + aq[c] * 16;
            cpa16(da,         v ? (const void*)(pAh[c] + ch * BK) : (const void*)Ah, v);
            cpa16(da + OFFAL, v ? (const void*)(pAl[c] + ch * BK) : (const void*)Al, v);
        }
        const int gk = ch * BK + kb;
        const int vb = (gk < K) ? 16 : 0;
        const __nv_bfloat16* sbh = Bh + (size_t)gk * ldb + ntile * BN + cb * 8;
        const __nv_bfloat16* sbl = Bl + (size_t)gk * ldb + ntile * BN + cb * 8;
        uint32_t db = sb + OFFBH + kb * BSTR + cb * 16;
        cpa16(db,      vb ? (const void*)sbh       : (const void*)Bh, vb);
        cpa16(db + 16, vb ? (const void*)(sbh + 8) : (const void*)Bh, vb);
        db = sb + OFFBL + kb * BSTR + cb * 16;
        cpa16(db,      vb ? (const void*)sbl       : (const void*)Bl, vb);
        cpa16(db + 16, vb ? (const void*)(sbl + 8) : (const void*)Bl, vb);
        asm volatile("cp.async.commit_group;" ::: "memory");
    };

    const uint32_t a_l = (uint32_t)((wm + (lane & 15)) * ASTR + (lane >> 4) * 16);
    const uint32_t b_l = (uint32_t)((lane & 15) * BSTR + (lane >> 4) * 16);

    issue(0);

    for (int ch = 0; ch < nc; ch++) {
        if (ch + 1 < nc) {
            issue(ch + 1);
            asm volatile("cp.async.wait_group 1;" ::: "memory");
        } else {
            asm volatile("cp.async.wait_group 0;" ::: "memory");
        }
        __syncthreads();

        const uint32_t sb = su + (uint32_t)(ch % NSTAGE) * STG;
#pragma unroll
        for (int ks = 0; ks < 2; ks++) {
            unsigned ah[MT][4], al[MT][4], bh[2][4], bl[2][4];
#pragma unroll
            for (int mt = 0; mt < MT; mt++) {
                const uint32_t off = a_l + (uint32_t)(ks * 32 + mt * 16 * ASTR);
                ldsm_x4(ah[mt], sb + off);
                ldsm_x4(al[mt], sb + OFFAL + off);
            }
#pragma unroll
            for (int p = 0; p < 2; p++) {
                const uint32_t off = b_l + (uint32_t)(ks * 16 * BSTR + (wn + p * 16) * 2);
                ldsm_x4t(bh[p], sb + OFFBH + off);
                ldsm_x4t(bl[p], sb + OFFBL + off);
            }
#pragma unroll
            for (int mt = 0; mt < MT; mt++)
#pragma unroll
                for (int nt = 0; nt < 4; nt++)
                    mma_bf16(acc[mt][nt], al[mt], &bh[nt >> 1][(nt & 1) * 2]);
#pragma unroll
            for (int mt = 0; mt < MT; mt++)
#pragma unroll
                for (int nt = 0; nt < 4; nt++)
                    mma_bf16(acc[mt][nt], ah[mt], &bl[nt >> 1][(nt & 1) * 2]);
#pragma unroll
            for (int mt = 0; mt < MT; mt++)
#pragma unroll
                for (int nt = 0; nt < 4; nt++)
                    mma_bf16(acc[mt][nt], ah[mt], &bh[nt >> 1][(nt & 1) * 2]);
        }
    }

    // ---- epilogue ----
#pragma unroll
    for (int nt = 0; nt < 4; nt++) {
        const int gn = ntile * BN + wn + nt * 8 + 2 * tig;
        float bx = 0.f, by = 0.f;
        if (bias) { bx = bias[gn]; by = bias[gn + 1]; }
        if (ADDVEC) { bx += addvec[gn]; by += addvec[gn + 1]; }
#pragma unroll
        for (int mt = 0; mt < MT; mt++) {
            const int gm0 = mtile * BMv + wm + mt * 16 + gq;
            float v0 = acc[mt][nt][0] + bx;
            float v1 = acc[mt][nt][1] + by;
            float v2 = acc[mt][nt][2] + bx;
            float v3 = acc[mt][nt][3] + by;
            if (RELU) {
                v0 = fmaxf(v0, 0.f); v1 = fmaxf(v1, 0.f);
                v2 = fmaxf(v2, 0.f); v3 = fmaxf(v3, 0.f);
            }
            if (gm0 < M) {
                if (WF32)
                    *reinterpret_cast<float2*>(C + (size_t)gm0 * ldc + gn) = make_float2(v0, v1);
                if (WSPLIT) {
                    float h0, l0, h1, l1;
                    split_bf(v0, h0, l0); split_bf(v1, h1, l1);
                    *reinterpret_cast<unsigned*>(Ch + (size_t)gm0 * ldc + gn) = pack2(h0, h1);
                    *reinterpret_cast<unsigned*>(Cl + (size_t)gm0 * ldc + gn) = pack2(l0, l1);
                }
            }
            if (gm0 + 8 < M) {
                if (WF32)
                    *reinterpret_cast<float2*>(C + (size_t)(gm0 + 8) * ldc + gn) = make_float2(v2, v3);
                if (WSPLIT) {
                    float h2, l2, h3, l3;
                    split_bf(v2, h2, l2); split_bf(v3, h3, l3);
                    *reinterpret_cast<unsigned*>(Ch + (size_t)(gm0 + 8) * ldc + gn) = pack2(h2, h3);
                    *reinterpret_cast<unsigned*>(Cl + (size_t)(gm0 + 8) * ldc + gn) = pack2(l2, l3);
                }
            }
        }
    }
}

// ---------------- fused split kernel ----------------
struct SJob { const float* in; __nv_bfloat16* oh; __nv_bfloat16* ol; int n; };
struct SJobs { SJob j[7]; };

__global__ void k_split_all(SJobs js)
{
    const SJob job = js.j[blockIdx.y];
    const int stride = gridDim.x * blockDim.x * 8;
    for (int i = (blockIdx.x * blockDim.x + threadIdx.x) * 8; i < job.n; i += stride) {
        const float4 v0 = ld4(job.in + i);
        const float4 v1 = ld4(job.in + i + 4);
        float h0, l0, h1, l1, h2, l2, h3, l3;
        float h4, l4, h5, l5, h6, l6, h7, l7;
        split_bf(v0.x, h0, l0); split_bf(v0.y, h1, l1);
        split_bf(v0.z, h2, l2); split_bf(v0.w, h3, l3);
        split_bf(v1.x, h4, l4); split_bf(v1.y, h5, l5);
        split_bf(v1.z, h6, l6); split_bf(v1.w, h7, l7);
        *reinterpret_cast<uint4*>(job.oh + i) =
            make_uint4(pack2(h0, h1), pack2(h2, h3), pack2(h4, h5), pack2(h6, h7));
        *reinterpret_cast<uint4*>(job.ol + i) =
            make_uint4(pack2(l0, l1), pack2(l2, l3), pack2(l4, l5), pack2(l6, l7));
    }
}

// ---------------- GEMM wrappers ----------------
__global__ __launch_bounds__(256, 2) void k_embed(
    const int* __restrict__ src, const float* __restrict__ bias, float* __restrict__ C)
{
    gemm_bf<2, true, false, false, true, true>(
        g_th, g_tl, FEAT_, src, g_m2vh, g_m2vl, D_, bias, nullptr,
        C, g_xh, g_xl, D_, NTOK, D_, FEAT_, blockIdx.y, blockIdx.x);
}

__global__ __launch_bounds__(256, 2) void k_projkv(
    const __nv_bfloat16* __restrict__ Wkh, const __nv_bfloat16* __restrict__ Wkl,
    const __nv_bfloat16* __restrict__ Wvh, const __nv_bfloat16* __restrict__ Wvl,
    const float* __restrict__ bk, const float* __restrict__ bv,
    float* __restrict__ K, float* __restrict__ V)
{
    if (blockIdx.z == 0) {
        gemm_bf<4, false, false, false, true, false>(
            g_xh, g_xl, D_, nullptr, Wkh, Wkl, D_, bk, nullptr,
            K, nullptr, nullptr, D_, NTOK, D_, D_, blockIdx.y, blockIdx.x);
    } else {
        gemm_bf<4, false, false, false, true, true>(
            g_xh, g_xl, D_, nullptr, Wvh, Wvl, D_, bv, nullptr,
            V, g_Vh, g_Vl, D_, NTOK, D_, D_, blockIdx.y, blockIdx.x);
    }
}

__global__ __launch_bounds__(256, 2) void k_pbv(const float* __restrict__ kv)
{
    const int b = blockIdx.z;
    gemm_bf<2, false, false, true, false, true>(
        g_pbh + (size_t)b * T_ * T_, g_pbl + (size_t)b * T_ * T_, T_, nullptr,
        g_Vh + (size_t)b * T_ * D_, g_Vl + (size_t)b * T_ * D_, D_,
        nullptr, kv + (size_t)b * D_,
        nullptr, g_wvh + (size_t)b * T_ * D_, g_wvl + (size_t)b * T_ * D_, D_,
        T_, D_, T_, blockIdx.y, blockIdx.x);
}

__global__ __launch_bounds__(256, 2) void k_wo(
    const __nv_bfloat16* __restrict__ Bh, const __nv_bfloat16* __restrict__ Bl,
    const float* __restrict__ bias, float* __restrict__ C)
{
    gemm_bf<2, false, false, false, true, false>(
        g_wvh, g_wvl, D_, nullptr, Bh, Bl, D_, bias, nullptr,
        C, nullptr, nullptr, D_, NTOK, D_, D_, blockIdx.y, blockIdx.x);
}

__global__ __launch_bounds__(256, 2) void k_moe1(int layer, const float* __restrict__ b1)
{
    const int e = blockIdx.z;
    const int Me = g_off[e + 1] - g_off[e];
    if ((int)(blockIdx.y * 128) >= Me) return;
    const size_t woff = ((size_t)layer * E_ + e) * D_ * FF_;
    const size_t ooff = (size_t)g_off[e] * FF_;
    gemm_bf<4, true, true, false, false, true>(
        g_xh, g_xl, D_, g_tok + g_off[e],
        g_e1h + woff, g_e1l + woff, FF_,
        b1 + (size_t)e * FF_, nullptr,
        nullptr, g_hh + ooff, g_hl + ooff, FF_,
        Me, FF_, D_, blockIdx.y, blockIdx.x);
}

__global__ __launch_bounds__(256, 2) void k_moe2(int layer, const float* __restrict__ b2)
{
    const int e = blockIdx.z;
    const int Me = g_off[e + 1] - g_off[e];
    if ((int)(blockIdx.y * 128) >= Me) return;
    const size_t woff = ((size_t)layer * E_ + e) * FF_ * D_;
    const size_t ioff = (size_t)g_off[e] * FF_;
    gemm_bf<4, false, false, false, true, false>(
        g_hh + ioff, g_hl + ioff, FF_, nullptr,
        g_e2h + woff, g_e2l + woff, D_,
        b2 + (size_t)e * D_, nullptr,
        g_eo + (size_t)g_off[e] * D_, nullptr, nullptr, D_,
        Me, D_, FF_, blockIdx.y, blockIdx.x);
}

// ---------------- Fourier positional bias (fast cos, writes split) ----------------
__global__ void k_pb(const float* __restrict__ frac,
                     const float* __restrict__ pbW,
                     const float* __restrict__ pbb,
                     const float* __restrict__ pba)
{
    __shared__ float w[NF_], ph[NF_], am[NF_];
    if (threadIdx.x < NF_) {
        w[threadIdx.x]  = pbW[threadIdx.x];
        ph[threadIdx.x] = pbb[threadIdx.x];
        am[threadIdx.x] = pba[threadIdx.x];
    }
    __syncthreads();
    const int idx = blockIdx.x * 256 + threadIdx.x;
    const int j = idx & 127;
    const int i = (idx >> 7) & 127;
    const int b = idx >> 14;
    const float d = (frac[b * T_ + j] - frac[b * T_ + i]) * SCALE_;
    float s = 0.f;
#pragma unroll
    for (int f = 0; f < NF_; f++) s += am[f] * __cosf(d * w[f] + ph[f]);
    float h, l;
    split_bf(s, h, l);
    g_pbh[idx] = __float2bfloat16_rn(h);
    g_pbl[idx] = __float2bfloat16_rn(l);
}

// ---------------- kv reduction ----------------
__global__ void k_kv(const float* __restrict__ K, const float* __restrict__ V,
                     float* __restrict__ kv)
{
    const int b = blockIdx.x;
    const int d = threadIdx.x;
    const float* Kb = K + (size_t)b * T_ * D_ + d;
    const float* Vb = V + (size_t)b * T_ * D_ + d;
    float s = 0.f;
#pragma unroll 8
    for (int t = 0; t < T_; t++) s += Kb[t * D_] * Vb[t * D_];
    kv[b * D_ + d] = s;
}

// ---------------- block reduction ----------------
__device__ __forceinline__ float blk_sum_256(float v, float* red) {
    const unsigned m = 0xffffffffu;
#pragma unroll
    for (int o = 16; o > 0; o >>= 1) v += __shfl_down_sync(m, v, o);
    if ((threadIdx.x & 31) == 0) red[threadIdx.x >> 5] = v;
    __syncthreads();
    if (threadIdx.x < 32) {
        float r = (threadIdx.x < 8) ? red[threadIdx.x] : 0.f;
#pragma unroll
        for (int o = 4; o > 0; o >>= 1) r += __shfl_down_sync(m, r, o);
        if (threadIdx.x == 0) red[0] = r;
    }
    __syncthreads();
    const float r = red[0];
    __syncthreads();
    return r;
}

__device__ __forceinline__ void ln_store(float* out, int t, int c, float v,
                                         const float* g, const float* b,
                                         float inv, float mean, bool wsplit) {
    const float r = (v - mean) * inv * g[c] + b[c];
    out[(size_t)t * D_ + c] = r;
    if (wsplit) {
        float h, l;
        split_bf(r, h, l);
        g_xh[(size_t)t * D_ + c] = __float2bfloat16_rn(h);
        g_xl[(size_t)t * D_ + c] = __float2bfloat16_rn(l);
    }
}

// ---------------- fused LN1 + gate ----------------
__global__ void k_ln_gate(const float* __restrict__ x, const float* __restrict__ y,
                          const float* __restrict__ g, const float* __restrict__ b,
                          float* __restrict__ out,
                          const float* __restrict__ gW, const float* __restrict__ gb,
                          int layer)
{
    __shared__ float red[8];
    __shared__ float xs[D_];
    __shared__ float lg[E_];
    const int t = blockIdx.x;
    const int tid = threadIdx.x;
    const float* xr = x + (size_t)t * D_;
    const float* yr = y + (size_t)t * D_;
    const float v0 = xr[tid]       + yr[tid];
    const float v1 = xr[tid + 256] + yr[tid + 256];
    const float mean = blk_sum_256(v0 + v1, red) * (1.f / D_);
    const float d0 = v0 - mean, d1 = v1 - mean;
    const float var = blk_sum_256(d0 * d0 + d1 * d1, red) * (1.f / D_);
    const float inv = rsqrtf(var + EPS_);

    {
        const float r0 = d0 * inv * g[tid]       + b[tid];
        const float r1 = d1 * inv * g[tid + 256] + b[tid + 256];
        out[(size_t)t * D_ + tid]       = r0;
        out[(size_t)t * D_ + tid + 256] = r1;
        float h, l;
        split_bf(r0, h, l);
        g_xh[(size_t)t * D_ + tid] = __float2bfloat16_rn(h);
        g_xl[(size_t)t * D_ + tid] = __float2bfloat16_rn(l);
        split_bf(r1, h, l);
        g_xh[(size_t)t * D_ + tid + 256] = __float2bfloat16_rn(h);
        g_xl[(size_t)t * D_ + tid + 256] = __float2bfloat16_rn(l);
        xs[tid] = r0;
        xs[tid + 256] = r1;
    }
    __syncthreads();

    const int e = tid >> 5;
    const int lane = tid & 31;
    float s = 0.f;
    for (int k = lane; k < D_; k += 32) s += xs[k] * gW[k * E_ + e];
    const unsigned m = 0xffffffffu;
#pragma unroll
    for (int o = 16; o > 0; o >>= 1) s += __shfl_down_sync(m, s, o);
    if (lane == 0) lg[e] = s + gb[e];
    __syncthreads();

    if (tid == 0) {
        float mx = lg[0];
#pragma unroll
        for (int k = 1; k < E_; k++) mx = fmaxf(mx, lg[k]);
        float ex[E_]; float sum = 0.f;
#pragma unroll
        for (int k = 0; k < E_; k++) { ex[k] = expf(lg[k] - mx); sum += ex[k]; }
        const float invs = 1.f / sum;
        int e0 = 0; float p0 = ex[0];
#pragma unroll
        for (int k = 1; k < E_; k++) if (ex[k] > p0) { p0 = ex[k]; e0 = k; }
        int e1 = -1; float p1 = -1.f;
#pragma unroll
        for (int k = 0; k < E_; k++)
            if (k != e0 && ex[k] > p1) { p1 = ex[k]; e1 = k; }
        g_te[2 * t]     = e0; g_tw[2 * t]     = p0 * invs;
        g_te[2 * t + 1] = e1; g_tw[2 * t + 1] = p1 * invs;
        atomicAdd(&g_cntA[layer * E_ + e0], 1);
        atomicAdd(&g_cntA[layer * E_ + e1], 1);
    }
}

__global__ void k_zero_all() {
    if (threadIdx.x < NL_ * E_) g_cntA[threadIdx.x] = 0;
}

__global__ void k_scan(int layer) {
    if (threadIdx.x == 0) {
        int a = 0;
        for (int e = 0; e < E_; e++) {
            g_off[e] = a; g_cur[e] = a;
            a += g_cntA[layer * E_ + e];
        }
        g_off[E_] = a;
    }
}

__global__ void k_scatter() {
    const int t = blockIdx.x * 256 + threadIdx.x;
    if (t >= NTOK) return;
#pragma unroll
    for (int k = 0; k < 2; k++) {
        const int e = g_te[2 * t + k];
        const int p = atomicAdd(&g_cur[e], 1);
        g_tok[p] = t;
        g_pos[2 * t + k] = p;
    }
}

// ---------------- LN2 ----------------
__global__ void k_ln2(const float* __restrict__ x,
                      const float* __restrict__ g, const float* __restrict__ b,
                      float* __restrict__ out, int wsplit)
{
    __shared__ float red[8];
    const int t = blockIdx.x;
    const int tid = threadIdx.x;
    const int p0 = g_pos[2 * t], p1 = g_pos[2 * t + 1];
    const float w0 = g_tw[2 * t], w1 = g_tw[2 * t + 1];
    const float* e0 = g_eo + (size_t)p0 * D_;
    const float* e1 = g_eo + (size_t)p1 * D_;
    const float* xr = x + (size_t)t * D_;
    const float v0 = xr[tid]       + w0 * e0[tid]       + w1 * e1[tid];
    const float v1 = xr[tid + 256] + w0 * e0[tid + 256] + w1 * e1[tid + 256];
    const float mean = blk_sum_256(v0 + v1, red) * (1.f / D_);
    const float d0 = v0 - mean, d1 = v1 - mean;
    const float var = blk_sum_256(d0 * d0 + d1 * d1, red) * (1.f / D_);
    const float inv = rsqrtf(var + EPS_);
    ln_store(out, t, tid,       v0, g, b, inv, mean, wsplit != 0);
    ln_store(out, t, tid + 256, v1, g, b, inv, mean, wsplit != 0);
}

// ---------------- host launcher ----------------
extern "C" void kernel_launch(void* const* d_in, const int* in_sizes, int n_in,
                              void* d_out, int out_size)
{
    const int*   src  = (const int*)  d_in[0];
    const float* frac = (const float*)d_in[1];
    const float* tab  = (const float*)d_in[2];
    const float* Wm2v = (const float*)d_in[3];
    const float* bm2v = (const float*)d_in[4];
    const float* pbW  = (const float*)d_in[5];
    const float* pbb  = (const float*)d_in[6];
    const float* pba  = (const float*)d_in[7];
    const float* Wk   = (const float*)d_in[8];
    const float* bk   = (const float*)d_in[9];
    const float* Wv   = (const float*)d_in[10];
    const float* bv   = (const float*)d_in[11];
    const float* Wo   = (const float*)d_in[12];
    const float* bo   = (const float*)d_in[13];
    const float* ln1g = (const float*)d_in[14];
    const float* ln1b = (const float*)d_in[15];
    const float* ln2g = (const float*)d_in[16];
    const float* ln2b = (const float*)d_in[17];
    const float* gW   = (const float*)d_in[18];
    const float* gb   = (const float*)d_in[19];
    const float* eW1  = (const float*)d_in[20];
    const float* eb1  = (const float*)d_in[21];
    const float* eW2  = (const float*)d_in[22];
    const float* eb2  = (const float*)d_in[23];

    float *x, *Kb, *Vb, *kvb, *o;
    cudaGetSymbolAddress((void**)&x,   g_x);
    cudaGetSymbolAddress((void**)&Kb,  g_K);
    cudaGetSymbolAddress((void**)&Vb,  g_V);
    cudaGetSymbolAddress((void**)&kvb, g_kv);
    cudaGetSymbolAddress((void**)&o,   g_o);

    __nv_bfloat16 *th, *tl, *m2vh, *m2vl, *Wkh, *Wkl, *Wvh, *Wvl, *Woh, *Wol;
    __nv_bfloat16 *e1h, *e1l, *e2h, *e2l;
    cudaGetSymbolAddress((void**)&th,   g_th);
    cudaGetSymbolAddress((void**)&tl,   g_tl);
    cudaGetSymbolAddress((void**)&m2vh, g_m2vh);
    cudaGetSymbolAddress((void**)&m2vl, g_m2vl);
    cudaGetSymbolAddress((void**)&Wkh,  g_Wkh);
    cudaGetSymbolAddress((void**)&Wkl,  g_Wkl);
    cudaGetSymbolAddress((void**)&Wvh,  g_Wvh);
    cudaGetSymbolAddress((void**)&Wvl,  g_Wvl);
    cudaGetSymbolAddress((void**)&Woh,  g_Woh);
    cudaGetSymbolAddress((void**)&Wol,  g_Wol);
    cudaGetSymbolAddress((void**)&e1h,  g_e1h);
    cudaGetSymbolAddress((void**)&e1l,  g_e1l);
    cudaGetSymbolAddress((void**)&e2h,  g_e2h);
    cudaGetSymbolAddress((void**)&e2l,  g_e2l);

    static bool attr_done = false;
    if (!attr_done) {
        cudaFuncSetAttribute(k_embed,  cudaFuncAttributeMaxDynamicSharedMemorySize, SMEM2);
        cudaFuncSetAttribute(k_projkv, cudaFuncAttributeMaxDynamicSharedMemorySize, SMEM4);
        cudaFuncSetAttribute(k_pbv,    cudaFuncAttributeMaxDynamicSharedMemorySize, SMEM2);
        cudaFuncSetAttribute(k_wo,     cudaFuncAttributeMaxDynamicSharedMemorySize, SMEM2);
        cudaFuncSetAttribute(k_moe1,   cudaFuncAttributeMaxDynamicSharedMemorySize, SMEM4);
        cudaFuncSetAttribute(k_moe2,   cudaFuncAttributeMaxDynamicSharedMemorySize, SMEM4);
        attr_done = true;
    }

    // weight splits: one launch
    SJobs js;
    js.j[0] = { tab,  th,   tl,   VOCAB_ * FEAT_ };
    js.j[1] = { Wm2v, m2vh, m2vl, FEAT_ * D_ };
    js.j[2] = { Wk,   Wkh,  Wkl,  NL_ * D_ * D_ };
    js.j[3] = { Wv,   Wvh,  Wvl,  NL_ * D_ * D_ };
    js.j[4] = { Wo,   Woh,  Wol,  NL_ * D_ * D_ };
    js.j[5] = { eW1,  e1h,  e1l,  NL_ * E_ * D_ * FF_ };
    js.j[6] = { eW2,  e2h,  e2l,  NL_ * E_ * FF_ * D_ };
    k_split_all<<<dim3(1024, 7), 256>>>(js);
    k_zero_all<<<1, 32>>>();

    k_embed<<<dim3(4, 64), 256, SMEM2>>>(src, bm2v, x);
    k_pb<<<(B_ * T_ * T_) / 256, 256>>>(frac, pbW, pbb, pba);

    for (int i = 0; i < NL_; i++) {
        const size_t wOff = (size_t)i * D_ * D_;
        k_projkv<<<dim3(4, 32, 2), 256, SMEM4>>>(
            Wkh + wOff, Wkl + wOff, Wvh + wOff, Wvl + wOff,
            bk + i * D_, bv + i * D_, Kb, Vb);
        k_kv<<<B_, 512>>>(Kb, Vb, kvb);
        k_pbv<<<dim3(4, 2, B_), 256, SMEM2>>>(kvb);
        k_wo<<<dim3(4, 64), 256, SMEM2>>>(Woh + wOff, Wol + wOff, bo + i * D_, o);
        k_ln_gate<<<NTOK, 256>>>(x, o, ln1g + i * D_, ln1b + i * D_, x,
                                 gW + (size_t)i * D_ * E_, gb + i * E_, i);
        k_scan<<<1, 1>>>(i);
        k_scatter<<<NTOK / 256, 256>>>();

        k_moe1<<<dim3(FF_ / BN, 32, E_), 256, SMEM4>>>(i, eb1 + (size_t)i * E_ * FF_);
        k_moe2<<<dim3(D_ / BN, 32, E_), 256, SMEM4>>>(i, eb2 + (size_t)i * E_ * D_);

        float* dst = (i == NL_ - 1) ? (float*)d_out : x;
        k_ln2<<<NTOK, 256>>>(x, ln2g + i * D_, ln2b + i * D_, dst,
                             (i == NL_ - 1) ? 0 : 1);
    }
}